// round 6
// baseline (speedup 1.0000x reference)
#include <cuda_runtime.h>
#include <math.h>
#include <stdint.h>

// ---------------------------------------------------------------------------
// Problem constants
// ---------------------------------------------------------------------------
#define Bn   4
#define Cc   192
#define C2   384
#define Hh   96
#define Ww   96
#define HW   (Hh*Ww)          // 9216
#define NH   8
#define HD   24
#define Gg   8
#define CG   24

// scratch offsets (floats)
#define OFF_QKV1  0ul
#define OFF_QKV   14155776ul
#define OFF_CAT   28311552ul
#define OFF_SC    42467328ul
#define OFF_POOL  56623104ul
#define OFF_K2    60162048ul
#define OFF_OFF   63412224ul
#define OFF_FEAT  64075776ul
#define OFF_K     71153664ul
#define OFF_AO    78231552ul
#define OFF_QN    85309440ul
#define OFF_KN    85310208ul
#define OFF_ATTN  85310976ul
#define OFF_XT    85329408ul     // 7077888
#define OFF_WQKV  92407296ul     // 73728
#define OFF_WK2   92481024ul     // 1327104
#define OFF_WK3   93808128ul     // 1327104
#define OFF_WK4   95135232ul     // 62208
#define OFF_WPW   95197440ul     // 36864
#define OFF_WPROJ 95234304ul     // 36864
#define SCRATCH_TOTAL 95271168ul

__device__ float g_scratch[SCRATCH_TOTAL];

// ---------------------------------------------------------------------------
// tf32 / cp.async helpers
// ---------------------------------------------------------------------------
__device__ __forceinline__ float f2tf32(float x) {
    uint32_t u;
    asm("cvt.rna.tf32.f32 %0, %1;" : "=r"(u) : "f"(x));
    return __uint_as_float(u);
}

__device__ __forceinline__ void mma_16x8x8(float* c, const uint32_t* a,
                                           uint32_t b0, uint32_t b1) {
    asm volatile(
        "mma.sync.aligned.m16n8k8.row.col.f32.tf32.tf32.f32 "
        "{%0,%1,%2,%3}, {%4,%5,%6,%7}, {%8,%9}, {%0,%1,%2,%3};\n"
        : "+f"(c[0]), "+f"(c[1]), "+f"(c[2]), "+f"(c[3])
        : "r"(a[0]), "r"(a[1]), "r"(a[2]), "r"(a[3]), "r"(b0), "r"(b1));
}

__device__ __forceinline__ void cpasync4(uint32_t saddr, const float* g, bool pred) {
    int sz = pred ? 4 : 0;
    asm volatile("cp.async.ca.shared.global [%0], [%1], 4, %2;\n"
                 :: "r"(saddr), "l"(g), "r"(sz));
}
__device__ __forceinline__ void cpasync16(uint32_t saddr, const float* g) {
    asm volatile("cp.async.cg.shared.global [%0], [%1], 16;\n"
                 :: "r"(saddr), "l"(g));
}
__device__ __forceinline__ void cpasync16p(uint32_t saddr, const float* g, bool pred) {
    int sz = pred ? 16 : 0;
    asm volatile("cp.async.cg.shared.global [%0], [%1], 16, %2;\n"
                 :: "r"(saddr), "l"(g), "r"(sz));
}
#define CP_COMMIT() asm volatile("cp.async.commit_group;\n" ::: "memory")
#define CP_WAIT0()  asm volatile("cp.async.wait_group 0;\n" ::: "memory")

// ---------------------------------------------------------------------------
// tf32 tensor-core implicit-GEMM conv, full cp.async version.
// BM = 32*FM, BN = 128, BK = 16, 256 threads = 8 warps (2M x 4N).
// Both A (weights) and B (activations) must be PRE-ROUNDED to tf32.
// A smem layout: [BM][ASTR=20] (row-major in K) — conflict-free frag loads.
// For KS==1, N must be a multiple of 128.
// ---------------------------------------------------------------------------
template<int KS, int FM>
__global__ __launch_bounds__(256)
void conv_mma(const float* __restrict__ Wt,
              const float* __restrict__ X,
              float* __restrict__ Y,
              const float* __restrict__ bias,
              int M, int Cin, int IH, int IW,
              int OH, int OW, int pad)
{
    constexpr int BM   = 32 * FM;
    constexpr int BN   = 128;
    constexpr int BK   = 16;
    constexpr int ASTR = 20;                 // floats per A row (16 data + 4 pad)
    constexpr int BSTR = BN + 8;
    constexpr int ACP  = BM * BK / 4;        // 16B copies for A tile
    constexpr int AIT  = (ACP + 255) / 256;

    __shared__ float As[2][BM * ASTR];
    __shared__ float Bs[2][BK * BSTR];

    const int N  = OH * OW;
    const int K  = Cin * KS * KS;
    const int bz = blockIdx.z;
    const int m0 = blockIdx.y * BM;
    const int n0 = blockIdx.x * BN;

    const int tid  = threadIdx.x;
    const int wid  = tid >> 5;
    const int lane = tid & 31;
    const int wm   = wid & 1;
    const int wn   = wid >> 1;
    const int mbase = wm * (16 * FM);
    const int nbase = wn * 32;
    const int lg = lane >> 2;
    const int lt = lane & 3;

    const float* Xb = X + (size_t)bz * Cin * IH * IW;

    float acc[FM][4][4];
    #pragma unroll
    for (int f = 0; f < FM; ++f)
        #pragma unroll
        for (int nf = 0; nf < 4; ++nf)
            #pragma unroll
            for (int r = 0; r < 4; ++r) acc[f][nf][r] = 0.f;

    // B-gather per-thread coords (KS==3 path)
    const int bn = tid & 127;
    const int gn = n0 + bn;
    const bool nvalid = gn < N;
    int oy = 0, ox = 0;
    if (KS == 3) { int g = nvalid ? gn : 0; oy = g / OW; ox = g - oy * OW; }

    auto issueA = [&](int k0, int buf) {
        #pragma unroll
        for (int r = 0; r < AIT; ++r) {
            int e = tid + r * 256;
            if (ACP >= 256 * (r + 1) || e < ACP) {
                int m  = e >> 2;
                int kq = e & 3;
                int gm = m0 + m;
                uint32_t s = (uint32_t)__cvta_generic_to_shared(
                    &As[buf][m * ASTR + kq * 4]);
                cpasync16p(s, Wt + (size_t)gm * K + k0 + kq * 4, gm < M);
            }
        }
    };
    auto issueB = [&](int k0, int buf) {
        if (KS == 1) {
            #pragma unroll
            for (int r = 0; r < 2; ++r) {
                int o  = tid + r * 256;
                int k  = o >> 5;
                int c4 = (o & 31) * 4;
                uint32_t s = (uint32_t)__cvta_generic_to_shared(&Bs[buf][k * BSTR + c4]);
                cpasync16(s, Xb + (size_t)(k0 + k) * N + n0 + c4);
            }
        } else {
            #pragma unroll
            for (int r = 0; r < 8; ++r) {
                int k  = (tid >> 7) + 2 * r;
                int gk = k0 + k;
                int ic = gk / 9;
                int t  = gk - ic * 9;
                int tdy = (t >= 6) ? 2 : ((t >= 3) ? 1 : 0);
                int tdx = t - 3 * tdy;
                int iy = oy + tdy - pad;
                int ix = ox + tdx - pad;
                bool ok = nvalid && iy >= 0 && iy < IH && ix >= 0 && ix < IW;
                uint32_t s = (uint32_t)__cvta_generic_to_shared(&Bs[buf][k * BSTR + bn]);
                cpasync4(s, Xb + ((size_t)ic * IH + iy) * IW + ix, ok);
            }
        }
    };
    auto compute = [&](int buf) {
        #pragma unroll
        for (int ks = 0; ks < 2; ++ks) {
            const int kr = ks * 8 + lt;
            uint32_t a[FM][4];
            #pragma unroll
            for (int f = 0; f < FM; ++f) {
                int mr = mbase + f * 16 + lg;
                a[f][0] = __float_as_uint(As[buf][mr * ASTR + kr]);
                a[f][1] = __float_as_uint(As[buf][(mr + 8) * ASTR + kr]);
                a[f][2] = __float_as_uint(As[buf][mr * ASTR + kr + 4]);
                a[f][3] = __float_as_uint(As[buf][(mr + 8) * ASTR + kr + 4]);
            }
            #pragma unroll
            for (int nf = 0; nf < 4; ++nf) {
                int nc = nbase + nf * 8 + lg;
                uint32_t b0 = __float_as_uint(Bs[buf][kr * BSTR + nc]);
                uint32_t b1 = __float_as_uint(Bs[buf][(kr + 4) * BSTR + nc]);
                #pragma unroll
                for (int f = 0; f < FM; ++f)
                    mma_16x8x8(acc[f][nf], a[f], b0, b1);
            }
        }
    };

    const int kTiles = K / BK;
    issueA(0, 0); issueB(0, 0); CP_COMMIT();
    CP_WAIT0(); __syncthreads();

    for (int t = 0; t < kTiles; ++t) {
        if (t + 1 < kTiles) {
            issueA((t + 1) * BK, (t + 1) & 1);
            issueB((t + 1) * BK, (t + 1) & 1);
            CP_COMMIT();
        }
        compute(t & 1);
        if (t + 1 < kTiles) {
            CP_WAIT0(); __syncthreads();
        }
    }

    // ---- epilogue ----
    #pragma unroll
    for (int f = 0; f < FM; ++f) {
        int r0 = m0 + mbase + f * 16 + lg;
        #pragma unroll
        for (int nf = 0; nf < 4; ++nf) {
            int cb = n0 + nbase + nf * 8 + 2 * lt;
            #pragma unroll
            for (int rr = 0; rr < 2; ++rr) {
                int m = r0 + rr * 8;
                if (m >= M) continue;
                float bval = bias ? bias[m] : 0.f;
                #pragma unroll
                for (int cc = 0; cc < 2; ++cc) {
                    int n = cb + cc;
                    if (n >= N) continue;
                    Y[((size_t)bz * M + m) * N + n] = acc[f][nf][rr * 2 + cc] + bval;
                }
            }
        }
    }
}

// ---------------------------------------------------------------------------
// vectorized tf32 rounding (n % 4 == 0)
// ---------------------------------------------------------------------------
__global__ void tf32round4_kernel(const float* __restrict__ X,
                                  float* __restrict__ Y, int n4)
{
    int i = blockIdx.x * 256 + threadIdx.x;
    if (i >= n4) return;
    float4 v = reinterpret_cast<const float4*>(X)[i];
    v.x = f2tf32(v.x); v.y = f2tf32(v.y); v.z = f2tf32(v.z); v.w = f2tf32(v.w);
    reinterpret_cast<float4*>(Y)[i] = v;
}

// ---------------------------------------------------------------------------
// grouped 3x3 conv, smem-tiled
// ---------------------------------------------------------------------------
__global__ __launch_bounds__(256)
void dwconv2_kernel(const float* __restrict__ X,
                    const float* __restrict__ W,
                    float* __restrict__ Y)
{
    __shared__ float xs[2][34][35];
    __shared__ float ws[36];

    const int tile = blockIdx.x;
    const int g    = blockIdx.y;
    const int b    = blockIdx.z;
    const int ty0  = (tile / 3) * 32;
    const int tx0  = (tile % 3) * 32;
    const int tid  = threadIdx.x;

    if (tid < 36) ws[tid] = W[(size_t)g * 36 + tid];

    for (int e = tid; e < 2 * 34 * 34; e += 256) {
        int c  = e / (34 * 34);
        int r  = e - c * 34 * 34;
        int yy = r / 34, xx = r - yy * 34;
        int gy = ty0 + yy - 1, gx = tx0 + xx - 1;
        float v = 0.f;
        if (gy >= 0 && gy < Hh && gx >= 0 && gx < Ww)
            v = X[((size_t)b * C2 + 2 * g + c) * HW + gy * Ww + gx];
        xs[c][yy][xx] = v;
    }
    __syncthreads();

    const int x  = tid & 31;
    const int yb = (tid >> 5) * 4;
    #pragma unroll
    for (int j = 0; j < 4; ++j) {
        int y = yb + j;
        float a0 = 0.f, a1 = 0.f;
        #pragma unroll
        for (int c = 0; c < 2; ++c)
            #pragma unroll
            for (int ky = 0; ky < 3; ++ky)
                #pragma unroll
                for (int kx = 0; kx < 3; ++kx) {
                    float v = xs[c][y + ky][x + kx];
                    a0 += v * ws[c * 9 + ky * 3 + kx];
                    a1 += v * ws[18 + c * 9 + ky * 3 + kx];
                }
        size_t o = ((size_t)b * C2 + 2 * g) * HW + (ty0 + y) * Ww + tx0 + x;
        Y[o]      = a0;
        Y[o + HW] = a1;
    }
}

// cat = tf32([q ; y]) (float4)
__global__ void cat4_kernel(const float* __restrict__ QKV,
                            const float* __restrict__ Yin,
                            float* __restrict__ CAT)
{
    int i = blockIdx.x * 256 + threadIdx.x;
    if (i >= Bn * C2 * HW / 4) return;
    int p4 = i % (HW / 4);
    int c  = (i / (HW / 4)) % C2;
    int b  = i / ((HW / 4) * C2);
    float4 v;
    if (c < Cc) v = reinterpret_cast<const float4*>(QKV + ((size_t)b * C2 + c) * HW)[p4];
    else        v = reinterpret_cast<const float4*>(Yin + ((size_t)b * Cc + (c - Cc)) * HW)[p4];
    v.x = f2tf32(v.x); v.y = f2tf32(v.y); v.z = f2tf32(v.z); v.w = f2tf32(v.w);
    reinterpret_cast<float4*>(CAT)[i] = v;
}

// 2x2 avg pool, 96 -> 48 (tf32 out, float4)
__global__ void pool4_kernel(const float* __restrict__ X, float* __restrict__ Y)
{
    int i = blockIdx.x * 256 + threadIdx.x;
    const int OHW4 = 48 * 48 / 4;      // 576
    if (i >= Bn * C2 * OHW4) return;
    int r  = i % OHW4;
    int bc = i / OHW4;
    int y  = r / 12;
    int x8 = (r % 12) * 8;
    const float* xp = X + (size_t)bc * HW;
    float4 r0a = *reinterpret_cast<const float4*>(xp + (2 * y) * Ww + x8);
    float4 r0b = *reinterpret_cast<const float4*>(xp + (2 * y) * Ww + x8 + 4);
    float4 r1a = *reinterpret_cast<const float4*>(xp + (2 * y + 1) * Ww + x8);
    float4 r1b = *reinterpret_cast<const float4*>(xp + (2 * y + 1) * Ww + x8 + 4);
    float4 o;
    o.x = f2tf32((r0a.x + r0a.y + r1a.x + r1a.y) * 0.25f);
    o.y = f2tf32((r0a.z + r0a.w + r1a.z + r1a.w) * 0.25f);
    o.z = f2tf32((r0b.x + r0b.y + r1b.x + r1b.y) * 0.25f);
    o.w = f2tf32((r0b.z + r0b.w + r1b.z + r1b.w) * 0.25f);
    reinterpret_cast<float4*>(Y)[i] = o;
}

// SC = tf32(SC * sigmoid(CAT + upsample(K2)))  (float4)
__global__ void sigmul4_kernel(float* __restrict__ SC,
                               const float* __restrict__ CAT,
                               const float* __restrict__ K2)
{
    int i = blockIdx.x * 256 + threadIdx.x;
    if (i >= Bn * C2 * HW / 4) return;
    int p4 = i % (HW / 4);
    int bc = i / (HW / 4);
    int p  = p4 * 4;
    int y  = p / Ww, x = p % Ww;
    int iy = (y * 46) / 96;
    const float* k2r = K2 + (size_t)bc * (46 * 46) + iy * 46;
    float4 cv = reinterpret_cast<const float4*>(CAT)[i];
    float4 sv = reinterpret_cast<const float4*>(SC)[i];
    float k0 = k2r[((x + 0) * 46) / 96];
    float k1 = k2r[((x + 1) * 46) / 96];
    float k2v = k2r[((x + 2) * 46) / 96];
    float k3 = k2r[((x + 3) * 46) / 96];
    sv.x = f2tf32(sv.x / (1.f + expf(-(cv.x + k0))));
    sv.y = f2tf32(sv.y / (1.f + expf(-(cv.y + k1))));
    sv.z = f2tf32(sv.z / (1.f + expf(-(cv.z + k2v))));
    sv.w = f2tf32(sv.w / (1.f + expf(-(cv.w + k3))));
    reinterpret_cast<float4*>(SC)[i] = sv;
}

// ---------------------------------------------------------------------------
// fused deformable conv; stores tf32(relu(out))
// ---------------------------------------------------------------------------
__global__ __launch_bounds__(128)
void deform_kernel(const float* __restrict__ Q,
                   const float* __restrict__ OFF,
                   const float* __restrict__ W,
                   const float* __restrict__ Bias,
                   float* __restrict__ Y)
{
    __shared__ float ws[24 * 216];
    const int g = blockIdx.y;
    const int b = blockIdx.z;
    const int tid = threadIdx.x;

    for (int e = tid; e < 24 * 216; e += 128) {
        int o = e / 216, r = e - o * 216;
        ws[e] = W[(size_t)(g * CG + o) * 216 + r];
    }
    __syncthreads();

    int p = blockIdx.x * 128 + tid;
    int y = p / Ww, x = p % Ww;
    const float* offb = OFF + (size_t)b * 18 * HW;

    float acc[24];
    #pragma unroll
    for (int o = 0; o < 24; ++o) acc[o] = Bias[g * CG + o];

    const float* qc = Q + ((size_t)b * C2 + g * CG) * HW;

    for (int t = 0; t < 9; ++t) {
        float dy = offb[(size_t)(2 * t) * HW + p];
        float dx = offb[(size_t)(2 * t + 1) * HW + p];
        float m  = 1.f / (1.f + expf(-offb[(size_t)t * HW + p]));
        float py = dy + (float)(y - 1 + t / 3);
        float px = dx + (float)(x - 1 + t % 3);
        float y0f = floorf(py), x0f = floorf(px);
        int   y0 = (int)y0f,    x0 = (int)x0f;
        float fy = py - y0f,    fx = px - x0f;
        float w00 = (1.f - fy) * (1.f - fx);
        float w01 = (1.f - fy) * fx;
        float w10 = fy * (1.f - fx);
        float w11 = fy * fx;
        bool vy0 = (y0 >= 0 && y0 <= Hh - 1), vy1 = (y0 + 1 >= 0 && y0 + 1 <= Hh - 1);
        bool vx0 = (x0 >= 0 && x0 <= Ww - 1), vx1 = (x0 + 1 >= 0 && x0 + 1 <= Ww - 1);
        int cy0 = min(max(y0, 0), Hh - 1),     cy1 = min(max(y0 + 1, 0), Hh - 1);
        int cx0 = min(max(x0, 0), Ww - 1),     cx1 = min(max(x0 + 1, 0), Ww - 1);
        int i00 = cy0 * Ww + cx0, i01 = cy0 * Ww + cx1;
        int i10 = cy1 * Ww + cx0, i11 = cy1 * Ww + cx1;
        w00 = (vy0 && vx0) ? w00 * m : 0.f;
        w01 = (vy0 && vx1) ? w01 * m : 0.f;
        w10 = (vy1 && vx0) ? w10 * m : 0.f;
        w11 = (vy1 && vx1) ? w11 * m : 0.f;

        #pragma unroll
        for (int i = 0; i < 24; ++i) {
            const float* qp = qc + (size_t)i * HW;
            float val = w00 * qp[i00] + w01 * qp[i01] + w10 * qp[i10] + w11 * qp[i11];
            const float* wr = &ws[i * 9 + t];
            #pragma unroll
            for (int o = 0; o < 24; ++o) acc[o] += val * wr[o * 216];
        }
    }
    #pragma unroll
    for (int o = 0; o < 24; ++o)
        Y[((size_t)b * Cc + g * CG + o) * HW + p] = f2tf32(fmaxf(acc[o], 0.f));
}

// ---------------------------------------------------------------------------
// row L2 norms
// ---------------------------------------------------------------------------
__global__ void rownorm_kernel(const float* __restrict__ QKV,
                               const float* __restrict__ Kb,
                               float* __restrict__ QN,
                               float* __restrict__ KN)
{
    int row   = blockIdx.x;
    int which = row / (Bn * Cc);
    row %= (Bn * Cc);
    int b = row / Cc, c = row % Cc;
    const float* src = which ? (Kb + ((size_t)b * Cc + c) * HW)
                             : (QKV + ((size_t)b * C2 + c) * HW);
    float s = 0.f;
    for (int n = threadIdx.x; n < HW / 4; n += 256) {
        float4 v = reinterpret_cast<const float4*>(src)[n];
        s += v.x * v.x + v.y * v.y + v.z * v.z + v.w * v.w;
    }
    __shared__ float sm[256];
    sm[threadIdx.x] = s;
    __syncthreads();
    for (int d = 128; d > 0; d >>= 1) {
        if (threadIdx.x < d) sm[threadIdx.x] += sm[threadIdx.x + d];
        __syncthreads();
    }
    if (threadIdx.x == 0) {
        float nrm = fmaxf(sqrtf(sm[0]), 1e-12f);
        (which ? KN : QN)[b * Cc + c] = nrm;
    }
}

// ---------------------------------------------------------------------------
// attention: one block per (b,h).  K-head staged through smem.
// ---------------------------------------------------------------------------
#define CNK 384
__global__ __launch_bounds__(256)
void attn2_kernel(const float* __restrict__ QKV,
                  const float* __restrict__ Kb,
                  const float* __restrict__ QN,
                  const float* __restrict__ KN,
                  const float* __restrict__ TEMP,
                  float* __restrict__ ATTN)
{
    __shared__ float ks_[24][CNK + 8];
    __shared__ float logits[24][24];

    const int b = blockIdx.x >> 3;
    const int h = blockIdx.x & 7;
    const int tid  = threadIdx.x;
    const int wid  = tid >> 5;
    const int lane = tid & 31;

    const float* qh = QKV + ((size_t)b * C2 + h * HD) * HW;
    const float* kh = Kb  + ((size_t)b * Cc + h * HD) * HW;

    float acc[3][24];
    #pragma unroll
    for (int r = 0; r < 3; ++r)
        #pragma unroll
        for (int j = 0; j < 24; ++j) acc[r][j] = 0.f;

    const float* q0p = qh + (size_t)(3 * wid + 0) * HW;
    const float* q1p = qh + (size_t)(3 * wid + 1) * HW;
    const float* q2p = qh + (size_t)(3 * wid + 2) * HW;

    for (int n0 = 0; n0 < HW; n0 += CNK) {
        __syncthreads();
        for (int e = tid; e < 24 * (CNK / 4); e += 256) {
            int j = e / (CNK / 4);
            int c = e - j * (CNK / 4);
            float4 v = *reinterpret_cast<const float4*>(kh + (size_t)j * HW + n0 + c * 4);
            ks_[j][c * 4 + 0] = v.x;
            ks_[j][c * 4 + 1] = v.y;
            ks_[j][c * 4 + 2] = v.z;
            ks_[j][c * 4 + 3] = v.w;
        }
        __syncthreads();

        for (int i = lane; i < CNK; i += 32) {
            int n = n0 + i;
            float q0 = q0p[n], q1 = q1p[n], q2 = q2p[n];
            #pragma unroll
            for (int j = 0; j < 24; ++j) {
                float kv = ks_[j][i];
                acc[0][j] += q0 * kv;
                acc[1][j] += q1 * kv;
                acc[2][j] += q2 * kv;
            }
        }
    }

    #pragma unroll
    for (int r = 0; r < 3; ++r)
        #pragma unroll
        for (int j = 0; j < 24; ++j) {
            float v = acc[r][j];
            for (int o = 16; o > 0; o >>= 1) v += __shfl_down_sync(0xffffffffu, v, o);
            if (lane == 0) logits[wid * 3 + r][j] = v;
        }
    __syncthreads();

    if (tid < 24) {
        int i = tid;
        float qn = QN[b * Cc + h * HD + i];
        float tp = TEMP[h];
        float s[24];
        float mx = -1e30f;
        #pragma unroll
        for (int j = 0; j < 24; ++j) {
            s[j] = logits[i][j] / (qn * KN[b * Cc + h * HD + j]) * tp;
            mx = fmaxf(mx, s[j]);
        }
        float sum = 0.f;
        #pragma unroll
        for (int j = 0; j < 24; ++j) { s[j] = expf(s[j] - mx); sum += s[j]; }
        float inv = 1.f / sum;
        #pragma unroll
        for (int j = 0; j < 24; ++j)
            ATTN[(((size_t)b * NH + h) * HD + i) * HD + j] = s[j] * inv;
    }
}

// out = attn @ v ; stores tf32 (AO feeds proj conv)
__global__ void attnv_kernel(const float* __restrict__ ATTN,
                             const float* __restrict__ QKV,
                             float* __restrict__ AO)
{
    int h = blockIdx.y, b = blockIdx.z;
    int n = blockIdx.x * 256 + threadIdx.x;
    __shared__ float a_s[HD * HD];
    for (int e = threadIdx.x; e < HD * HD; e += 256)
        a_s[e] = ATTN[((size_t)b * NH + h) * HD * HD + e];
    __syncthreads();
    const float* vb = QKV + ((size_t)b * C2 + Cc + h * HD) * HW;
    float acc[HD] = {};
    #pragma unroll
    for (int j = 0; j < HD; ++j) {
        float vv = vb[(size_t)j * HW + n];
        #pragma unroll
        for (int i = 0; i < HD; ++i) acc[i] += a_s[i * HD + j] * vv;
    }
    #pragma unroll
    for (int i = 0; i < HD; ++i)
        AO[((size_t)b * Cc + h * HD + i) * HW + n] = f2tf32(acc[i]);
}

// ---------------------------------------------------------------------------
// launcher
// ---------------------------------------------------------------------------
extern "C" void kernel_launch(void* const* d_in, const int* in_sizes, int n_in,
                              void* d_out, int out_size)
{
    const float* x           = (const float*)d_in[0];
    const float* y           = (const float*)d_in[1];
    const float* temperature = (const float*)d_in[2];
    const float* qkv_w       = (const float*)d_in[3];
    const float* qkv_conv_w  = (const float*)d_in[4];
    const float* proj_w      = (const float*)d_in[5];
    const float* k2_w        = (const float*)d_in[6];
    const float* k3_w        = (const float*)d_in[7];
    const float* k4_w        = (const float*)d_in[8];
    const float* deform_w    = (const float*)d_in[9];
    const float* deform_b    = (const float*)d_in[10];
    const float* pw_w        = (const float*)d_in[11];
    const float* pw_b        = (const float*)d_in[12];
    float* out = (float*)d_out;

    float* S = nullptr;
    cudaGetSymbolAddress((void**)&S, g_scratch);
    float* QKV1 = S + OFF_QKV1;
    float* QKV  = S + OFF_QKV;
    float* CAT  = S + OFF_CAT;
    float* SC   = S + OFF_SC;
    float* POOL = S + OFF_POOL;
    float* K2   = S + OFF_K2;
    float* OFFb = S + OFF_OFF;
    float* FEAT = S + OFF_FEAT;
    float* Kb   = S + OFF_K;
    float* AO   = S + OFF_AO;
    float* QN   = S + OFF_QN;
    float* KN   = S + OFF_KN;
    float* ATTN = S + OFF_ATTN;
    float* XT   = S + OFF_XT;
    float* WQKV = S + OFF_WQKV;
    float* WK2  = S + OFF_WK2;
    float* WK3  = S + OFF_WK3;
    float* WK4  = S + OFF_WK4;
    float* WPW  = S + OFF_WPW;
    float* WPROJ= S + OFF_WPROJ;

    const int NE = Bn * C2 * HW;
    const int NX = Bn * Cc * HW;

    // 0) tf32 pre-rounding: activations x and all GEMM weights
    tf32round4_kernel<<<(NX / 4 + 255) / 256, 256>>>(x, XT, NX / 4);
    tf32round4_kernel<<<(73728 / 4 + 255) / 256, 256>>>(qkv_w, WQKV, 73728 / 4);
    tf32round4_kernel<<<(1327104 / 4 + 255) / 256, 256>>>(k2_w, WK2, 1327104 / 4);
    tf32round4_kernel<<<(1327104 / 4 + 255) / 256, 256>>>(k3_w, WK3, 1327104 / 4);
    tf32round4_kernel<<<(62208 / 4 + 255) / 256, 256>>>(k4_w, WK4, 62208 / 4);
    tf32round4_kernel<<<(36864 / 4 + 255) / 256, 256>>>(pw_w, WPW, 36864 / 4);
    tf32round4_kernel<<<(36864 / 4 + 255) / 256, 256>>>(proj_w, WPROJ, 36864 / 4);

    // 1) qkv 1x1: 384 x 192 x 9216
    conv_mma<1, 4><<<dim3(HW / 128, C2 / 128, Bn), 256>>>(
        WQKV, XT, QKV1, nullptr, C2, Cc, Hh, Ww, Hh, Ww, 0);
    // 2) grouped 3x3 (groups=192)
    dwconv2_kernel<<<dim3(9, 192, Bn), 256>>>(QKV1, qkv_conv_w, QKV);
    // 3) cat = tf32([q ; y])
    cat4_kernel<<<(NE / 4 + 255) / 256, 256>>>(QKV, y, CAT);
    // 4) k3 conv 3x3 pad=1
    conv_mma<3, 4><<<dim3(HW / 128, C2 / 128, Bn), 256>>>(
        WK3, CAT, SC, nullptr, C2, C2, Hh, Ww, Hh, Ww, 1);
    // 5) avg pool 2x2
    pool4_kernel<<<(Bn * C2 * 576 + 255) / 256, 256>>>(CAT, POOL);
    // 6) k2 conv 3x3 pad=0 : 48x48 -> 46x46
    conv_mma<3, 4><<<dim3((46 * 46 + 127) / 128, C2 / 128, Bn), 256>>>(
        WK2, POOL, K2, nullptr, C2, C2, 48, 48, 46, 46, 0);
    // 7) SC = tf32(SC * sigmoid(CAT + upsample(K2)))
    sigmul4_kernel<<<(NE / 4 + 255) / 256, 256>>>(SC, CAT, K2);
    // 8) offset = conv3x3(sc, k4, pad=1), M=18
    conv_mma<3, 1><<<dim3(HW / 128, 1, Bn), 256>>>(
        WK4, SC, OFFb, nullptr, 18, C2, Hh, Ww, Hh, Ww, 1);
    // 9) deformable conv -> FEAT = tf32(relu(deform))
    deform_kernel<<<dim3(HW / 128, Gg, Bn), 128>>>(QKV, OFFb, deform_w, deform_b, FEAT);
    // 10) k = 1x1(FEAT) + pw_b
    conv_mma<1, 4><<<dim3(HW / 128, (Cc + 127) / 128, Bn), 256>>>(
        WPW, FEAT, Kb, pw_b, Cc, Cc, Hh, Ww, Hh, Ww, 0);
    // 11) row norms
    rownorm_kernel<<<2 * Bn * Cc, 256>>>(QKV, Kb, QN, KN);
    // 12) attention logits + softmax
    attn2_kernel<<<Bn * NH, 256>>>(QKV, Kb, QN, KN, temperature, ATTN);
    // 13) out = attn @ v
    attnv_kernel<<<dim3(HW / 256, NH, Bn), 256>>>(ATTN, QKV, AO);
    // 14) final 1x1 proj -> d_out
    conv_mma<1, 4><<<dim3(HW / 128, (Cc + 127) / 128, Bn), 256>>>(
        WPROJ, AO, out, nullptr, Cc, Cc, Hh, Ww, Hh, Ww, 0);
}

// round 7
// speedup vs baseline: 1.1817x; 1.1817x over previous
#include <cuda_runtime.h>
#include <math.h>
#include <stdint.h>

// ---------------------------------------------------------------------------
// Problem constants
// ---------------------------------------------------------------------------
#define Bn   4
#define Cc   192
#define C2   384
#define Hh   96
#define Ww   96
#define HW   (Hh*Ww)          // 9216
#define NH   8
#define HD   24
#define Gg   8
#define CG   24

// scratch offsets (floats)
#define OFF_QKV1  0ul
#define OFF_QKV   14155776ul
#define OFF_CAT   28311552ul
#define OFF_SC    42467328ul
#define OFF_POOL  56623104ul
#define OFF_K2    60162048ul
#define OFF_OFF   63412224ul
#define OFF_FEAT  64075776ul
#define OFF_K     71153664ul
#define OFF_AO    78231552ul
#define OFF_QN    85309440ul
#define OFF_KN    85310208ul
#define OFF_ATTN  85310976ul
#define OFF_XT    85329408ul     // 7077888
#define SCRATCH_TOTAL 92407296ul

__device__ float g_scratch[SCRATCH_TOTAL];

// ---------------------------------------------------------------------------
// tf32 / cp.async helpers
// ---------------------------------------------------------------------------
__device__ __forceinline__ float f2tf32(float x) {
    uint32_t u;
    asm("cvt.rna.tf32.f32 %0, %1;" : "=r"(u) : "f"(x));
    return __uint_as_float(u);
}

__device__ __forceinline__ void mma_16x8x8(float* c, const uint32_t* a,
                                           uint32_t b0, uint32_t b1) {
    asm volatile(
        "mma.sync.aligned.m16n8k8.row.col.f32.tf32.tf32.f32 "
        "{%0,%1,%2,%3}, {%4,%5,%6,%7}, {%8,%9}, {%0,%1,%2,%3};\n"
        : "+f"(c[0]), "+f"(c[1]), "+f"(c[2]), "+f"(c[3])
        : "r"(a[0]), "r"(a[1]), "r"(a[2]), "r"(a[3]), "r"(b0), "r"(b1));
}

__device__ __forceinline__ void cpasync4(uint32_t saddr, const float* g, bool pred) {
    int sz = pred ? 4 : 0;
    asm volatile("cp.async.ca.shared.global [%0], [%1], 4, %2;\n"
                 :: "r"(saddr), "l"(g), "r"(sz));
}
__device__ __forceinline__ void cpasync16(uint32_t saddr, const float* g) {
    asm volatile("cp.async.cg.shared.global [%0], [%1], 16;\n"
                 :: "r"(saddr), "l"(g));
}
#define CP_COMMIT() asm volatile("cp.async.commit_group;\n" ::: "memory")
#define CP_WAIT0()  asm volatile("cp.async.wait_group 0;\n" ::: "memory")
#define CP_WAIT1()  asm volatile("cp.async.wait_group 1;\n" ::: "memory")

// ---------------------------------------------------------------------------
// tf32 tensor-core implicit-GEMM conv.
// A (weights, fp32): LDG float4 -> f2tf32 -> STS, double-buffered (L1-friendly).
// B (activations, pre-rounded tf32): cp.async, 3-stage pipeline.
// BM = 32*FM, BN = 128, BK = 16, 256 threads = 8 warps (2M x 4N).
// For KS==1, N must be a multiple of 128.
// ---------------------------------------------------------------------------
template<int KS, int FM>
__global__ __launch_bounds__(256)
void conv_mma(const float* __restrict__ Wt,
              const float* __restrict__ X,
              float* __restrict__ Y,
              const float* __restrict__ bias,
              int M, int Cin, int IH, int IW,
              int OH, int OW, int pad)
{
    constexpr int BM   = 32 * FM;
    constexpr int BN   = 128;
    constexpr int BK   = 16;
    constexpr int ASTR = BM + 8;
    constexpr int BSTR = BN + 8;
    constexpr int AELE = BM * BK / 4;
    constexpr int AITER = (AELE + 255) / 256;

    __shared__ float As[2][BK * ASTR];
    __shared__ float Bs[3][BK * BSTR];

    const int N  = OH * OW;
    const int K  = Cin * KS * KS;
    const int bz = blockIdx.z;
    const int m0 = blockIdx.y * BM;
    const int n0 = blockIdx.x * BN;

    const int tid  = threadIdx.x;
    const int wid  = tid >> 5;
    const int lane = tid & 31;
    const int wm   = wid & 1;
    const int wn   = wid >> 1;
    const int mbase = wm * (16 * FM);
    const int nbase = wn * 32;
    const int lg = lane >> 2;
    const int lt = lane & 3;

    const float* Xb = X + (size_t)bz * Cin * IH * IW;

    float acc[FM][4][4];
    #pragma unroll
    for (int f = 0; f < FM; ++f)
        #pragma unroll
        for (int nf = 0; nf < 4; ++nf)
            #pragma unroll
            for (int r = 0; r < 4; ++r) acc[f][nf][r] = 0.f;

    // B-gather per-thread coords (KS==3 path)
    const int bn = tid & 127;
    const int gn = n0 + bn;
    const bool nvalid = gn < N;
    int oy = 0, ox = 0;
    if (KS == 3) { int g = nvalid ? gn : 0; oy = g / OW; ox = g - oy * OW; }

    float4 aReg[AITER];

    auto ldA = [&](int k0) {
        #pragma unroll
        for (int r = 0; r < AITER; ++r) {
            int e = tid + r * 256;
            float4 v = make_float4(0.f, 0.f, 0.f, 0.f);
            if (AELE == 512 || e < AELE) {
                int m  = e >> 2;
                int kq = e & 3;
                int gm = m0 + m;
                if (gm < M)
                    v = *reinterpret_cast<const float4*>(Wt + (size_t)gm * K + k0 + kq * 4);
            }
            aReg[r] = v;
        }
    };
    auto stA = [&](int buf) {
        #pragma unroll
        for (int r = 0; r < AITER; ++r) {
            int e = tid + r * 256;
            if (AELE == 512 || e < AELE) {
                int m  = e >> 2;
                int kq = e & 3;
                float* p = &As[buf][(kq * 4) * ASTR + m];
                p[0 * ASTR] = f2tf32(aReg[r].x);
                p[1 * ASTR] = f2tf32(aReg[r].y);
                p[2 * ASTR] = f2tf32(aReg[r].z);
                p[3 * ASTR] = f2tf32(aReg[r].w);
            }
        }
    };
    auto issueB = [&](int k0, int buf) {
        if (KS == 1) {
            #pragma unroll
            for (int r = 0; r < 2; ++r) {
                int o  = tid + r * 256;
                int k  = o >> 5;
                int c4 = (o & 31) * 4;
                uint32_t s = (uint32_t)__cvta_generic_to_shared(&Bs[buf][k * BSTR + c4]);
                cpasync16(s, Xb + (size_t)(k0 + k) * N + n0 + c4);
            }
        } else {
            #pragma unroll
            for (int r = 0; r < 8; ++r) {
                int k  = (tid >> 7) + 2 * r;
                int gk = k0 + k;
                int ic = gk / 9;
                int t  = gk - ic * 9;
                int tdy = (t >= 6) ? 2 : ((t >= 3) ? 1 : 0);
                int tdx = t - 3 * tdy;
                int iy = oy + tdy - pad;
                int ix = ox + tdx - pad;
                bool ok = nvalid && iy >= 0 && iy < IH && ix >= 0 && ix < IW;
                uint32_t s = (uint32_t)__cvta_generic_to_shared(&Bs[buf][k * BSTR + bn]);
                cpasync4(s, Xb + ((size_t)ic * IH + iy) * IW + ix, ok);
            }
        }
    };
    auto compute = [&](int abuf, int bbuf) {
        #pragma unroll
        for (int ks = 0; ks < 2; ++ks) {
            const int kr = ks * 8 + lt;
            uint32_t a[FM][4];
            #pragma unroll
            for (int f = 0; f < FM; ++f) {
                int mr = mbase + f * 16 + lg;
                a[f][0] = __float_as_uint(As[abuf][kr * ASTR + mr]);
                a[f][1] = __float_as_uint(As[abuf][kr * ASTR + mr + 8]);
                a[f][2] = __float_as_uint(As[abuf][(kr + 4) * ASTR + mr]);
                a[f][3] = __float_as_uint(As[abuf][(kr + 4) * ASTR + mr + 8]);
            }
            #pragma unroll
            for (int nf = 0; nf < 4; ++nf) {
                int nc = nbase + nf * 8 + lg;
                uint32_t b0 = __float_as_uint(Bs[bbuf][kr * BSTR + nc]);
                uint32_t b1 = __float_as_uint(Bs[bbuf][(kr + 4) * BSTR + nc]);
                #pragma unroll
                for (int f = 0; f < FM; ++f)
                    mma_16x8x8(acc[f][nf], a[f], b0, b1);
            }
        }
    };

    const int kTiles = K / BK;    // >= 12 for all our convs

    // prologue: B tiles 0 and 1 in flight, A tile 0 in smem
    issueB(0, 0); CP_COMMIT();
    issueB(BK, 1); CP_COMMIT();
    ldA(0); stA(0);
    CP_WAIT1(); __syncthreads();   // B0 ready, B1 outstanding

    for (int t = 0; t < kTiles; ++t) {
        if (t + 2 < kTiles) { issueB((t + 2) * BK, (t + 2) % 3); CP_COMMIT(); }
        if (t + 1 < kTiles) ldA((t + 1) * BK);
        compute(t & 1, t % 3);
        if (t + 1 < kTiles) {
            stA((t + 1) & 1);
            if (t + 2 < kTiles) { CP_WAIT1(); } else { CP_WAIT0(); }
            __syncthreads();
        }
    }

    // ---- epilogue ----
    #pragma unroll
    for (int f = 0; f < FM; ++f) {
        int r0 = m0 + mbase + f * 16 + lg;
        #pragma unroll
        for (int nf = 0; nf < 4; ++nf) {
            int cb = n0 + nbase + nf * 8 + 2 * lt;
            #pragma unroll
            for (int rr = 0; rr < 2; ++rr) {
                int m = r0 + rr * 8;
                if (m >= M) continue;
                float bval = bias ? bias[m] : 0.f;
                #pragma unroll
                for (int cc = 0; cc < 2; ++cc) {
                    int n = cb + cc;
                    if (n >= N) continue;
                    Y[((size_t)bz * M + m) * N + n] = acc[f][nf][rr * 2 + cc] + bval;
                }
            }
        }
    }
}

// ---------------------------------------------------------------------------
// vectorized tf32 rounding (n % 4 == 0)
// ---------------------------------------------------------------------------
__global__ void tf32round4_kernel(const float* __restrict__ X,
                                  float* __restrict__ Y, int n4)
{
    int i = blockIdx.x * 256 + threadIdx.x;
    if (i >= n4) return;
    float4 v = reinterpret_cast<const float4*>(X)[i];
    v.x = f2tf32(v.x); v.y = f2tf32(v.y); v.z = f2tf32(v.z); v.w = f2tf32(v.w);
    reinterpret_cast<float4*>(Y)[i] = v;
}

// ---------------------------------------------------------------------------
// grouped 3x3 conv, smem-tiled
// ---------------------------------------------------------------------------
__global__ __launch_bounds__(256)
void dwconv2_kernel(const float* __restrict__ X,
                    const float* __restrict__ W,
                    float* __restrict__ Y)
{
    __shared__ float xs[2][34][35];
    __shared__ float ws[36];

    const int tile = blockIdx.x;
    const int g    = blockIdx.y;
    const int b    = blockIdx.z;
    const int ty0  = (tile / 3) * 32;
    const int tx0  = (tile % 3) * 32;
    const int tid  = threadIdx.x;

    if (tid < 36) ws[tid] = W[(size_t)g * 36 + tid];

    for (int e = tid; e < 2 * 34 * 34; e += 256) {
        int c  = e / (34 * 34);
        int r  = e - c * 34 * 34;
        int yy = r / 34, xx = r - yy * 34;
        int gy = ty0 + yy - 1, gx = tx0 + xx - 1;
        float v = 0.f;
        if (gy >= 0 && gy < Hh && gx >= 0 && gx < Ww)
            v = X[((size_t)b * C2 + 2 * g + c) * HW + gy * Ww + gx];
        xs[c][yy][xx] = v;
    }
    __syncthreads();

    const int x  = tid & 31;
    const int yb = (tid >> 5) * 4;
    #pragma unroll
    for (int j = 0; j < 4; ++j) {
        int y = yb + j;
        float a0 = 0.f, a1 = 0.f;
        #pragma unroll
        for (int c = 0; c < 2; ++c)
            #pragma unroll
            for (int ky = 0; ky < 3; ++ky)
                #pragma unroll
                for (int kx = 0; kx < 3; ++kx) {
                    float v = xs[c][y + ky][x + kx];
                    a0 += v * ws[c * 9 + ky * 3 + kx];
                    a1 += v * ws[18 + c * 9 + ky * 3 + kx];
                }
        size_t o = ((size_t)b * C2 + 2 * g) * HW + (ty0 + y) * Ww + tx0 + x;
        Y[o]      = a0;
        Y[o + HW] = a1;
    }
}

// cat = tf32([q ; y]) (float4)
__global__ void cat4_kernel(const float* __restrict__ QKV,
                            const float* __restrict__ Yin,
                            float* __restrict__ CAT)
{
    int i = blockIdx.x * 256 + threadIdx.x;
    if (i >= Bn * C2 * HW / 4) return;
    int p4 = i % (HW / 4);
    int c  = (i / (HW / 4)) % C2;
    int b  = i / ((HW / 4) * C2);
    float4 v;
    if (c < Cc) v = reinterpret_cast<const float4*>(QKV + ((size_t)b * C2 + c) * HW)[p4];
    else        v = reinterpret_cast<const float4*>(Yin + ((size_t)b * Cc + (c - Cc)) * HW)[p4];
    v.x = f2tf32(v.x); v.y = f2tf32(v.y); v.z = f2tf32(v.z); v.w = f2tf32(v.w);
    reinterpret_cast<float4*>(CAT)[i] = v;
}

// 2x2 avg pool, 96 -> 48 (tf32 out, float4)
__global__ void pool4_kernel(const float* __restrict__ X, float* __restrict__ Y)
{
    int i = blockIdx.x * 256 + threadIdx.x;
    const int OHW4 = 48 * 48 / 4;      // 576
    if (i >= Bn * C2 * OHW4) return;
    int r  = i % OHW4;
    int bc = i / OHW4;
    int y  = r / 12;
    int x8 = (r % 12) * 8;
    const float* xp = X + (size_t)bc * HW;
    float4 r0a = *reinterpret_cast<const float4*>(xp + (2 * y) * Ww + x8);
    float4 r0b = *reinterpret_cast<const float4*>(xp + (2 * y) * Ww + x8 + 4);
    float4 r1a = *reinterpret_cast<const float4*>(xp + (2 * y + 1) * Ww + x8);
    float4 r1b = *reinterpret_cast<const float4*>(xp + (2 * y + 1) * Ww + x8 + 4);
    float4 o;
    o.x = f2tf32((r0a.x + r0a.y + r1a.x + r1a.y) * 0.25f);
    o.y = f2tf32((r0a.z + r0a.w + r1a.z + r1a.w) * 0.25f);
    o.z = f2tf32((r0b.x + r0b.y + r1b.x + r1b.y) * 0.25f);
    o.w = f2tf32((r0b.z + r0b.w + r1b.z + r1b.w) * 0.25f);
    reinterpret_cast<float4*>(Y)[i] = o;
}

// SC = tf32(SC * sigmoid(CAT + upsample(K2)))  (float4)
__global__ void sigmul4_kernel(float* __restrict__ SC,
                               const float* __restrict__ CAT,
                               const float* __restrict__ K2)
{
    int i = blockIdx.x * 256 + threadIdx.x;
    if (i >= Bn * C2 * HW / 4) return;
    int p4 = i % (HW / 4);
    int bc = i / (HW / 4);
    int p  = p4 * 4;
    int y  = p / Ww, x = p % Ww;
    int iy = (y * 46) / 96;
    const float* k2r = K2 + (size_t)bc * (46 * 46) + iy * 46;
    float4 cv = reinterpret_cast<const float4*>(CAT)[i];
    float4 sv = reinterpret_cast<const float4*>(SC)[i];
    float k0 = k2r[((x + 0) * 46) / 96];
    float k1 = k2r[((x + 1) * 46) / 96];
    float k2v = k2r[((x + 2) * 46) / 96];
    float k3 = k2r[((x + 3) * 46) / 96];
    sv.x = f2tf32(sv.x / (1.f + expf(-(cv.x + k0))));
    sv.y = f2tf32(sv.y / (1.f + expf(-(cv.y + k1))));
    sv.z = f2tf32(sv.z / (1.f + expf(-(cv.z + k2v))));
    sv.w = f2tf32(sv.w / (1.f + expf(-(cv.w + k3))));
    reinterpret_cast<float4*>(SC)[i] = sv;
}

// ---------------------------------------------------------------------------
// fused deformable conv; stores tf32(relu(out))
// ---------------------------------------------------------------------------
__global__ __launch_bounds__(128)
void deform_kernel(const float* __restrict__ Q,
                   const float* __restrict__ OFF,
                   const float* __restrict__ W,
                   const float* __restrict__ Bias,
                   float* __restrict__ Y)
{
    __shared__ float ws[24 * 216];
    const int g = blockIdx.y;
    const int b = blockIdx.z;
    const int tid = threadIdx.x;

    for (int e = tid; e < 24 * 216; e += 128) {
        int o = e / 216, r = e - o * 216;
        ws[e] = W[(size_t)(g * CG + o) * 216 + r];
    }
    __syncthreads();

    int p = blockIdx.x * 128 + tid;
    int y = p / Ww, x = p % Ww;
    const float* offb = OFF + (size_t)b * 18 * HW;

    float acc[24];
    #pragma unroll
    for (int o = 0; o < 24; ++o) acc[o] = Bias[g * CG + o];

    const float* qc = Q + ((size_t)b * C2 + g * CG) * HW;

    for (int t = 0; t < 9; ++t) {
        float dy = offb[(size_t)(2 * t) * HW + p];
        float dx = offb[(size_t)(2 * t + 1) * HW + p];
        float m  = 1.f / (1.f + expf(-offb[(size_t)t * HW + p]));
        float py = dy + (float)(y - 1 + t / 3);
        float px = dx + (float)(x - 1 + t % 3);
        float y0f = floorf(py), x0f = floorf(px);
        int   y0 = (int)y0f,    x0 = (int)x0f;
        float fy = py - y0f,    fx = px - x0f;
        float w00 = (1.f - fy) * (1.f - fx);
        float w01 = (1.f - fy) * fx;
        float w10 = fy * (1.f - fx);
        float w11 = fy * fx;
        bool vy0 = (y0 >= 0 && y0 <= Hh - 1), vy1 = (y0 + 1 >= 0 && y0 + 1 <= Hh - 1);
        bool vx0 = (x0 >= 0 && x0 <= Ww - 1), vx1 = (x0 + 1 >= 0 && x0 + 1 <= Ww - 1);
        int cy0 = min(max(y0, 0), Hh - 1),     cy1 = min(max(y0 + 1, 0), Hh - 1);
        int cx0 = min(max(x0, 0), Ww - 1),     cx1 = min(max(x0 + 1, 0), Ww - 1);
        int i00 = cy0 * Ww + cx0, i01 = cy0 * Ww + cx1;
        int i10 = cy1 * Ww + cx0, i11 = cy1 * Ww + cx1;
        w00 = (vy0 && vx0) ? w00 * m : 0.f;
        w01 = (vy0 && vx1) ? w01 * m : 0.f;
        w10 = (vy1 && vx0) ? w10 * m : 0.f;
        w11 = (vy1 && vx1) ? w11 * m : 0.f;

        #pragma unroll
        for (int i = 0; i < 24; ++i) {
            const float* qp = qc + (size_t)i * HW;
            float val = w00 * qp[i00] + w01 * qp[i01] + w10 * qp[i10] + w11 * qp[i11];
            const float* wr = &ws[i * 9 + t];
            #pragma unroll
            for (int o = 0; o < 24; ++o) acc[o] += val * wr[o * 216];
        }
    }
    #pragma unroll
    for (int o = 0; o < 24; ++o)
        Y[((size_t)b * Cc + g * CG + o) * HW + p] = f2tf32(fmaxf(acc[o], 0.f));
}

// ---------------------------------------------------------------------------
// row L2 norms (float4)
// ---------------------------------------------------------------------------
__global__ void rownorm_kernel(const float* __restrict__ QKV,
                               const float* __restrict__ Kb,
                               float* __restrict__ QN,
                               float* __restrict__ KN)
{
    int row   = blockIdx.x;
    int which = row / (Bn * Cc);
    row %= (Bn * Cc);
    int b = row / Cc, c = row % Cc;
    const float* src = which ? (Kb + ((size_t)b * Cc + c) * HW)
                             : (QKV + ((size_t)b * C2 + c) * HW);
    float s = 0.f;
    for (int n = threadIdx.x; n < HW / 4; n += 256) {
        float4 v = reinterpret_cast<const float4*>(src)[n];
        s += v.x * v.x + v.y * v.y + v.z * v.z + v.w * v.w;
    }
    __shared__ float sm[256];
    sm[threadIdx.x] = s;
    __syncthreads();
    for (int d = 128; d > 0; d >>= 1) {
        if (threadIdx.x < d) sm[threadIdx.x] += sm[threadIdx.x + d];
        __syncthreads();
    }
    if (threadIdx.x == 0) {
        float nrm = fmaxf(sqrtf(sm[0]), 1e-12f);
        (which ? KN : QN)[b * Cc + c] = nrm;
    }
}

// ---------------------------------------------------------------------------
// attention: one block per (b,h).  K-head staged through smem.
// ---------------------------------------------------------------------------
#define CNK 384
__global__ __launch_bounds__(256)
void attn2_kernel(const float* __restrict__ QKV,
                  const float* __restrict__ Kb,
                  const float* __restrict__ QN,
                  const float* __restrict__ KN,
                  const float* __restrict__ TEMP,
                  float* __restrict__ ATTN)
{
    __shared__ float ks_[24][CNK + 8];
    __shared__ float logits[24][24];

    const int b = blockIdx.x >> 3;
    const int h = blockIdx.x & 7;
    const int tid  = threadIdx.x;
    const int wid  = tid >> 5;
    const int lane = tid & 31;

    const float* qh = QKV + ((size_t)b * C2 + h * HD) * HW;
    const float* kh = Kb  + ((size_t)b * Cc + h * HD) * HW;

    float acc[3][24];
    #pragma unroll
    for (int r = 0; r < 3; ++r)
        #pragma unroll
        for (int j = 0; j < 24; ++j) acc[r][j] = 0.f;

    const float* q0p = qh + (size_t)(3 * wid + 0) * HW;
    const float* q1p = qh + (size_t)(3 * wid + 1) * HW;
    const float* q2p = qh + (size_t)(3 * wid + 2) * HW;

    for (int n0 = 0; n0 < HW; n0 += CNK) {
        __syncthreads();
        for (int e = tid; e < 24 * (CNK / 4); e += 256) {
            int j = e / (CNK / 4);
            int c = e - j * (CNK / 4);
            float4 v = *reinterpret_cast<const float4*>(kh + (size_t)j * HW + n0 + c * 4);
            ks_[j][c * 4 + 0] = v.x;
            ks_[j][c * 4 + 1] = v.y;
            ks_[j][c * 4 + 2] = v.z;
            ks_[j][c * 4 + 3] = v.w;
        }
        __syncthreads();

        for (int i = lane; i < CNK; i += 32) {
            int n = n0 + i;
            float q0 = q0p[n], q1 = q1p[n], q2 = q2p[n];
            #pragma unroll
            for (int j = 0; j < 24; ++j) {
                float kv = ks_[j][i];
                acc[0][j] += q0 * kv;
                acc[1][j] += q1 * kv;
                acc[2][j] += q2 * kv;
            }
        }
    }

    #pragma unroll
    for (int r = 0; r < 3; ++r)
        #pragma unroll
        for (int j = 0; j < 24; ++j) {
            float v = acc[r][j];
            for (int o = 16; o > 0; o >>= 1) v += __shfl_down_sync(0xffffffffu, v, o);
            if (lane == 0) logits[wid * 3 + r][j] = v;
        }
    __syncthreads();

    if (tid < 24) {
        int i = tid;
        float qn = QN[b * Cc + h * HD + i];
        float tp = TEMP[h];
        float s[24];
        float mx = -1e30f;
        #pragma unroll
        for (int j = 0; j < 24; ++j) {
            s[j] = logits[i][j] / (qn * KN[b * Cc + h * HD + j]) * tp;
            mx = fmaxf(mx, s[j]);
        }
        float sum = 0.f;
        #pragma unroll
        for (int j = 0; j < 24; ++j) { s[j] = expf(s[j] - mx); sum += s[j]; }
        float inv = 1.f / sum;
        #pragma unroll
        for (int j = 0; j < 24; ++j)
            ATTN[(((size_t)b * NH + h) * HD + i) * HD + j] = s[j] * inv;
    }
}

// out = attn @ v ; stores tf32 (AO feeds proj conv)
__global__ void attnv_kernel(const float* __restrict__ ATTN,
                             const float* __restrict__ QKV,
                             float* __restrict__ AO)
{
    int h = blockIdx.y, b = blockIdx.z;
    int n = blockIdx.x * 256 + threadIdx.x;
    __shared__ float a_s[HD * HD];
    for (int e = threadIdx.x; e < HD * HD; e += 256)
        a_s[e] = ATTN[((size_t)b * NH + h) * HD * HD + e];
    __syncthreads();
    const float* vb = QKV + ((size_t)b * C2 + Cc + h * HD) * HW;
    float acc[HD] = {};
    #pragma unroll
    for (int j = 0; j < HD; ++j) {
        float vv = vb[(size_t)j * HW + n];
        #pragma unroll
        for (int i = 0; i < HD; ++i) acc[i] += a_s[i * HD + j] * vv;
    }
    #pragma unroll
    for (int i = 0; i < HD; ++i)
        AO[((size_t)b * Cc + h * HD + i) * HW + n] = f2tf32(acc[i]);
}

// ---------------------------------------------------------------------------
// launcher
// ---------------------------------------------------------------------------
extern "C" void kernel_launch(void* const* d_in, const int* in_sizes, int n_in,
                              void* d_out, int out_size)
{
    const float* x           = (const float*)d_in[0];
    const float* y           = (const float*)d_in[1];
    const float* temperature = (const float*)d_in[2];
    const float* qkv_w       = (const float*)d_in[3];
    const float* qkv_conv_w  = (const float*)d_in[4];
    const float* proj_w      = (const float*)d_in[5];
    const float* k2_w        = (const float*)d_in[6];
    const float* k3_w        = (const float*)d_in[7];
    const float* k4_w        = (const float*)d_in[8];
    const float* deform_w    = (const float*)d_in[9];
    const float* deform_b    = (const float*)d_in[10];
    const float* pw_w        = (const float*)d_in[11];
    const float* pw_b        = (const float*)d_in[12];
    float* out = (float*)d_out;

    float* S = nullptr;
    cudaGetSymbolAddress((void**)&S, g_scratch);
    float* QKV1 = S + OFF_QKV1;
    float* QKV  = S + OFF_QKV;
    float* CAT  = S + OFF_CAT;
    float* SC   = S + OFF_SC;
    float* POOL = S + OFF_POOL;
    float* K2   = S + OFF_K2;
    float* OFFb = S + OFF_OFF;
    float* FEAT = S + OFF_FEAT;
    float* Kb   = S + OFF_K;
    float* AO   = S + OFF_AO;
    float* QN   = S + OFF_QN;
    float* KN   = S + OFF_KN;
    float* ATTN = S + OFF_ATTN;
    float* XT   = S + OFF_XT;

    const int NE = Bn * C2 * HW;
    const int NX = Bn * Cc * HW;

    // 0) XT = tf32(x)
    tf32round4_kernel<<<(NX / 4 + 255) / 256, 256>>>(x, XT, NX / 4);
    // 1) qkv 1x1: 384 x 192 x 9216
    conv_mma<1, 4><<<dim3(HW / 128, C2 / 128, Bn), 256>>>(
        qkv_w, XT, QKV1, nullptr, C2, Cc, Hh, Ww, Hh, Ww, 0);
    // 2) grouped 3x3 (groups=192)
    dwconv2_kernel<<<dim3(9, 192, Bn), 256>>>(QKV1, qkv_conv_w, QKV);
    // 3) cat = tf32([q ; y])
    cat4_kernel<<<(NE / 4 + 255) / 256, 256>>>(QKV, y, CAT);
    // 4) k3 conv 3x3 pad=1
    conv_mma<3, 4><<<dim3(HW / 128, C2 / 128, Bn), 256>>>(
        k3_w, CAT, SC, nullptr, C2, C2, Hh, Ww, Hh, Ww, 1);
    // 5) avg pool 2x2
    pool4_kernel<<<(Bn * C2 * 576 + 255) / 256, 256>>>(CAT, POOL);
    // 6) k2 conv 3x3 pad=0 : 48x48 -> 46x46
    conv_mma<3, 4><<<dim3((46 * 46 + 127) / 128, C2 / 128, Bn), 256>>>(
        k2_w, POOL, K2, nullptr, C2, C2, 48, 48, 46, 46, 0);
    // 7) SC = tf32(SC * sigmoid(CAT + upsample(K2)))
    sigmul4_kernel<<<(NE / 4 + 255) / 256, 256>>>(SC, CAT, K2);
    // 8) offset = conv3x3(sc, k4, pad=1), M=18
    conv_mma<3, 1><<<dim3(HW / 128, 1, Bn), 256>>>(
        k4_w, SC, OFFb, nullptr, 18, C2, Hh, Ww, Hh, Ww, 1);
    // 9) deformable conv -> FEAT = tf32(relu(deform))
    deform_kernel<<<dim3(HW / 128, Gg, Bn), 128>>>(QKV, OFFb, deform_w, deform_b, FEAT);
    // 10) k = 1x1(FEAT) + pw_b
    conv_mma<1, 4><<<dim3(HW / 128, (Cc + 127) / 128, Bn), 256>>>(
        pw_w, FEAT, Kb, pw_b, Cc, Cc, Hh, Ww, Hh, Ww, 0);
    // 11) row norms
    rownorm_kernel<<<2 * Bn * Cc, 256>>>(QKV, Kb, QN, KN);
    // 12) attention logits + softmax
    attn2_kernel<<<Bn * NH, 256>>>(QKV, Kb, QN, KN, temperature, ATTN);
    // 13) out = attn @ v
    attnv_kernel<<<dim3(HW / 256, NH, Bn), 256>>>(ATTN, QKV, AO);
    // 14) final 1x1 proj -> d_out
    conv_mma<1, 4><<<dim3(HW / 128, (Cc + 127) / 128, Bn), 256>>>(
        proj_w, AO, out, nullptr, Cc, Cc, Hh, Ww, Hh, Ww, 0);
}

// round 8
// speedup vs baseline: 1.3698x; 1.1592x over previous
#include <cuda_runtime.h>
#include <math.h>
#include <stdint.h>

// ---------------------------------------------------------------------------
// Problem constants
// ---------------------------------------------------------------------------
#define Bn   4
#define Cc   192
#define C2   384
#define Hh   96
#define Ww   96
#define HW   (Hh*Ww)          // 9216
#define NH   8
#define HD   24
#define Gg   8
#define CG   24

// scratch offsets (floats)
#define OFF_QKV1  0ul
#define OFF_QKV   14155776ul
#define OFF_CAT   28311552ul
#define OFF_SC    42467328ul
#define OFF_POOL  56623104ul
#define OFF_K2    60162048ul
#define OFF_OFF   63412224ul
#define OFF_FEAT  64075776ul
#define OFF_K     71153664ul
#define OFF_AO    78231552ul
#define OFF_QN    85309440ul
#define OFF_KN    85310208ul
#define OFF_ATTN  85310976ul
#define OFF_XT    85329408ul     // 7077888
#define SCRATCH_TOTAL 92407296ul

__device__ float g_scratch[SCRATCH_TOTAL];

// ---------------------------------------------------------------------------
// tf32 / cp.async helpers
// ---------------------------------------------------------------------------
__device__ __forceinline__ float f2tf32(float x) {
    uint32_t u;
    asm("cvt.rna.tf32.f32 %0, %1;" : "=r"(u) : "f"(x));
    return __uint_as_float(u);
}

__device__ __forceinline__ void mma_16x8x8(float* c, const uint32_t* a,
                                           uint32_t b0, uint32_t b1) {
    asm volatile(
        "mma.sync.aligned.m16n8k8.row.col.f32.tf32.tf32.f32 "
        "{%0,%1,%2,%3}, {%4,%5,%6,%7}, {%8,%9}, {%0,%1,%2,%3};\n"
        : "+f"(c[0]), "+f"(c[1]), "+f"(c[2]), "+f"(c[3])
        : "r"(a[0]), "r"(a[1]), "r"(a[2]), "r"(a[3]), "r"(b0), "r"(b1));
}

__device__ __forceinline__ void cpasync4(uint32_t saddr, const float* g, bool pred) {
    int sz = pred ? 4 : 0;
    asm volatile("cp.async.ca.shared.global [%0], [%1], 4, %2;\n"
                 :: "r"(saddr), "l"(g), "r"(sz));
}
__device__ __forceinline__ void cpasync16(uint32_t saddr, const float* g) {
    asm volatile("cp.async.cg.shared.global [%0], [%1], 16;\n"
                 :: "r"(saddr), "l"(g));
}
#define CP_COMMIT() asm volatile("cp.async.commit_group;\n" ::: "memory")
#define CP_WAIT0()  asm volatile("cp.async.wait_group 0;\n" ::: "memory")

// ---------------------------------------------------------------------------
// tf32 tensor-core implicit-GEMM conv (round-5 proven configuration).
// A (weights, fp32): LDG float4 -> f2tf32 -> STS, double-buffered (L1-friendly).
// B (activations, pre-rounded tf32): cp.async, 2-stage.
// BM = 32*FM, BN = 128, BK = 16, 256 threads = 8 warps (2M x 4N).
// For KS==1, N must be a multiple of 128.
// ---------------------------------------------------------------------------
template<int KS, int FM>
__global__ __launch_bounds__(256)
void conv_mma(const float* __restrict__ Wt,
              const float* __restrict__ X,
              float* __restrict__ Y,
              const float* __restrict__ bias,
              int M, int Cin, int IH, int IW,
              int OH, int OW, int pad)
{
    constexpr int BM   = 32 * FM;
    constexpr int BN   = 128;
    constexpr int BK   = 16;
    constexpr int ASTR = BM + 8;
    constexpr int BSTR = BN + 8;
    constexpr int AELE = BM * BK / 4;
    constexpr int AITER = (AELE + 255) / 256;

    __shared__ float As[2][BK * ASTR];
    __shared__ float Bs[2][BK * BSTR];

    const int N  = OH * OW;
    const int K  = Cin * KS * KS;
    const int bz = blockIdx.z;
    const int m0 = blockIdx.y * BM;
    const int n0 = blockIdx.x * BN;

    const int tid  = threadIdx.x;
    const int wid  = tid >> 5;
    const int lane = tid & 31;
    const int wm   = wid & 1;
    const int wn   = wid >> 1;
    const int mbase = wm * (16 * FM);
    const int nbase = wn * 32;
    const int lg = lane >> 2;
    const int lt = lane & 3;

    const float* Xb = X + (size_t)bz * Cin * IH * IW;

    float acc[FM][4][4];
    #pragma unroll
    for (int f = 0; f < FM; ++f)
        #pragma unroll
        for (int nf = 0; nf < 4; ++nf)
            #pragma unroll
            for (int r = 0; r < 4; ++r) acc[f][nf][r] = 0.f;

    // B-gather per-thread coords (KS==3 path)
    const int bn = tid & 127;
    const int gn = n0 + bn;
    const bool nvalid = gn < N;
    int oy = 0, ox = 0;
    if (KS == 3) { int g = nvalid ? gn : 0; oy = g / OW; ox = g - oy * OW; }

    float4 aReg[AITER];

    auto ldA = [&](int k0) {
        #pragma unroll
        for (int r = 0; r < AITER; ++r) {
            int e = tid + r * 256;
            float4 v = make_float4(0.f, 0.f, 0.f, 0.f);
            if (AELE == 512 || e < AELE) {
                int m  = e >> 2;
                int kq = e & 3;
                int gm = m0 + m;
                if (gm < M)
                    v = *reinterpret_cast<const float4*>(Wt + (size_t)gm * K + k0 + kq * 4);
            }
            aReg[r] = v;
        }
    };
    auto stA = [&](int buf) {
        #pragma unroll
        for (int r = 0; r < AITER; ++r) {
            int e = tid + r * 256;
            if (AELE == 512 || e < AELE) {
                int m  = e >> 2;
                int kq = e & 3;
                float* p = &As[buf][(kq * 4) * ASTR + m];
                p[0 * ASTR] = f2tf32(aReg[r].x);
                p[1 * ASTR] = f2tf32(aReg[r].y);
                p[2 * ASTR] = f2tf32(aReg[r].z);
                p[3 * ASTR] = f2tf32(aReg[r].w);
            }
        }
    };
    auto issueB = [&](int k0, int buf) {
        if (KS == 1) {
            #pragma unroll
            for (int r = 0; r < 2; ++r) {
                int o  = tid + r * 256;
                int k  = o >> 5;
                int c4 = (o & 31) * 4;
                uint32_t s = (uint32_t)__cvta_generic_to_shared(&Bs[buf][k * BSTR + c4]);
                cpasync16(s, Xb + (size_t)(k0 + k) * N + n0 + c4);
            }
        } else {
            #pragma unroll
            for (int r = 0; r < 8; ++r) {
                int k  = (tid >> 7) + 2 * r;
                int gk = k0 + k;
                int ic = gk / 9;
                int t  = gk - ic * 9;
                int tdy = (t >= 6) ? 2 : ((t >= 3) ? 1 : 0);
                int tdx = t - 3 * tdy;
                int iy = oy + tdy - pad;
                int ix = ox + tdx - pad;
                bool ok = nvalid && iy >= 0 && iy < IH && ix >= 0 && ix < IW;
                uint32_t s = (uint32_t)__cvta_generic_to_shared(&Bs[buf][k * BSTR + bn]);
                cpasync4(s, Xb + ((size_t)ic * IH + iy) * IW + ix, ok);
            }
        }
    };
    auto compute = [&](int buf) {
        #pragma unroll
        for (int ks = 0; ks < 2; ++ks) {
            const int kr = ks * 8 + lt;
            uint32_t a[FM][4];
            #pragma unroll
            for (int f = 0; f < FM; ++f) {
                int mr = mbase + f * 16 + lg;
                a[f][0] = __float_as_uint(As[buf][kr * ASTR + mr]);
                a[f][1] = __float_as_uint(As[buf][kr * ASTR + mr + 8]);
                a[f][2] = __float_as_uint(As[buf][(kr + 4) * ASTR + mr]);
                a[f][3] = __float_as_uint(As[buf][(kr + 4) * ASTR + mr + 8]);
            }
            #pragma unroll
            for (int nf = 0; nf < 4; ++nf) {
                int nc = nbase + nf * 8 + lg;
                uint32_t b0 = __float_as_uint(Bs[buf][kr * BSTR + nc]);
                uint32_t b1 = __float_as_uint(Bs[buf][(kr + 4) * BSTR + nc]);
                #pragma unroll
                for (int f = 0; f < FM; ++f)
                    mma_16x8x8(acc[f][nf], a[f], b0, b1);
            }
        }
    };

    const int kTiles = K / BK;
    issueB(0, 0); CP_COMMIT();
    ldA(0); stA(0);
    CP_WAIT0(); __syncthreads();

    for (int t = 0; t < kTiles; ++t) {
        if (t + 1 < kTiles) {
            issueB((t + 1) * BK, (t + 1) & 1); CP_COMMIT();
            ldA((t + 1) * BK);
        }
        compute(t & 1);
        if (t + 1 < kTiles) {
            stA((t + 1) & 1);
            CP_WAIT0(); __syncthreads();
        }
    }

    // ---- epilogue ----
    #pragma unroll
    for (int f = 0; f < FM; ++f) {
        int r0 = m0 + mbase + f * 16 + lg;
        #pragma unroll
        for (int nf = 0; nf < 4; ++nf) {
            int cb = n0 + nbase + nf * 8 + 2 * lt;
            #pragma unroll
            for (int rr = 0; rr < 2; ++rr) {
                int m = r0 + rr * 8;
                if (m >= M) continue;
                float bval = bias ? bias[m] : 0.f;
                #pragma unroll
                for (int cc = 0; cc < 2; ++cc) {
                    int n = cb + cc;
                    if (n >= N) continue;
                    Y[((size_t)bz * M + m) * N + n] = acc[f][nf][rr * 2 + cc] + bval;
                }
            }
        }
    }
}

// ---------------------------------------------------------------------------
// vectorized tf32 rounding (n % 4 == 0)
// ---------------------------------------------------------------------------
__global__ void tf32round4_kernel(const float* __restrict__ X,
                                  float* __restrict__ Y, int n4)
{
    int i = blockIdx.x * 256 + threadIdx.x;
    if (i >= n4) return;
    float4 v = reinterpret_cast<const float4*>(X)[i];
    v.x = f2tf32(v.x); v.y = f2tf32(v.y); v.z = f2tf32(v.z); v.w = f2tf32(v.w);
    reinterpret_cast<float4*>(Y)[i] = v;
}

// ---------------------------------------------------------------------------
// grouped 3x3 conv, smem-tiled
// ---------------------------------------------------------------------------
__global__ __launch_bounds__(256)
void dwconv2_kernel(const float* __restrict__ X,
                    const float* __restrict__ W,
                    float* __restrict__ Y)
{
    __shared__ float xs[2][34][35];
    __shared__ float ws[36];

    const int tile = blockIdx.x;
    const int g    = blockIdx.y;
    const int b    = blockIdx.z;
    const int ty0  = (tile / 3) * 32;
    const int tx0  = (tile % 3) * 32;
    const int tid  = threadIdx.x;

    if (tid < 36) ws[tid] = W[(size_t)g * 36 + tid];

    for (int e = tid; e < 2 * 34 * 34; e += 256) {
        int c  = e / (34 * 34);
        int r  = e - c * 34 * 34;
        int yy = r / 34, xx = r - yy * 34;
        int gy = ty0 + yy - 1, gx = tx0 + xx - 1;
        float v = 0.f;
        if (gy >= 0 && gy < Hh && gx >= 0 && gx < Ww)
            v = X[((size_t)b * C2 + 2 * g + c) * HW + gy * Ww + gx];
        xs[c][yy][xx] = v;
    }
    __syncthreads();

    const int x  = tid & 31;
    const int yb = (tid >> 5) * 4;
    #pragma unroll
    for (int j = 0; j < 4; ++j) {
        int y = yb + j;
        float a0 = 0.f, a1 = 0.f;
        #pragma unroll
        for (int c = 0; c < 2; ++c)
            #pragma unroll
            for (int ky = 0; ky < 3; ++ky)
                #pragma unroll
                for (int kx = 0; kx < 3; ++kx) {
                    float v = xs[c][y + ky][x + kx];
                    a0 += v * ws[c * 9 + ky * 3 + kx];
                    a1 += v * ws[18 + c * 9 + ky * 3 + kx];
                }
        size_t o = ((size_t)b * C2 + 2 * g) * HW + (ty0 + y) * Ww + tx0 + x;
        Y[o]      = a0;
        Y[o + HW] = a1;
    }
}

// cat = tf32([q ; y]) (float4)
__global__ void cat4_kernel(const float* __restrict__ QKV,
                            const float* __restrict__ Yin,
                            float* __restrict__ CAT)
{
    int i = blockIdx.x * 256 + threadIdx.x;
    if (i >= Bn * C2 * HW / 4) return;
    int p4 = i % (HW / 4);
    int c  = (i / (HW / 4)) % C2;
    int b  = i / ((HW / 4) * C2);
    float4 v;
    if (c < Cc) v = reinterpret_cast<const float4*>(QKV + ((size_t)b * C2 + c) * HW)[p4];
    else        v = reinterpret_cast<const float4*>(Yin + ((size_t)b * Cc + (c - Cc)) * HW)[p4];
    v.x = f2tf32(v.x); v.y = f2tf32(v.y); v.z = f2tf32(v.z); v.w = f2tf32(v.w);
    reinterpret_cast<float4*>(CAT)[i] = v;
}

// 2x2 avg pool, 96 -> 48 (tf32 out, float4)
__global__ void pool4_kernel(const float* __restrict__ X, float* __restrict__ Y)
{
    int i = blockIdx.x * 256 + threadIdx.x;
    const int OHW4 = 48 * 48 / 4;      // 576
    if (i >= Bn * C2 * OHW4) return;
    int r  = i % OHW4;
    int bc = i / OHW4;
    int y  = r / 12;
    int x8 = (r % 12) * 8;
    const float* xp = X + (size_t)bc * HW;
    float4 r0a = *reinterpret_cast<const float4*>(xp + (2 * y) * Ww + x8);
    float4 r0b = *reinterpret_cast<const float4*>(xp + (2 * y) * Ww + x8 + 4);
    float4 r1a = *reinterpret_cast<const float4*>(xp + (2 * y + 1) * Ww + x8);
    float4 r1b = *reinterpret_cast<const float4*>(xp + (2 * y + 1) * Ww + x8 + 4);
    float4 o;
    o.x = f2tf32((r0a.x + r0a.y + r1a.x + r1a.y) * 0.25f);
    o.y = f2tf32((r0a.z + r0a.w + r1a.z + r1a.w) * 0.25f);
    o.z = f2tf32((r0b.x + r0b.y + r1b.x + r1b.y) * 0.25f);
    o.w = f2tf32((r0b.z + r0b.w + r1b.z + r1b.w) * 0.25f);
    reinterpret_cast<float4*>(Y)[i] = o;
}

// SC = tf32(SC * sigmoid(CAT + upsample(K2)))  (float4)
__global__ void sigmul4_kernel(float* __restrict__ SC,
                               const float* __restrict__ CAT,
                               const float* __restrict__ K2)
{
    int i = blockIdx.x * 256 + threadIdx.x;
    if (i >= Bn * C2 * HW / 4) return;
    int p4 = i % (HW / 4);
    int bc = i / (HW / 4);
    int p  = p4 * 4;
    int y  = p / Ww, x = p % Ww;
    int iy = (y * 46) / 96;
    const float* k2r = K2 + (size_t)bc * (46 * 46) + iy * 46;
    float4 cv = reinterpret_cast<const float4*>(CAT)[i];
    float4 sv = reinterpret_cast<const float4*>(SC)[i];
    float k0 = k2r[((x + 0) * 46) / 96];
    float k1 = k2r[((x + 1) * 46) / 96];
    float k2v = k2r[((x + 2) * 46) / 96];
    float k3 = k2r[((x + 3) * 46) / 96];
    sv.x = f2tf32(sv.x / (1.f + expf(-(cv.x + k0))));
    sv.y = f2tf32(sv.y / (1.f + expf(-(cv.y + k1))));
    sv.z = f2tf32(sv.z / (1.f + expf(-(cv.z + k2v))));
    sv.w = f2tf32(sv.w / (1.f + expf(-(cv.w + k3))));
    reinterpret_cast<float4*>(SC)[i] = sv;
}

// ---------------------------------------------------------------------------
// fused deformable conv; stores tf32(relu(out))
// ---------------------------------------------------------------------------
__global__ __launch_bounds__(128)
void deform_kernel(const float* __restrict__ Q,
                   const float* __restrict__ OFF,
                   const float* __restrict__ W,
                   const float* __restrict__ Bias,
                   float* __restrict__ Y)
{
    __shared__ float ws[24 * 216];
    const int g = blockIdx.y;
    const int b = blockIdx.z;
    const int tid = threadIdx.x;

    for (int e = tid; e < 24 * 216; e += 128) {
        int o = e / 216, r = e - o * 216;
        ws[e] = W[(size_t)(g * CG + o) * 216 + r];
    }
    __syncthreads();

    int p = blockIdx.x * 128 + tid;
    int y = p / Ww, x = p % Ww;
    const float* offb = OFF + (size_t)b * 18 * HW;

    float acc[24];
    #pragma unroll
    for (int o = 0; o < 24; ++o) acc[o] = Bias[g * CG + o];

    const float* qc = Q + ((size_t)b * C2 + g * CG) * HW;

    for (int t = 0; t < 9; ++t) {
        float dy = offb[(size_t)(2 * t) * HW + p];
        float dx = offb[(size_t)(2 * t + 1) * HW + p];
        float m  = 1.f / (1.f + expf(-offb[(size_t)t * HW + p]));
        float py = dy + (float)(y - 1 + t / 3);
        float px = dx + (float)(x - 1 + t % 3);
        float y0f = floorf(py), x0f = floorf(px);
        int   y0 = (int)y0f,    x0 = (int)x0f;
        float fy = py - y0f,    fx = px - x0f;
        float w00 = (1.f - fy) * (1.f - fx);
        float w01 = (1.f - fy) * fx;
        float w10 = fy * (1.f - fx);
        float w11 = fy * fx;
        bool vy0 = (y0 >= 0 && y0 <= Hh - 1), vy1 = (y0 + 1 >= 0 && y0 + 1 <= Hh - 1);
        bool vx0 = (x0 >= 0 && x0 <= Ww - 1), vx1 = (x0 + 1 >= 0 && x0 + 1 <= Ww - 1);
        int cy0 = min(max(y0, 0), Hh - 1),     cy1 = min(max(y0 + 1, 0), Hh - 1);
        int cx0 = min(max(x0, 0), Ww - 1),     cx1 = min(max(x0 + 1, 0), Ww - 1);
        int i00 = cy0 * Ww + cx0, i01 = cy0 * Ww + cx1;
        int i10 = cy1 * Ww + cx0, i11 = cy1 * Ww + cx1;
        w00 = (vy0 && vx0) ? w00 * m : 0.f;
        w01 = (vy0 && vx1) ? w01 * m : 0.f;
        w10 = (vy1 && vx0) ? w10 * m : 0.f;
        w11 = (vy1 && vx1) ? w11 * m : 0.f;

        #pragma unroll
        for (int i = 0; i < 24; ++i) {
            const float* qp = qc + (size_t)i * HW;
            float val = w00 * qp[i00] + w01 * qp[i01] + w10 * qp[i10] + w11 * qp[i11];
            const float* wr = &ws[i * 9 + t];
            #pragma unroll
            for (int o = 0; o < 24; ++o) acc[o] += val * wr[o * 216];
        }
    }
    #pragma unroll
    for (int o = 0; o < 24; ++o)
        Y[((size_t)b * Cc + g * CG + o) * HW + p] = f2tf32(fmaxf(acc[o], 0.f));
}

// ---------------------------------------------------------------------------
// row L2 norms (float4)
// ---------------------------------------------------------------------------
__global__ void rownorm_kernel(const float* __restrict__ QKV,
                               const float* __restrict__ Kb,
                               float* __restrict__ QN,
                               float* __restrict__ KN)
{
    int row   = blockIdx.x;
    int which = row / (Bn * Cc);
    row %= (Bn * Cc);
    int b = row / Cc, c = row % Cc;
    const float* src = which ? (Kb + ((size_t)b * Cc + c) * HW)
                             : (QKV + ((size_t)b * C2 + c) * HW);
    float s = 0.f;
    for (int n = threadIdx.x; n < HW / 4; n += 256) {
        float4 v = reinterpret_cast<const float4*>(src)[n];
        s += v.x * v.x + v.y * v.y + v.z * v.z + v.w * v.w;
    }
    __shared__ float sm[256];
    sm[threadIdx.x] = s;
    __syncthreads();
    for (int d = 128; d > 0; d >>= 1) {
        if (threadIdx.x < d) sm[threadIdx.x] += sm[threadIdx.x + d];
        __syncthreads();
    }
    if (threadIdx.x == 0) {
        float nrm = fmaxf(sqrtf(sm[0]), 1e-12f);
        (which ? KN : QN)[b * Cc + c] = nrm;
    }
}

// ---------------------------------------------------------------------------
// attention: one block per (b,h).  K-head staged through smem.
// ---------------------------------------------------------------------------
#define CNK 384
__global__ __launch_bounds__(256)
void attn2_kernel(const float* __restrict__ QKV,
                  const float* __restrict__ Kb,
                  const float* __restrict__ QN,
                  const float* __restrict__ KN,
                  const float* __restrict__ TEMP,
                  float* __restrict__ ATTN)
{
    __shared__ float ks_[24][CNK + 8];
    __shared__ float logits[24][24];

    const int b = blockIdx.x >> 3;
    const int h = blockIdx.x & 7;
    const int tid  = threadIdx.x;
    const int wid  = tid >> 5;
    const int lane = tid & 31;

    const float* qh = QKV + ((size_t)b * C2 + h * HD) * HW;
    const float* kh = Kb  + ((size_t)b * Cc + h * HD) * HW;

    float acc[3][24];
    #pragma unroll
    for (int r = 0; r < 3; ++r)
        #pragma unroll
        for (int j = 0; j < 24; ++j) acc[r][j] = 0.f;

    const float* q0p = qh + (size_t)(3 * wid + 0) * HW;
    const float* q1p = qh + (size_t)(3 * wid + 1) * HW;
    const float* q2p = qh + (size_t)(3 * wid + 2) * HW;

    for (int n0 = 0; n0 < HW; n0 += CNK) {
        __syncthreads();
        for (int e = tid; e < 24 * (CNK / 4); e += 256) {
            int j = e / (CNK / 4);
            int c = e - j * (CNK / 4);
            float4 v = *reinterpret_cast<const float4*>(kh + (size_t)j * HW + n0 + c * 4);
            ks_[j][c * 4 + 0] = v.x;
            ks_[j][c * 4 + 1] = v.y;
            ks_[j][c * 4 + 2] = v.z;
            ks_[j][c * 4 + 3] = v.w;
        }
        __syncthreads();

        for (int i = lane; i < CNK; i += 32) {
            int n = n0 + i;
            float q0 = q0p[n], q1 = q1p[n], q2 = q2p[n];
            #pragma unroll
            for (int j = 0; j < 24; ++j) {
                float kv = ks_[j][i];
                acc[0][j] += q0 * kv;
                acc[1][j] += q1 * kv;
                acc[2][j] += q2 * kv;
            }
        }
    }

    #pragma unroll
    for (int r = 0; r < 3; ++r)
        #pragma unroll
        for (int j = 0; j < 24; ++j) {
            float v = acc[r][j];
            for (int o = 16; o > 0; o >>= 1) v += __shfl_down_sync(0xffffffffu, v, o);
            if (lane == 0) logits[wid * 3 + r][j] = v;
        }
    __syncthreads();

    if (tid < 24) {
        int i = tid;
        float qn = QN[b * Cc + h * HD + i];
        float tp = TEMP[h];
        float s[24];
        float mx = -1e30f;
        #pragma unroll
        for (int j = 0; j < 24; ++j) {
            s[j] = logits[i][j] / (qn * KN[b * Cc + h * HD + j]) * tp;
            mx = fmaxf(mx, s[j]);
        }
        float sum = 0.f;
        #pragma unroll
        for (int j = 0; j < 24; ++j) { s[j] = expf(s[j] - mx); sum += s[j]; }
        float inv = 1.f / sum;
        #pragma unroll
        for (int j = 0; j < 24; ++j)
            ATTN[(((size_t)b * NH + h) * HD + i) * HD + j] = s[j] * inv;
    }
}

// out = attn @ v ; stores tf32 (AO feeds proj conv)
__global__ void attnv_kernel(const float* __restrict__ ATTN,
                             const float* __restrict__ QKV,
                             float* __restrict__ AO)
{
    int h = blockIdx.y, b = blockIdx.z;
    int n = blockIdx.x * 256 + threadIdx.x;
    __shared__ float a_s[HD * HD];
    for (int e = threadIdx.x; e < HD * HD; e += 256)
        a_s[e] = ATTN[((size_t)b * NH + h) * HD * HD + e];
    __syncthreads();
    const float* vb = QKV + ((size_t)b * C2 + Cc + h * HD) * HW;
    float acc[HD] = {};
    #pragma unroll
    for (int j = 0; j < HD; ++j) {
        float vv = vb[(size_t)j * HW + n];
        #pragma unroll
        for (int i = 0; i < HD; ++i) acc[i] += a_s[i * HD + j] * vv;
    }
    #pragma unroll
    for (int i = 0; i < HD; ++i)
        AO[((size_t)b * Cc + h * HD + i) * HW + n] = f2tf32(acc[i]);
}

// ---------------------------------------------------------------------------
// launcher
// ---------------------------------------------------------------------------
extern "C" void kernel_launch(void* const* d_in, const int* in_sizes, int n_in,
                              void* d_out, int out_size)
{
    const float* x           = (const float*)d_in[0];
    const float* y           = (const float*)d_in[1];
    const float* temperature = (const float*)d_in[2];
    const float* qkv_w       = (const float*)d_in[3];
    const float* qkv_conv_w  = (const float*)d_in[4];
    const float* proj_w      = (const float*)d_in[5];
    const float* k2_w        = (const float*)d_in[6];
    const float* k3_w        = (const float*)d_in[7];
    const float* k4_w        = (const float*)d_in[8];
    const float* deform_w    = (const float*)d_in[9];
    const float* deform_b    = (const float*)d_in[10];
    const float* pw_w        = (const float*)d_in[11];
    const float* pw_b        = (const float*)d_in[12];
    float* out = (float*)d_out;

    float* S = nullptr;
    cudaGetSymbolAddress((void**)&S, g_scratch);
    float* QKV1 = S + OFF_QKV1;
    float* QKV  = S + OFF_QKV;
    float* CAT  = S + OFF_CAT;
    float* SC   = S + OFF_SC;
    float* POOL = S + OFF_POOL;
    float* K2   = S + OFF_K2;
    float* OFFb = S + OFF_OFF;
    float* FEAT = S + OFF_FEAT;
    float* Kb   = S + OFF_K;
    float* AO   = S + OFF_AO;
    float* QN   = S + OFF_QN;
    float* KN   = S + OFF_KN;
    float* ATTN = S + OFF_ATTN;
    float* XT   = S + OFF_XT;

    const int NE = Bn * C2 * HW;
    const int NX = Bn * Cc * HW;

    // 0) XT = tf32(x)
    tf32round4_kernel<<<(NX / 4 + 255) / 256, 256>>>(x, XT, NX / 4);
    // 1) qkv 1x1: 384 x 192 x 9216
    conv_mma<1, 4><<<dim3(HW / 128, C2 / 128, Bn), 256>>>(
        qkv_w, XT, QKV1, nullptr, C2, Cc, Hh, Ww, Hh, Ww, 0);
    // 2) grouped 3x3 (groups=192)
    dwconv2_kernel<<<dim3(9, 192, Bn), 256>>>(QKV1, qkv_conv_w, QKV);
    // 3) cat = tf32([q ; y])
    cat4_kernel<<<(NE / 4 + 255) / 256, 256>>>(QKV, y, CAT);
    // 4) k3 conv 3x3 pad=1
    conv_mma<3, 4><<<dim3(HW / 128, C2 / 128, Bn), 256>>>(
        k3_w, CAT, SC, nullptr, C2, C2, Hh, Ww, Hh, Ww, 1);
    // 5) avg pool 2x2
    pool4_kernel<<<(Bn * C2 * 576 + 255) / 256, 256>>>(CAT, POOL);
    // 6) k2 conv 3x3 pad=0 : 48x48 -> 46x46
    conv_mma<3, 4><<<dim3((46 * 46 + 127) / 128, C2 / 128, Bn), 256>>>(
        k2_w, POOL, K2, nullptr, C2, C2, 48, 48, 46, 46, 0);
    // 7) SC = tf32(SC * sigmoid(CAT + upsample(K2)))
    sigmul4_kernel<<<(NE / 4 + 255) / 256, 256>>>(SC, CAT, K2);
    // 8) offset = conv3x3(sc, k4, pad=1), M=18
    conv_mma<3, 1><<<dim3(HW / 128, 1, Bn), 256>>>(
        k4_w, SC, OFFb, nullptr, 18, C2, Hh, Ww, Hh, Ww, 1);
    // 9) deformable conv -> FEAT = tf32(relu(deform))
    deform_kernel<<<dim3(HW / 128, Gg, Bn), 128>>>(QKV, OFFb, deform_w, deform_b, FEAT);
    // 10) k = 1x1(FEAT) + pw_b
    conv_mma<1, 4><<<dim3(HW / 128, (Cc + 127) / 128, Bn), 256>>>(
        pw_w, FEAT, Kb, pw_b, Cc, Cc, Hh, Ww, Hh, Ww, 0);
    // 11) row norms
    rownorm_kernel<<<2 * Bn * Cc, 256>>>(QKV, Kb, QN, KN);
    // 12) attention logits + softmax
    attn2_kernel<<<Bn * NH, 256>>>(QKV, Kb, QN, KN, temperature, ATTN);
    // 13) out = attn @ v
    attnv_kernel<<<dim3(HW / 256, NH, Bn), 256>>>(ATTN, QKV, AO);
    // 14) final 1x1 proj -> d_out
    conv_mma<1, 4><<<dim3(HW / 128, (Cc + 127) / 128, Bn), 256>>>(
        proj_w, AO, out, nullptr, Cc, Cc, Hh, Ww, Hh, Ww, 0);
}

// round 9
// speedup vs baseline: 1.6636x; 1.2144x over previous
#include <cuda_runtime.h>
#include <math.h>
#include <stdint.h>

// ---------------------------------------------------------------------------
// Problem constants
// ---------------------------------------------------------------------------
#define Bn   4
#define Cc   192
#define C2   384
#define Hh   96
#define Ww   96
#define HW   (Hh*Ww)          // 9216
#define NH   8
#define HD   24
#define Gg   8
#define CG   24

// scratch offsets (floats)
#define OFF_QKV1  0ul
#define OFF_QKV   14155776ul
#define OFF_CAT   28311552ul
#define OFF_SC    42467328ul
#define OFF_POOL  56623104ul
#define OFF_K2    60162048ul
#define OFF_OFF   63412224ul
#define OFF_FEAT  64075776ul
#define OFF_K     71153664ul
#define OFF_AO    78231552ul
#define OFF_QN    85309440ul
#define OFF_KN    85310208ul
#define OFF_ATTN  85310976ul
#define OFF_XT    85329408ul     // 7077888
#define OFF_WK3P  92407296ul     // 1327104
#define OFF_WK2P  93734400ul     // 1327104
#define OFF_WK4P  95061504ul     // 62208
#define SCRATCH_TOTAL 95123712ul

__device__ float g_scratch[SCRATCH_TOTAL];

// ---------------------------------------------------------------------------
// tf32 / cp.async helpers
// ---------------------------------------------------------------------------
__device__ __forceinline__ float f2tf32(float x) {
    uint32_t u;
    asm("cvt.rna.tf32.f32 %0, %1;" : "=r"(u) : "f"(x));
    return __uint_as_float(u);
}

__device__ __forceinline__ void mma_16x8x8(float* c, const uint32_t* a,
                                           uint32_t b0, uint32_t b1) {
    asm volatile(
        "mma.sync.aligned.m16n8k8.row.col.f32.tf32.tf32.f32 "
        "{%0,%1,%2,%3}, {%4,%5,%6,%7}, {%8,%9}, {%0,%1,%2,%3};\n"
        : "+f"(c[0]), "+f"(c[1]), "+f"(c[2]), "+f"(c[3])
        : "r"(a[0]), "r"(a[1]), "r"(a[2]), "r"(a[3]), "r"(b0), "r"(b1));
}

__device__ __forceinline__ void cpasync4(uint32_t saddr, const float* g, bool pred) {
    int sz = pred ? 4 : 0;
    asm volatile("cp.async.ca.shared.global [%0], [%1], 4, %2;\n"
                 :: "r"(saddr), "l"(g), "r"(sz));
}
__device__ __forceinline__ void cpasync16(uint32_t saddr, const float* g) {
    asm volatile("cp.async.cg.shared.global [%0], [%1], 16;\n"
                 :: "r"(saddr), "l"(g));
}
#define CP_COMMIT() asm volatile("cp.async.commit_group;\n" ::: "memory")
#define CP_WAIT0()  asm volatile("cp.async.wait_group 0;\n" ::: "memory")

// ---------------------------------------------------------------------------
// Weight K-order permutation for 3x3 convs: Wp[m][t][ic] = W[m][ic][t].
// Lets every 16-wide k-tile of the implicit GEMM share ONE tap (Cin % 16 == 0),
// collapsing per-copy address ALU to a single IMAD.
// ---------------------------------------------------------------------------
__global__ void permw_kernel(const float* __restrict__ W,
                             float* __restrict__ Wp, int M, int Cin)
{
    int K = Cin * 9;
    int i = blockIdx.x * 256 + threadIdx.x;
    if (i >= M * K) return;
    int m = i / K;
    int r = i - m * K;          // r = t*Cin + ic
    int t = r / Cin;
    int ic = r - t * Cin;
    Wp[i] = W[(size_t)m * K + ic * 9 + t];
}

// ---------------------------------------------------------------------------
// tf32 tensor-core implicit-GEMM conv (round-5 proven pipeline).
// A (weights fp32, K-order = tap-major for KS==3): LDG float4 -> f2tf32 -> STS.
// B (activations pre-rounded tf32): cp.async, 2-stage.
// KS==3 requires Cin % 16 == 0 (constant tap per k-tile).
// For KS==1, N must be a multiple of 128.
// ---------------------------------------------------------------------------
template<int KS, int FM>
__global__ __launch_bounds__(256)
void conv_mma(const float* __restrict__ Wt,
              const float* __restrict__ X,
              float* __restrict__ Y,
              const float* __restrict__ bias,
              int M, int Cin, int IH, int IW,
              int OH, int OW, int pad)
{
    constexpr int BM   = 32 * FM;
    constexpr int BN   = 128;
    constexpr int BK   = 16;
    constexpr int ASTR = BM + 8;
    constexpr int BSTR = BN + 8;
    constexpr int AELE = BM * BK / 4;
    constexpr int AITER = (AELE + 255) / 256;

    __shared__ float As[2][BK * ASTR];
    __shared__ float Bs[2][BK * BSTR];

    const int N  = OH * OW;
    const int K  = Cin * KS * KS;
    const int IHW = IH * IW;
    const int bz = blockIdx.z;
    const int m0 = blockIdx.y * BM;
    const int n0 = blockIdx.x * BN;

    const int tid  = threadIdx.x;
    const int wid  = tid >> 5;
    const int lane = tid & 31;
    const int wm   = wid & 1;
    const int wn   = wid >> 1;
    const int mbase = wm * (16 * FM);
    const int nbase = wn * 32;
    const int lg = lane >> 2;
    const int lt = lane & 3;

    const float* Xb = X + (size_t)bz * Cin * IHW;

    float acc[FM][4][4];
    #pragma unroll
    for (int f = 0; f < FM; ++f)
        #pragma unroll
        for (int nf = 0; nf < 4; ++nf)
            #pragma unroll
            for (int r = 0; r < 4; ++r) acc[f][nf][r] = 0.f;

    // B-gather per-thread coords (KS==3 path)
    const int bn = tid & 127;
    const int gn = n0 + bn;
    const bool nvalid = gn < N;
    int oy = 0, ox = 0;
    if (KS == 3) { int g = nvalid ? gn : 0; oy = g / OW; ox = g - oy * OW; }

    float4 aReg[AITER];

    auto ldA = [&](int k0) {
        #pragma unroll
        for (int r = 0; r < AITER; ++r) {
            int e = tid + r * 256;
            float4 v = make_float4(0.f, 0.f, 0.f, 0.f);
            if (AELE == 512 || e < AELE) {
                int m  = e >> 2;
                int kq = e & 3;
                int gm = m0 + m;
                if (gm < M)
                    v = *reinterpret_cast<const float4*>(Wt + (size_t)gm * K + k0 + kq * 4);
            }
            aReg[r] = v;
        }
    };
    auto stA = [&](int buf) {
        #pragma unroll
        for (int r = 0; r < AITER; ++r) {
            int e = tid + r * 256;
            if (AELE == 512 || e < AELE) {
                int m  = e >> 2;
                int kq = e & 3;
                float* p = &As[buf][(kq * 4) * ASTR + m];
                p[0 * ASTR] = f2tf32(aReg[r].x);
                p[1 * ASTR] = f2tf32(aReg[r].y);
                p[2 * ASTR] = f2tf32(aReg[r].z);
                p[3 * ASTR] = f2tf32(aReg[r].w);
            }
        }
    };
    auto issueB = [&](int k0, int buf) {
        if (KS == 1) {
            #pragma unroll
            for (int r = 0; r < 2; ++r) {
                int o  = tid + r * 256;
                int k  = o >> 5;
                int c4 = (o & 31) * 4;
                uint32_t s = (uint32_t)__cvta_generic_to_shared(&Bs[buf][k * BSTR + c4]);
                cpasync16(s, Xb + (size_t)(k0 + k) * N + n0 + c4);
            }
        } else {
            // tap-major K: whole tile shares one tap (uniform across block)
            int tp  = k0 / Cin;              // uniform
            int icb = k0 - tp * Cin;
            int tdy = (tp >= 6) ? 2 : ((tp >= 3) ? 1 : 0);
            int tdx = tp - 3 * tdy;
            int iy  = oy + tdy - pad;
            int ix  = ox + tdx - pad;
            bool ok = nvalid && iy >= 0 && iy < IH && ix >= 0 && ix < IW;
            const float* base = Xb + (size_t)iy * IW + ix;
            #pragma unroll
            for (int r = 0; r < 8; ++r) {
                int k = (tid >> 7) + 2 * r;
                uint32_t s = (uint32_t)__cvta_generic_to_shared(&Bs[buf][k * BSTR + bn]);
                cpasync4(s, base + (icb + k) * IHW, ok);
            }
        }
    };
    auto compute = [&](int buf) {
        #pragma unroll
        for (int ks = 0; ks < 2; ++ks) {
            const int kr = ks * 8 + lt;
            uint32_t a[FM][4];
            #pragma unroll
            for (int f = 0; f < FM; ++f) {
                int mr = mbase + f * 16 + lg;
                a[f][0] = __float_as_uint(As[buf][kr * ASTR + mr]);
                a[f][1] = __float_as_uint(As[buf][kr * ASTR + mr + 8]);
                a[f][2] = __float_as_uint(As[buf][(kr + 4) * ASTR + mr]);
                a[f][3] = __float_as_uint(As[buf][(kr + 4) * ASTR + mr + 8]);
            }
            #pragma unroll
            for (int nf = 0; nf < 4; ++nf) {
                int nc = nbase + nf * 8 + lg;
                uint32_t b0 = __float_as_uint(Bs[buf][kr * BSTR + nc]);
                uint32_t b1 = __float_as_uint(Bs[buf][(kr + 4) * BSTR + nc]);
                #pragma unroll
                for (int f = 0; f < FM; ++f)
                    mma_16x8x8(acc[f][nf], a[f], b0, b1);
            }
        }
    };

    const int kTiles = K / BK;
    issueB(0, 0); CP_COMMIT();
    ldA(0); stA(0);
    CP_WAIT0(); __syncthreads();

    for (int t = 0; t < kTiles; ++t) {
        if (t + 1 < kTiles) {
            issueB((t + 1) * BK, (t + 1) & 1); CP_COMMIT();
            ldA((t + 1) * BK);
        }
        compute(t & 1);
        if (t + 1 < kTiles) {
            stA((t + 1) & 1);
            CP_WAIT0(); __syncthreads();
        }
    }

    // ---- epilogue ----
    #pragma unroll
    for (int f = 0; f < FM; ++f) {
        int r0 = m0 + mbase + f * 16 + lg;
        #pragma unroll
        for (int nf = 0; nf < 4; ++nf) {
            int cb = n0 + nbase + nf * 8 + 2 * lt;
            #pragma unroll
            for (int rr = 0; rr < 2; ++rr) {
                int m = r0 + rr * 8;
                if (m >= M) continue;
                float bval = bias ? bias[m] : 0.f;
                #pragma unroll
                for (int cc = 0; cc < 2; ++cc) {
                    int n = cb + cc;
                    if (n >= N) continue;
                    Y[((size_t)bz * M + m) * N + n] = acc[f][nf][rr * 2 + cc] + bval;
                }
            }
        }
    }
}

// ---------------------------------------------------------------------------
// vectorized tf32 rounding (n % 4 == 0)
// ---------------------------------------------------------------------------
__global__ void tf32round4_kernel(const float* __restrict__ X,
                                  float* __restrict__ Y, int n4)
{
    int i = blockIdx.x * 256 + threadIdx.x;
    if (i >= n4) return;
    float4 v = reinterpret_cast<const float4*>(X)[i];
    v.x = f2tf32(v.x); v.y = f2tf32(v.y); v.z = f2tf32(v.z); v.w = f2tf32(v.w);
    reinterpret_cast<float4*>(Y)[i] = v;
}

// ---------------------------------------------------------------------------
// grouped 3x3 conv, smem-tiled
// ---------------------------------------------------------------------------
__global__ __launch_bounds__(256)
void dwconv2_kernel(const float* __restrict__ X,
                    const float* __restrict__ W,
                    float* __restrict__ Y)
{
    __shared__ float xs[2][34][35];
    __shared__ float ws[36];

    const int tile = blockIdx.x;
    const int g    = blockIdx.y;
    const int b    = blockIdx.z;
    const int ty0  = (tile / 3) * 32;
    const int tx0  = (tile % 3) * 32;
    const int tid  = threadIdx.x;

    if (tid < 36) ws[tid] = W[(size_t)g * 36 + tid];

    for (int e = tid; e < 2 * 34 * 34; e += 256) {
        int c  = e / (34 * 34);
        int r  = e - c * 34 * 34;
        int yy = r / 34, xx = r - yy * 34;
        int gy = ty0 + yy - 1, gx = tx0 + xx - 1;
        float v = 0.f;
        if (gy >= 0 && gy < Hh && gx >= 0 && gx < Ww)
            v = X[((size_t)b * C2 + 2 * g + c) * HW + gy * Ww + gx];
        xs[c][yy][xx] = v;
    }
    __syncthreads();

    const int x  = tid & 31;
    const int yb = (tid >> 5) * 4;
    #pragma unroll
    for (int j = 0; j < 4; ++j) {
        int y = yb + j;
        float a0 = 0.f, a1 = 0.f;
        #pragma unroll
        for (int c = 0; c < 2; ++c)
            #pragma unroll
            for (int ky = 0; ky < 3; ++ky)
                #pragma unroll
                for (int kx = 0; kx < 3; ++kx) {
                    float v = xs[c][y + ky][x + kx];
                    a0 += v * ws[c * 9 + ky * 3 + kx];
                    a1 += v * ws[18 + c * 9 + ky * 3 + kx];
                }
        size_t o = ((size_t)b * C2 + 2 * g) * HW + (ty0 + y) * Ww + tx0 + x;
        Y[o]      = a0;
        Y[o + HW] = a1;
    }
}

// cat = tf32([q ; y]) (float4)
__global__ void cat4_kernel(const float* __restrict__ QKV,
                            const float* __restrict__ Yin,
                            float* __restrict__ CAT)
{
    int i = blockIdx.x * 256 + threadIdx.x;
    if (i >= Bn * C2 * HW / 4) return;
    int p4 = i % (HW / 4);
    int c  = (i / (HW / 4)) % C2;
    int b  = i / ((HW / 4) * C2);
    float4 v;
    if (c < Cc) v = reinterpret_cast<const float4*>(QKV + ((size_t)b * C2 + c) * HW)[p4];
    else        v = reinterpret_cast<const float4*>(Yin + ((size_t)b * Cc + (c - Cc)) * HW)[p4];
    v.x = f2tf32(v.x); v.y = f2tf32(v.y); v.z = f2tf32(v.z); v.w = f2tf32(v.w);
    reinterpret_cast<float4*>(CAT)[i] = v;
}

// 2x2 avg pool, 96 -> 48 (tf32 out, float4)
__global__ void pool4_kernel(const float* __restrict__ X, float* __restrict__ Y)
{
    int i = blockIdx.x * 256 + threadIdx.x;
    const int OHW4 = 48 * 48 / 4;      // 576
    if (i >= Bn * C2 * OHW4) return;
    int r  = i % OHW4;
    int bc = i / OHW4;
    int y  = r / 12;
    int x8 = (r % 12) * 8;
    const float* xp = X + (size_t)bc * HW;
    float4 r0a = *reinterpret_cast<const float4*>(xp + (2 * y) * Ww + x8);
    float4 r0b = *reinterpret_cast<const float4*>(xp + (2 * y) * Ww + x8 + 4);
    float4 r1a = *reinterpret_cast<const float4*>(xp + (2 * y + 1) * Ww + x8);
    float4 r1b = *reinterpret_cast<const float4*>(xp + (2 * y + 1) * Ww + x8 + 4);
    float4 o;
    o.x = f2tf32((r0a.x + r0a.y + r1a.x + r1a.y) * 0.25f);
    o.y = f2tf32((r0a.z + r0a.w + r1a.z + r1a.w) * 0.25f);
    o.z = f2tf32((r0b.x + r0b.y + r1b.x + r1b.y) * 0.25f);
    o.w = f2tf32((r0b.z + r0b.w + r1b.z + r1b.w) * 0.25f);
    reinterpret_cast<float4*>(Y)[i] = o;
}

// SC = tf32(SC * sigmoid(CAT + upsample(K2)))  (float4)
__global__ void sigmul4_kernel(float* __restrict__ SC,
                               const float* __restrict__ CAT,
                               const float* __restrict__ K2)
{
    int i = blockIdx.x * 256 + threadIdx.x;
    if (i >= Bn * C2 * HW / 4) return;
    int p4 = i % (HW / 4);
    int bc = i / (HW / 4);
    int p  = p4 * 4;
    int y  = p / Ww, x = p % Ww;
    int iy = (y * 46) / 96;
    const float* k2r = K2 + (size_t)bc * (46 * 46) + iy * 46;
    float4 cv = reinterpret_cast<const float4*>(CAT)[i];
    float4 sv = reinterpret_cast<const float4*>(SC)[i];
    float k0 = k2r[((x + 0) * 46) / 96];
    float k1 = k2r[((x + 1) * 46) / 96];
    float k2v = k2r[((x + 2) * 46) / 96];
    float k3 = k2r[((x + 3) * 46) / 96];
    sv.x = f2tf32(sv.x / (1.f + expf(-(cv.x + k0))));
    sv.y = f2tf32(sv.y / (1.f + expf(-(cv.y + k1))));
    sv.z = f2tf32(sv.z / (1.f + expf(-(cv.z + k2v))));
    sv.w = f2tf32(sv.w / (1.f + expf(-(cv.w + k3))));
    reinterpret_cast<float4*>(SC)[i] = sv;
}

// ---------------------------------------------------------------------------
// fused deformable conv; weights transposed in smem for vector LDS.
// stores tf32(relu(out))
// ---------------------------------------------------------------------------
__global__ __launch_bounds__(128)
void deform_kernel(const float* __restrict__ Q,
                   const float* __restrict__ OFF,
                   const float* __restrict__ W,
                   const float* __restrict__ Bias,
                   float* __restrict__ Y)
{
    __shared__ float ws2[216 * 24];   // ws2[(i*9+t)*24 + o]
    const int g = blockIdx.y;
    const int b = blockIdx.z;
    const int tid = threadIdx.x;

    for (int e = tid; e < 216 * 24; e += 128) {
        int it = e / 24;              // i*9 + t
        int o  = e - it * 24;
        ws2[e] = W[(size_t)(g * CG + o) * 216 + it];
    }
    __syncthreads();

    int p = blockIdx.x * 128 + tid;
    int y = p / Ww, x = p % Ww;
    const float* offb = OFF + (size_t)b * 18 * HW;

    float acc[24];
    #pragma unroll
    for (int o = 0; o < 24; ++o) acc[o] = Bias[g * CG + o];

    const float* qc = Q + ((size_t)b * C2 + g * CG) * HW;

    for (int t = 0; t < 9; ++t) {
        float dy = offb[(size_t)(2 * t) * HW + p];
        float dx = offb[(size_t)(2 * t + 1) * HW + p];
        float m  = 1.f / (1.f + expf(-offb[(size_t)t * HW + p]));
        float py = dy + (float)(y - 1 + t / 3);
        float px = dx + (float)(x - 1 + t % 3);
        float y0f = floorf(py), x0f = floorf(px);
        int   y0 = (int)y0f,    x0 = (int)x0f;
        float fy = py - y0f,    fx = px - x0f;
        float w00 = (1.f - fy) * (1.f - fx);
        float w01 = (1.f - fy) * fx;
        float w10 = fy * (1.f - fx);
        float w11 = fy * fx;
        bool vy0 = (y0 >= 0 && y0 <= Hh - 1), vy1 = (y0 + 1 >= 0 && y0 + 1 <= Hh - 1);
        bool vx0 = (x0 >= 0 && x0 <= Ww - 1), vx1 = (x0 + 1 >= 0 && x0 + 1 <= Ww - 1);
        int cy0 = min(max(y0, 0), Hh - 1),     cy1 = min(max(y0 + 1, 0), Hh - 1);
        int cx0 = min(max(x0, 0), Ww - 1),     cx1 = min(max(x0 + 1, 0), Ww - 1);
        int i00 = cy0 * Ww + cx0, i01 = cy0 * Ww + cx1;
        int i10 = cy1 * Ww + cx0, i11 = cy1 * Ww + cx1;
        w00 = (vy0 && vx0) ? w00 * m : 0.f;
        w01 = (vy0 && vx1) ? w01 * m : 0.f;
        w10 = (vy1 && vx0) ? w10 * m : 0.f;
        w11 = (vy1 && vx1) ? w11 * m : 0.f;

        #pragma unroll
        for (int i = 0; i < 24; ++i) {
            const float* qp = qc + (size_t)i * HW;
            float val = w00 * qp[i00] + w01 * qp[i01] + w10 * qp[i10] + w11 * qp[i11];
            const float* wr = &ws2[(i * 9 + t) * 24];
            #pragma unroll
            for (int o = 0; o < 24; ++o) acc[o] += val * wr[o];
        }
    }
    #pragma unroll
    for (int o = 0; o < 24; ++o)
        Y[((size_t)b * Cc + g * CG + o) * HW + p] = f2tf32(fmaxf(acc[o], 0.f));
}

// ---------------------------------------------------------------------------
// row L2 norms (float4)
// ---------------------------------------------------------------------------
__global__ void rownorm_kernel(const float* __restrict__ QKV,
                               const float* __restrict__ Kb,
                               float* __restrict__ QN,
                               float* __restrict__ KN)
{
    int row   = blockIdx.x;
    int which = row / (Bn * Cc);
    row %= (Bn * Cc);
    int b = row / Cc, c = row % Cc;
    const float* src = which ? (Kb + ((size_t)b * Cc + c) * HW)
                             : (QKV + ((size_t)b * C2 + c) * HW);
    float s = 0.f;
    for (int n = threadIdx.x; n < HW / 4; n += 256) {
        float4 v = reinterpret_cast<const float4*>(src)[n];
        s += v.x * v.x + v.y * v.y + v.z * v.z + v.w * v.w;
    }
    __shared__ float sm[256];
    sm[threadIdx.x] = s;
    __syncthreads();
    for (int d = 128; d > 0; d >>= 1) {
        if (threadIdx.x < d) sm[threadIdx.x] += sm[threadIdx.x + d];
        __syncthreads();
    }
    if (threadIdx.x == 0) {
        float nrm = fmaxf(sqrtf(sm[0]), 1e-12f);
        (which ? KN : QN)[b * Cc + c] = nrm;
    }
}

// ---------------------------------------------------------------------------
// attention: one block per (b,h).  K-head staged through smem.
// ---------------------------------------------------------------------------
#define CNK 384
__global__ __launch_bounds__(256)
void attn2_kernel(const float* __restrict__ QKV,
                  const float* __restrict__ Kb,
                  const float* __restrict__ QN,
                  const float* __restrict__ KN,
                  const float* __restrict__ TEMP,
                  float* __restrict__ ATTN)
{
    __shared__ float ks_[24][CNK + 8];
    __shared__ float logits[24][24];

    const int b = blockIdx.x >> 3;
    const int h = blockIdx.x & 7;
    const int tid  = threadIdx.x;
    const int wid  = tid >> 5;
    const int lane = tid & 31;

    const float* qh = QKV + ((size_t)b * C2 + h * HD) * HW;
    const float* kh = Kb  + ((size_t)b * Cc + h * HD) * HW;

    float acc[3][24];
    #pragma unroll
    for (int r = 0; r < 3; ++r)
        #pragma unroll
        for (int j = 0; j < 24; ++j) acc[r][j] = 0.f;

    const float* q0p = qh + (size_t)(3 * wid + 0) * HW;
    const float* q1p = qh + (size_t)(3 * wid + 1) * HW;
    const float* q2p = qh + (size_t)(3 * wid + 2) * HW;

    for (int n0 = 0; n0 < HW; n0 += CNK) {
        __syncthreads();
        for (int e = tid; e < 24 * (CNK / 4); e += 256) {
            int j = e / (CNK / 4);
            int c = e - j * (CNK / 4);
            float4 v = *reinterpret_cast<const float4*>(kh + (size_t)j * HW + n0 + c * 4);
            ks_[j][c * 4 + 0] = v.x;
            ks_[j][c * 4 + 1] = v.y;
            ks_[j][c * 4 + 2] = v.z;
            ks_[j][c * 4 + 3] = v.w;
        }
        __syncthreads();

        for (int i = lane; i < CNK; i += 32) {
            int n = n0 + i;
            float q0 = q0p[n], q1 = q1p[n], q2 = q2p[n];
            #pragma unroll
            for (int j = 0; j < 24; ++j) {
                float kv = ks_[j][i];
                acc[0][j] += q0 * kv;
                acc[1][j] += q1 * kv;
                acc[2][j] += q2 * kv;
            }
        }
    }

    #pragma unroll
    for (int r = 0; r < 3; ++r)
        #pragma unroll
        for (int j = 0; j < 24; ++j) {
            float v = acc[r][j];
            for (int o = 16; o > 0; o >>= 1) v += __shfl_down_sync(0xffffffffu, v, o);
            if (lane == 0) logits[wid * 3 + r][j] = v;
        }
    __syncthreads();

    if (tid < 24) {
        int i = tid;
        float qn = QN[b * Cc + h * HD + i];
        float tp = TEMP[h];
        float s[24];
        float mx = -1e30f;
        #pragma unroll
        for (int j = 0; j < 24; ++j) {
            s[j] = logits[i][j] / (qn * KN[b * Cc + h * HD + j]) * tp;
            mx = fmaxf(mx, s[j]);
        }
        float sum = 0.f;
        #pragma unroll
        for (int j = 0; j < 24; ++j) { s[j] = expf(s[j] - mx); sum += s[j]; }
        float inv = 1.f / sum;
        #pragma unroll
        for (int j = 0; j < 24; ++j)
            ATTN[(((size_t)b * NH + h) * HD + i) * HD + j] = s[j] * inv;
    }
}

// out = attn @ v ; stores tf32 (AO feeds proj conv)
__global__ void attnv_kernel(const float* __restrict__ ATTN,
                             const float* __restrict__ QKV,
                             float* __restrict__ AO)
{
    int h = blockIdx.y, b = blockIdx.z;
    int n = blockIdx.x * 256 + threadIdx.x;
    __shared__ float a_s[HD * HD];
    for (int e = threadIdx.x; e < HD * HD; e += 256)
        a_s[e] = ATTN[((size_t)b * NH + h) * HD * HD + e];
    __syncthreads();
    const float* vb = QKV + ((size_t)b * C2 + Cc + h * HD) * HW;
    float acc[HD] = {};
    #pragma unroll
    for (int j = 0; j < HD; ++j) {
        float vv = vb[(size_t)j * HW + n];
        #pragma unroll
        for (int i = 0; i < HD; ++i) acc[i] += a_s[i * HD + j] * vv;
    }
    #pragma unroll
    for (int i = 0; i < HD; ++i)
        AO[((size_t)b * Cc + h * HD + i) * HW + n] = f2tf32(acc[i]);
}

// ---------------------------------------------------------------------------
// launcher
// ---------------------------------------------------------------------------
extern "C" void kernel_launch(void* const* d_in, const int* in_sizes, int n_in,
                              void* d_out, int out_size)
{
    const float* x           = (const float*)d_in[0];
    const float* y           = (const float*)d_in[1];
    const float* temperature = (const float*)d_in[2];
    const float* qkv_w       = (const float*)d_in[3];
    const float* qkv_conv_w  = (const float*)d_in[4];
    const float* proj_w      = (const float*)d_in[5];
    const float* k2_w        = (const float*)d_in[6];
    const float* k3_w        = (const float*)d_in[7];
    const float* k4_w        = (const float*)d_in[8];
    const float* deform_w    = (const float*)d_in[9];
    const float* deform_b    = (const float*)d_in[10];
    const float* pw_w        = (const float*)d_in[11];
    const float* pw_b        = (const float*)d_in[12];
    float* out = (float*)d_out;

    float* S = nullptr;
    cudaGetSymbolAddress((void**)&S, g_scratch);
    float* QKV1 = S + OFF_QKV1;
    float* QKV  = S + OFF_QKV;
    float* CAT  = S + OFF_CAT;
    float* SC   = S + OFF_SC;
    float* POOL = S + OFF_POOL;
    float* K2   = S + OFF_K2;
    float* OFFb = S + OFF_OFF;
    float* FEAT = S + OFF_FEAT;
    float* Kb   = S + OFF_K;
    float* AO   = S + OFF_AO;
    float* QN   = S + OFF_QN;
    float* KN   = S + OFF_KN;
    float* ATTN = S + OFF_ATTN;
    float* XT   = S + OFF_XT;
    float* WK3P = S + OFF_WK3P;
    float* WK2P = S + OFF_WK2P;
    float* WK4P = S + OFF_WK4P;

    const int NE = Bn * C2 * HW;
    const int NX = Bn * Cc * HW;

    // 0) prep: XT = tf32(x); permute 3x3 weights to tap-major K order
    tf32round4_kernel<<<(NX / 4 + 255) / 256, 256>>>(x, XT, NX / 4);
    permw_kernel<<<(1327104 + 255) / 256, 256>>>(k3_w, WK3P, C2, C2);
    permw_kernel<<<(1327104 + 255) / 256, 256>>>(k2_w, WK2P, C2, C2);
    permw_kernel<<<(62208 + 255) / 256, 256>>>(k4_w, WK4P, 18, C2);

    // 1) qkv 1x1: 384 x 192 x 9216
    conv_mma<1, 4><<<dim3(HW / 128, C2 / 128, Bn), 256>>>(
        qkv_w, XT, QKV1, nullptr, C2, Cc, Hh, Ww, Hh, Ww, 0);
    // 2) grouped 3x3 (groups=192)
    dwconv2_kernel<<<dim3(9, 192, Bn), 256>>>(QKV1, qkv_conv_w, QKV);
    // 3) cat = tf32([q ; y])
    cat4_kernel<<<(NE / 4 + 255) / 256, 256>>>(QKV, y, CAT);
    // 4) k3 conv 3x3 pad=1 (tap-major weights)
    conv_mma<3, 4><<<dim3(HW / 128, C2 / 128, Bn), 256>>>(
        WK3P, CAT, SC, nullptr, C2, C2, Hh, Ww, Hh, Ww, 1);
    // 5) avg pool 2x2
    pool4_kernel<<<(Bn * C2 * 576 + 255) / 256, 256>>>(CAT, POOL);
    // 6) k2 conv 3x3 pad=0 : 48x48 -> 46x46 (tap-major weights)
    conv_mma<3, 4><<<dim3((46 * 46 + 127) / 128, C2 / 128, Bn), 256>>>(
        WK2P, POOL, K2, nullptr, C2, C2, 48, 48, 46, 46, 0);
    // 7) SC = tf32(SC * sigmoid(CAT + upsample(K2)))
    sigmul4_kernel<<<(NE / 4 + 255) / 256, 256>>>(SC, CAT, K2);
    // 8) offset = conv3x3(sc, k4, pad=1), M=18 (tap-major weights)
    conv_mma<3, 1><<<dim3(HW / 128, 1, Bn), 256>>>(
        WK4P, SC, OFFb, nullptr, 18, C2, Hh, Ww, Hh, Ww, 1);
    // 9) deformable conv -> FEAT = tf32(relu(deform))
    deform_kernel<<<dim3(HW / 128, Gg, Bn), 128>>>(QKV, OFFb, deform_w, deform_b, FEAT);
    // 10) k = 1x1(FEAT) + pw_b
    conv_mma<1, 4><<<dim3(HW / 128, (Cc + 127) / 128, Bn), 256>>>(
        pw_w, FEAT, Kb, pw_b, Cc, Cc, Hh, Ww, Hh, Ww, 0);
    // 11) row norms
    rownorm_kernel<<<2 * Bn * Cc, 256>>>(QKV, Kb, QN, KN);
    // 12) attention logits + softmax
    attn2_kernel<<<Bn * NH, 256>>>(QKV, Kb, QN, KN, temperature, ATTN);
    // 13) out = attn @ v
    attnv_kernel<<<dim3(HW / 256, NH, Bn), 256>>>(ATTN, QKV, AO);
    // 14) final 1x1 proj -> d_out
    conv_mma<1, 4><<<dim3(HW / 128, (Cc + 127) / 128, Bn), 256>>>(
        proj_w, AO, out, nullptr, Cc, Cc, Hh, Ww, Hh, Ww, 0);
}

// round 10
// speedup vs baseline: 1.9410x; 1.1667x over previous
#include <cuda_runtime.h>
#include <cuda_fp16.h>
#include <math.h>
#include <stdint.h>

// ---------------------------------------------------------------------------
// Problem constants
// ---------------------------------------------------------------------------
#define Bn   4
#define Cc   192
#define C2   384
#define Hh   96
#define Ww   96
#define HW   (Hh*Ww)          // 9216
#define NH   8
#define HD   24
#define Gg   8
#define CG   24

// scratch offsets (floats)
#define OFF_QKV1  0ul
#define OFF_QKV   14155776ul
#define OFF_CAT   28311552ul
#define OFF_SC    42467328ul
#define OFF_POOL  56623104ul
#define OFF_K2    60162048ul
#define OFF_OFF   63412224ul
#define OFF_FEAT  64075776ul
#define OFF_K     71153664ul
#define OFF_AO    78231552ul
#define OFF_QN    85309440ul
#define OFF_KN    85310208ul
#define OFF_ATTN  85310976ul
#define OFF_WK3P  85329408ul     // 1327104
#define OFF_WK2P  86656512ul     // 1327104
#define OFF_WK4P  87983616ul     // 62208
#define SCRATCH_TOTAL 88045824ul

__device__ float g_scratch[SCRATCH_TOTAL];

// ---------------------------------------------------------------------------
// helpers
// ---------------------------------------------------------------------------
__device__ __forceinline__ uint32_t pack_h2(float lo, float hi) {
    __half2 h = __floats2half2_rn(lo, hi);
    return *reinterpret_cast<uint32_t*>(&h);
}

__device__ __forceinline__ void mma_16x8x16(float* c, const uint32_t* a,
                                            uint32_t b0, uint32_t b1) {
    asm volatile(
        "mma.sync.aligned.m16n8k16.row.col.f32.f16.f16.f32 "
        "{%0,%1,%2,%3}, {%4,%5,%6,%7}, {%8,%9}, {%0,%1,%2,%3};\n"
        : "+f"(c[0]), "+f"(c[1]), "+f"(c[2]), "+f"(c[3])
        : "r"(a[0]), "r"(a[1]), "r"(a[2]), "r"(a[3]), "r"(b0), "r"(b1));
}

__device__ __forceinline__ void cpasync4(uint32_t saddr, const float* g, bool pred) {
    int sz = pred ? 4 : 0;
    asm volatile("cp.async.ca.shared.global [%0], [%1], 4, %2;\n"
                 :: "r"(saddr), "l"(g), "r"(sz));
}
__device__ __forceinline__ void cpasync16(uint32_t saddr, const float* g) {
    asm volatile("cp.async.cg.shared.global [%0], [%1], 16;\n"
                 :: "r"(saddr), "l"(g));
}
#define CP_COMMIT() asm volatile("cp.async.commit_group;\n" ::: "memory")
#define CP_WAIT0()  asm volatile("cp.async.wait_group 0;\n" ::: "memory")

// ---------------------------------------------------------------------------
// Weight K-order permutation for 3x3 convs: Wp[m][t][ic] = W[m][ic][t].
// ---------------------------------------------------------------------------
__global__ void permw_kernel(const float* __restrict__ W,
                             float* __restrict__ Wp, int M, int Cin)
{
    int K = Cin * 9;
    int i = blockIdx.x * 256 + threadIdx.x;
    if (i >= M * K) return;
    int m = i / K;
    int r = i - m * K;          // r = t*Cin + ic
    int t = r / Cin;
    int ic = r - t * Cin;
    Wp[i] = W[(size_t)m * K + ic * 9 + t];
}

// ---------------------------------------------------------------------------
// fp16 tensor-core implicit-GEMM conv (proven 2-stage cp.async skeleton).
// A (weights fp32, tap-major K for KS==3): LDG float4 -> half2 -> STS (2/f4).
//   As2 layout: uint32 half2-pairs [kpair(8)][BM+8] ; frag banks 8*lt+lg, no conflicts.
// B (activations raw fp32): cp.async [k(16)][BSTR=132] ; converted to half2 at
//   fragment load. frag banks 8*lt+lg, no conflicts; cp.async dest 16B aligned.
// mma.m16n8k16 f16 (K=16 per instruction, one k-step per tile).
// KS==3 requires Cin % 16 == 0. For KS==1, N must be a multiple of 128.
// ---------------------------------------------------------------------------
template<int KS, int FM>
__global__ __launch_bounds__(256)
void conv_mma(const float* __restrict__ Wt,
              const float* __restrict__ X,
              float* __restrict__ Y,
              const float* __restrict__ bias,
              int M, int Cin, int IH, int IW,
              int OH, int OW, int pad)
{
    constexpr int BM    = 32 * FM;
    constexpr int BN    = 128;
    constexpr int BK    = 16;
    constexpr int A2STR = BM + 8;           // uint32 stride per kpair row
    constexpr int BSTR  = 132;              // fp32 stride per k row
    constexpr int AELE  = BM * BK / 4;      // float4 gmem loads for A tile
    constexpr int AITER = (AELE + 255) / 256;

    __shared__ uint32_t As2[2][8 * A2STR];
    __shared__ float    Bs[2][BK * BSTR];

    const int N   = OH * OW;
    const int K   = Cin * KS * KS;
    const int IHW = IH * IW;
    const int bz  = blockIdx.z;
    const int m0  = blockIdx.y * BM;
    const int n0  = blockIdx.x * BN;

    const int tid  = threadIdx.x;
    const int wid  = tid >> 5;
    const int lane = tid & 31;
    const int wm   = wid & 1;
    const int wn   = wid >> 1;
    const int mbase = wm * (16 * FM);
    const int nbase = wn * 32;
    const int lg = lane >> 2;
    const int lt = lane & 3;

    const float* Xb = X + (size_t)bz * Cin * IHW;

    float acc[FM][4][4];
    #pragma unroll
    for (int f = 0; f < FM; ++f)
        #pragma unroll
        for (int nf = 0; nf < 4; ++nf)
            #pragma unroll
            for (int r = 0; r < 4; ++r) acc[f][nf][r] = 0.f;

    // B-gather per-thread coords (KS==3 path)
    const int bn = tid & 127;
    const int gn = n0 + bn;
    const bool nvalid = gn < N;
    int oy = 0, ox = 0;
    if (KS == 3) { int g = nvalid ? gn : 0; oy = g / OW; ox = g - oy * OW; }

    float4 aReg[AITER];

    auto ldA = [&](int k0) {
        #pragma unroll
        for (int r = 0; r < AITER; ++r) {
            int e = tid + r * 256;
            float4 v = make_float4(0.f, 0.f, 0.f, 0.f);
            if (AELE == 512 || e < AELE) {
                int m  = e >> 2;
                int kq = e & 3;
                int gm = m0 + m;
                if (gm < M)
                    v = *reinterpret_cast<const float4*>(Wt + (size_t)gm * K + k0 + kq * 4);
            }
            aReg[r] = v;
        }
    };
    auto stA = [&](int buf) {
        #pragma unroll
        for (int r = 0; r < AITER; ++r) {
            int e = tid + r * 256;
            if (AELE == 512 || e < AELE) {
                int m  = e >> 2;
                int kq = e & 3;
                As2[buf][(kq * 2 + 0) * A2STR + m] = pack_h2(aReg[r].x, aReg[r].y);
                As2[buf][(kq * 2 + 1) * A2STR + m] = pack_h2(aReg[r].z, aReg[r].w);
            }
        }
    };
    auto issueB = [&](int k0, int buf) {
        if (KS == 1) {
            #pragma unroll
            for (int r = 0; r < 2; ++r) {
                int o  = tid + r * 256;
                int k  = o >> 5;
                int c4 = (o & 31) * 4;
                uint32_t s = (uint32_t)__cvta_generic_to_shared(&Bs[buf][k * BSTR + c4]);
                cpasync16(s, Xb + (size_t)(k0 + k) * N + n0 + c4);
            }
        } else {
            // tap-major K: whole tile shares one tap (uniform across block)
            int tp  = k0 / Cin;
            int icb = k0 - tp * Cin;
            int tdy = (tp >= 6) ? 2 : ((tp >= 3) ? 1 : 0);
            int tdx = tp - 3 * tdy;
            int iy  = oy + tdy - pad;
            int ix  = ox + tdx - pad;
            bool ok = nvalid && iy >= 0 && iy < IH && ix >= 0 && ix < IW;
            const float* base = Xb + (size_t)iy * IW + ix;
            #pragma unroll
            for (int r = 0; r < 8; ++r) {
                int k = (tid >> 7) + 2 * r;
                uint32_t s = (uint32_t)__cvta_generic_to_shared(&Bs[buf][k * BSTR + bn]);
                cpasync4(s, base + (icb + k) * IHW, ok);
            }
        }
    };
    auto compute = [&](int buf) {
        uint32_t a[FM][4];
        #pragma unroll
        for (int f = 0; f < FM; ++f) {
            int mr = mbase + f * 16 + lg;
            a[f][0] = As2[buf][lt * A2STR + mr];
            a[f][1] = As2[buf][lt * A2STR + mr + 8];
            a[f][2] = As2[buf][(lt + 4) * A2STR + mr];
            a[f][3] = As2[buf][(lt + 4) * A2STR + mr + 8];
        }
        #pragma unroll
        for (int nf = 0; nf < 4; ++nf) {
            int nc = nbase + nf * 8 + lg;
            uint32_t b0 = pack_h2(Bs[buf][(2 * lt) * BSTR + nc],
                                  Bs[buf][(2 * lt + 1) * BSTR + nc]);
            uint32_t b1 = pack_h2(Bs[buf][(2 * lt + 8) * BSTR + nc],
                                  Bs[buf][(2 * lt + 9) * BSTR + nc]);
            #pragma unroll
            for (int f = 0; f < FM; ++f)
                mma_16x8x16(acc[f][nf], a[f], b0, b1);
        }
    };

    const int kTiles = K / BK;
    issueB(0, 0); CP_COMMIT();
    ldA(0); stA(0);
    CP_WAIT0(); __syncthreads();

    for (int t = 0; t < kTiles; ++t) {
        if (t + 1 < kTiles) {
            issueB((t + 1) * BK, (t + 1) & 1); CP_COMMIT();
            ldA((t + 1) * BK);
        }
        compute(t & 1);
        if (t + 1 < kTiles) {
            stA((t + 1) & 1);
            CP_WAIT0(); __syncthreads();
        }
    }

    // ---- epilogue ----
    #pragma unroll
    for (int f = 0; f < FM; ++f) {
        int r0 = m0 + mbase + f * 16 + lg;
        #pragma unroll
        for (int nf = 0; nf < 4; ++nf) {
            int cb = n0 + nbase + nf * 8 + 2 * lt;
            #pragma unroll
            for (int rr = 0; rr < 2; ++rr) {
                int m = r0 + rr * 8;
                if (m >= M) continue;
                float bval = bias ? bias[m] : 0.f;
                #pragma unroll
                for (int cc = 0; cc < 2; ++cc) {
                    int n = cb + cc;
                    if (n >= N) continue;
                    Y[((size_t)bz * M + m) * N + n] = acc[f][nf][rr * 2 + cc] + bval;
                }
            }
        }
    }
}

// ---------------------------------------------------------------------------
// grouped 3x3 conv, smem-tiled
// ---------------------------------------------------------------------------
__global__ __launch_bounds__(256)
void dwconv2_kernel(const float* __restrict__ X,
                    const float* __restrict__ W,
                    float* __restrict__ Y)
{
    __shared__ float xs[2][34][35];
    __shared__ float ws[36];

    const int tile = blockIdx.x;
    const int g    = blockIdx.y;
    const int b    = blockIdx.z;
    const int ty0  = (tile / 3) * 32;
    const int tx0  = (tile % 3) * 32;
    const int tid  = threadIdx.x;

    if (tid < 36) ws[tid] = W[(size_t)g * 36 + tid];

    for (int e = tid; e < 2 * 34 * 34; e += 256) {
        int c  = e / (34 * 34);
        int r  = e - c * 34 * 34;
        int yy = r / 34, xx = r - yy * 34;
        int gy = ty0 + yy - 1, gx = tx0 + xx - 1;
        float v = 0.f;
        if (gy >= 0 && gy < Hh && gx >= 0 && gx < Ww)
            v = X[((size_t)b * C2 + 2 * g + c) * HW + gy * Ww + gx];
        xs[c][yy][xx] = v;
    }
    __syncthreads();

    const int x  = tid & 31;
    const int yb = (tid >> 5) * 4;
    #pragma unroll
    for (int j = 0; j < 4; ++j) {
        int y = yb + j;
        float a0 = 0.f, a1 = 0.f;
        #pragma unroll
        for (int c = 0; c < 2; ++c)
            #pragma unroll
            for (int ky = 0; ky < 3; ++ky)
                #pragma unroll
                for (int kx = 0; kx < 3; ++kx) {
                    float v = xs[c][y + ky][x + kx];
                    a0 += v * ws[c * 9 + ky * 3 + kx];
                    a1 += v * ws[18 + c * 9 + ky * 3 + kx];
                }
        size_t o = ((size_t)b * C2 + 2 * g) * HW + (ty0 + y) * Ww + tx0 + x;
        Y[o]      = a0;
        Y[o + HW] = a1;
    }
}

// cat = [q ; y] (float4)
__global__ void cat4_kernel(const float* __restrict__ QKV,
                            const float* __restrict__ Yin,
                            float* __restrict__ CAT)
{
    int i = blockIdx.x * 256 + threadIdx.x;
    if (i >= Bn * C2 * HW / 4) return;
    int p4 = i % (HW / 4);
    int c  = (i / (HW / 4)) % C2;
    int b  = i / ((HW / 4) * C2);
    float4 v;
    if (c < Cc) v = reinterpret_cast<const float4*>(QKV + ((size_t)b * C2 + c) * HW)[p4];
    else        v = reinterpret_cast<const float4*>(Yin + ((size_t)b * Cc + (c - Cc)) * HW)[p4];
    reinterpret_cast<float4*>(CAT)[i] = v;
}

// 2x2 avg pool, 96 -> 48 (float4)
__global__ void pool4_kernel(const float* __restrict__ X, float* __restrict__ Y)
{
    int i = blockIdx.x * 256 + threadIdx.x;
    const int OHW4 = 48 * 48 / 4;      // 576
    if (i >= Bn * C2 * OHW4) return;
    int r  = i % OHW4;
    int bc = i / OHW4;
    int y  = r / 12;
    int x8 = (r % 12) * 8;
    const float* xp = X + (size_t)bc * HW;
    float4 r0a = *reinterpret_cast<const float4*>(xp + (2 * y) * Ww + x8);
    float4 r0b = *reinterpret_cast<const float4*>(xp + (2 * y) * Ww + x8 + 4);
    float4 r1a = *reinterpret_cast<const float4*>(xp + (2 * y + 1) * Ww + x8);
    float4 r1b = *reinterpret_cast<const float4*>(xp + (2 * y + 1) * Ww + x8 + 4);
    float4 o;
    o.x = (r0a.x + r0a.y + r1a.x + r1a.y) * 0.25f;
    o.y = (r0a.z + r0a.w + r1a.z + r1a.w) * 0.25f;
    o.z = (r0b.x + r0b.y + r1b.x + r1b.y) * 0.25f;
    o.w = (r0b.z + r0b.w + r1b.z + r1b.w) * 0.25f;
    reinterpret_cast<float4*>(Y)[i] = o;
}

// SC = SC * sigmoid(CAT + upsample(K2))  (float4)
__global__ void sigmul4_kernel(float* __restrict__ SC,
                               const float* __restrict__ CAT,
                               const float* __restrict__ K2)
{
    int i = blockIdx.x * 256 + threadIdx.x;
    if (i >= Bn * C2 * HW / 4) return;
    int p4 = i % (HW / 4);
    int bc = i / (HW / 4);
    int p  = p4 * 4;
    int y  = p / Ww, x = p % Ww;
    int iy = (y * 46) / 96;
    const float* k2r = K2 + (size_t)bc * (46 * 46) + iy * 46;
    float4 cv = reinterpret_cast<const float4*>(CAT)[i];
    float4 sv = reinterpret_cast<const float4*>(SC)[i];
    float k0 = k2r[((x + 0) * 46) / 96];
    float k1 = k2r[((x + 1) * 46) / 96];
    float k2v = k2r[((x + 2) * 46) / 96];
    float k3 = k2r[((x + 3) * 46) / 96];
    sv.x = sv.x / (1.f + expf(-(cv.x + k0)));
    sv.y = sv.y / (1.f + expf(-(cv.y + k1)));
    sv.z = sv.z / (1.f + expf(-(cv.z + k2v)));
    sv.w = sv.w / (1.f + expf(-(cv.w + k3)));
    reinterpret_cast<float4*>(SC)[i] = sv;
}

// ---------------------------------------------------------------------------
// fused deformable conv; weights transposed in smem; stores relu(out)
// ---------------------------------------------------------------------------
__global__ __launch_bounds__(128)
void deform_kernel(const float* __restrict__ Q,
                   const float* __restrict__ OFF,
                   const float* __restrict__ W,
                   const float* __restrict__ Bias,
                   float* __restrict__ Y)
{
    __shared__ float ws2[216 * 24];   // ws2[(i*9+t)*24 + o]
    const int g = blockIdx.y;
    const int b = blockIdx.z;
    const int tid = threadIdx.x;

    for (int e = tid; e < 216 * 24; e += 128) {
        int it = e / 24;
        int o  = e - it * 24;
        ws2[e] = W[(size_t)(g * CG + o) * 216 + it];
    }
    __syncthreads();

    int p = blockIdx.x * 128 + tid;
    int y = p / Ww, x = p % Ww;
    const float* offb = OFF + (size_t)b * 18 * HW;

    float acc[24];
    #pragma unroll
    for (int o = 0; o < 24; ++o) acc[o] = Bias[g * CG + o];

    const float* qc = Q + ((size_t)b * C2 + g * CG) * HW;

    for (int t = 0; t < 9; ++t) {
        float dy = offb[(size_t)(2 * t) * HW + p];
        float dx = offb[(size_t)(2 * t + 1) * HW + p];
        float m  = 1.f / (1.f + expf(-offb[(size_t)t * HW + p]));
        float py = dy + (float)(y - 1 + t / 3);
        float px = dx + (float)(x - 1 + t % 3);
        float y0f = floorf(py), x0f = floorf(px);
        int   y0 = (int)y0f,    x0 = (int)x0f;
        float fy = py - y0f,    fx = px - x0f;
        float w00 = (1.f - fy) * (1.f - fx);
        float w01 = (1.f - fy) * fx;
        float w10 = fy * (1.f - fx);
        float w11 = fy * fx;
        bool vy0 = (y0 >= 0 && y0 <= Hh - 1), vy1 = (y0 + 1 >= 0 && y0 + 1 <= Hh - 1);
        bool vx0 = (x0 >= 0 && x0 <= Ww - 1), vx1 = (x0 + 1 >= 0 && x0 + 1 <= Ww - 1);
        int cy0 = min(max(y0, 0), Hh - 1),     cy1 = min(max(y0 + 1, 0), Hh - 1);
        int cx0 = min(max(x0, 0), Ww - 1),     cx1 = min(max(x0 + 1, 0), Ww - 1);
        int i00 = cy0 * Ww + cx0, i01 = cy0 * Ww + cx1;
        int i10 = cy1 * Ww + cx0, i11 = cy1 * Ww + cx1;
        w00 = (vy0 && vx0) ? w00 * m : 0.f;
        w01 = (vy0 && vx1) ? w01 * m : 0.f;
        w10 = (vy1 && vx0) ? w10 * m : 0.f;
        w11 = (vy1 && vx1) ? w11 * m : 0.f;

        #pragma unroll
        for (int i = 0; i < 24; ++i) {
            const float* qp = qc + (size_t)i * HW;
            float val = w00 * qp[i00] + w01 * qp[i01] + w10 * qp[i10] + w11 * qp[i11];
            const float* wr = &ws2[(i * 9 + t) * 24];
            #pragma unroll
            for (int o = 0; o < 24; ++o) acc[o] += val * wr[o];
        }
    }
    #pragma unroll
    for (int o = 0; o < 24; ++o)
        Y[((size_t)b * Cc + g * CG + o) * HW + p] = fmaxf(acc[o], 0.f);
}

// ---------------------------------------------------------------------------
// row L2 norms (float4)
// ---------------------------------------------------------------------------
__global__ void rownorm_kernel(const float* __restrict__ QKV,
                               const float* __restrict__ Kb,
                               float* __restrict__ QN,
                               float* __restrict__ KN)
{
    int row   = blockIdx.x;
    int which = row / (Bn * Cc);
    row %= (Bn * Cc);
    int b = row / Cc, c = row % Cc;
    const float* src = which ? (Kb + ((size_t)b * Cc + c) * HW)
                             : (QKV + ((size_t)b * C2 + c) * HW);
    float s = 0.f;
    for (int n = threadIdx.x; n < HW / 4; n += 256) {
        float4 v = reinterpret_cast<const float4*>(src)[n];
        s += v.x * v.x + v.y * v.y + v.z * v.z + v.w * v.w;
    }
    __shared__ float sm[256];
    sm[threadIdx.x] = s;
    __syncthreads();
    for (int d = 128; d > 0; d >>= 1) {
        if (threadIdx.x < d) sm[threadIdx.x] += sm[threadIdx.x + d];
        __syncthreads();
    }
    if (threadIdx.x == 0) {
        float nrm = fmaxf(sqrtf(sm[0]), 1e-12f);
        (which ? KN : QN)[b * Cc + c] = nrm;
    }
}

// ---------------------------------------------------------------------------
// attention: one block per (b,h).  K-head staged through smem.
// ---------------------------------------------------------------------------
#define CNK 384
__global__ __launch_bounds__(256)
void attn2_kernel(const float* __restrict__ QKV,
                  const float* __restrict__ Kb,
                  const float* __restrict__ QN,
                  const float* __restrict__ KN,
                  const float* __restrict__ TEMP,
                  float* __restrict__ ATTN)
{
    __shared__ float ks_[24][CNK + 8];
    __shared__ float logits[24][24];

    const int b = blockIdx.x >> 3;
    const int h = blockIdx.x & 7;
    const int tid  = threadIdx.x;
    const int wid  = tid >> 5;
    const int lane = tid & 31;

    const float* qh = QKV + ((size_t)b * C2 + h * HD) * HW;
    const float* kh = Kb  + ((size_t)b * Cc + h * HD) * HW;

    float acc[3][24];
    #pragma unroll
    for (int r = 0; r < 3; ++r)
        #pragma unroll
        for (int j = 0; j < 24; ++j) acc[r][j] = 0.f;

    const float* q0p = qh + (size_t)(3 * wid + 0) * HW;
    const float* q1p = qh + (size_t)(3 * wid + 1) * HW;
    const float* q2p = qh + (size_t)(3 * wid + 2) * HW;

    for (int n0 = 0; n0 < HW; n0 += CNK) {
        __syncthreads();
        for (int e = tid; e < 24 * (CNK / 4); e += 256) {
            int j = e / (CNK / 4);
            int c = e - j * (CNK / 4);
            float4 v = *reinterpret_cast<const float4*>(kh + (size_t)j * HW + n0 + c * 4);
            ks_[j][c * 4 + 0] = v.x;
            ks_[j][c * 4 + 1] = v.y;
            ks_[j][c * 4 + 2] = v.z;
            ks_[j][c * 4 + 3] = v.w;
        }
        __syncthreads();

        for (int i = lane; i < CNK; i += 32) {
            int n = n0 + i;
            float q0 = q0p[n], q1 = q1p[n], q2 = q2p[n];
            #pragma unroll
            for (int j = 0; j < 24; ++j) {
                float kv = ks_[j][i];
                acc[0][j] += q0 * kv;
                acc[1][j] += q1 * kv;
                acc[2][j] += q2 * kv;
            }
        }
    }

    #pragma unroll
    for (int r = 0; r < 3; ++r)
        #pragma unroll
        for (int j = 0; j < 24; ++j) {
            float v = acc[r][j];
            for (int o = 16; o > 0; o >>= 1) v += __shfl_down_sync(0xffffffffu, v, o);
            if (lane == 0) logits[wid * 3 + r][j] = v;
        }
    __syncthreads();

    if (tid < 24) {
        int i = tid;
        float qn = QN[b * Cc + h * HD + i];
        float tp = TEMP[h];
        float s[24];
        float mx = -1e30f;
        #pragma unroll
        for (int j = 0; j < 24; ++j) {
            s[j] = logits[i][j] / (qn * KN[b * Cc + h * HD + j]) * tp;
            mx = fmaxf(mx, s[j]);
        }
        float sum = 0.f;
        #pragma unroll
        for (int j = 0; j < 24; ++j) { s[j] = expf(s[j] - mx); sum += s[j]; }
        float inv = 1.f / sum;
        #pragma unroll
        for (int j = 0; j < 24; ++j)
            ATTN[(((size_t)b * NH + h) * HD + i) * HD + j] = s[j] * inv;
    }
}

// out = attn @ v
__global__ void attnv_kernel(const float* __restrict__ ATTN,
                             const float* __restrict__ QKV,
                             float* __restrict__ AO)
{
    int h = blockIdx.y, b = blockIdx.z;
    int n = blockIdx.x * 256 + threadIdx.x;
    __shared__ float a_s[HD * HD];
    for (int e = threadIdx.x; e < HD * HD; e += 256)
        a_s[e] = ATTN[((size_t)b * NH + h) * HD * HD + e];
    __syncthreads();
    const float* vb = QKV + ((size_t)b * C2 + Cc + h * HD) * HW;
    float acc[HD] = {};
    #pragma unroll
    for (int j = 0; j < HD; ++j) {
        float vv = vb[(size_t)j * HW + n];
        #pragma unroll
        for (int i = 0; i < HD; ++i) acc[i] += a_s[i * HD + j] * vv;
    }
    #pragma unroll
    for (int i = 0; i < HD; ++i)
        AO[((size_t)b * Cc + h * HD + i) * HW + n] = acc[i];
}

// ---------------------------------------------------------------------------
// launcher
// ---------------------------------------------------------------------------
extern "C" void kernel_launch(void* const* d_in, const int* in_sizes, int n_in,
                              void* d_out, int out_size)
{
    const float* x           = (const float*)d_in[0];
    const float* y           = (const float*)d_in[1];
    const float* temperature = (const float*)d_in[2];
    const float* qkv_w       = (const float*)d_in[3];
    const float* qkv_conv_w  = (const float*)d_in[4];
    const float* proj_w      = (const float*)d_in[5];
    const float* k2_w        = (const float*)d_in[6];
    const float* k3_w        = (const float*)d_in[7];
    const float* k4_w        = (const float*)d_in[8];
    const float* deform_w    = (const float*)d_in[9];
    const float* deform_b    = (const float*)d_in[10];
    const float* pw_w        = (const float*)d_in[11];
    const float* pw_b        = (const float*)d_in[12];
    float* out = (float*)d_out;

    float* S = nullptr;
    cudaGetSymbolAddress((void**)&S, g_scratch);
    float* QKV1 = S + OFF_QKV1;
    float* QKV  = S + OFF_QKV;
    float* CAT  = S + OFF_CAT;
    float* SC   = S + OFF_SC;
    float* POOL = S + OFF_POOL;
    float* K2   = S + OFF_K2;
    float* OFFb = S + OFF_OFF;
    float* FEAT = S + OFF_FEAT;
    float* Kb   = S + OFF_K;
    float* AO   = S + OFF_AO;
    float* QN   = S + OFF_QN;
    float* KN   = S + OFF_KN;
    float* ATTN = S + OFF_ATTN;
    float* WK3P = S + OFF_WK3P;
    float* WK2P = S + OFF_WK2P;
    float* WK4P = S + OFF_WK4P;

    const int NE = Bn * C2 * HW;

    // 0) permute 3x3 weights to tap-major K order
    permw_kernel<<<(1327104 + 255) / 256, 256>>>(k3_w, WK3P, C2, C2);
    permw_kernel<<<(1327104 + 255) / 256, 256>>>(k2_w, WK2P, C2, C2);
    permw_kernel<<<(62208 + 255) / 256, 256>>>(k4_w, WK4P, 18, C2);

    // 1) qkv 1x1: 384 x 192 x 9216
    conv_mma<1, 4><<<dim3(HW / 128, C2 / 128, Bn), 256>>>(
        qkv_w, x, QKV1, nullptr, C2, Cc, Hh, Ww, Hh, Ww, 0);
    // 2) grouped 3x3 (groups=192)
    dwconv2_kernel<<<dim3(9, 192, Bn), 256>>>(QKV1, qkv_conv_w, QKV);
    // 3) cat = [q ; y]
    cat4_kernel<<<(NE / 4 + 255) / 256, 256>>>(QKV, y, CAT);
    // 4) k3 conv 3x3 pad=1 (tap-major weights)
    conv_mma<3, 4><<<dim3(HW / 128, C2 / 128, Bn), 256>>>(
        WK3P, CAT, SC, nullptr, C2, C2, Hh, Ww, Hh, Ww, 1);
    // 5) avg pool 2x2
    pool4_kernel<<<(Bn * C2 * 576 + 255) / 256, 256>>>(CAT, POOL);
    // 6) k2 conv 3x3 pad=0 : 48x48 -> 46x46 (tap-major weights)
    conv_mma<3, 4><<<dim3((46 * 46 + 127) / 128, C2 / 128, Bn), 256>>>(
        WK2P, POOL, K2, nullptr, C2, C2, 48, 48, 46, 46, 0);
    // 7) SC = SC * sigmoid(CAT + upsample(K2))
    sigmul4_kernel<<<(NE / 4 + 255) / 256, 256>>>(SC, CAT, K2);
    // 8) offset = conv3x3(sc, k4, pad=1), M=18 (tap-major weights)
    conv_mma<3, 1><<<dim3(HW / 128, 1, Bn), 256>>>(
        WK4P, SC, OFFb, nullptr, 18, C2, Hh, Ww, Hh, Ww, 1);
    // 9) deformable conv -> FEAT = relu(deform)
    deform_kernel<<<dim3(HW / 128, Gg, Bn), 128>>>(QKV, OFFb, deform_w, deform_b, FEAT);
    // 10) k = 1x1(FEAT) + pw_b
    conv_mma<1, 4><<<dim3(HW / 128, (Cc + 127) / 128, Bn), 256>>>(
        pw_w, FEAT, Kb, pw_b, Cc, Cc, Hh, Ww, Hh, Ww, 0);
    // 11) row norms
    rownorm_kernel<<<2 * Bn * Cc, 256>>>(QKV, Kb, QN, KN);
    // 12) attention logits + softmax
    attn2_kernel<<<Bn * NH, 256>>>(QKV, Kb, QN, KN, temperature, ATTN);
    // 13) out = attn @ v
    attnv_kernel<<<dim3(HW / 256, NH, Bn), 256>>>(ATTN, QKV, AO);
    // 14) final 1x1 proj -> d_out
    conv_mma<1, 4><<<dim3(HW / 128, (Cc + 127) / 128, Bn), 256>>>(
        proj_w, AO, out, nullptr, Cc, Cc, Hh, Ww, Hh, Ww, 0);
}

// round 11
// speedup vs baseline: 2.1749x; 1.1205x over previous
#include <cuda_runtime.h>
#include <cuda_fp16.h>
#include <math.h>
#include <stdint.h>

// ---------------------------------------------------------------------------
// Problem constants
// ---------------------------------------------------------------------------
#define Bn   4
#define Cc   192
#define C2   384
#define Hh   96
#define Ww   96
#define HW   (Hh*Ww)          // 9216
#define NH   8
#define HD   24
#define Gg   8
#define CG   24

// scratch offsets (in floats / uint32 slots)
#define OFF_QKV1  0ul
#define OFF_QKV   14155776ul
#define OFF_CAT   28311552ul
#define OFF_SC    42467328ul
#define OFF_POOL  56623104ul
#define OFF_K2    60162048ul
#define OFF_OFF   63412224ul
#define OFF_FEAT  64075776ul
#define OFF_K     71153664ul
#define OFF_AO    78231552ul
#define OFF_QN    85309440ul
#define OFF_KN    85310208ul
#define OFF_ATTN  85310976ul
#define OFF_WK3P  85329408ul     // 1327104
#define OFF_WK2P  86656512ul     // 1327104
#define OFF_WK4P  87983616ul     // 62208
#define OFF_XH    88045824ul     // 3538944
#define OFF_CATH  91584768ul     // 7077888
#define OFF_POOLH 98662656ul     // 1769472
#define OFF_SCH   100432128ul    // 7077888
#define OFF_FEATH 107510016ul    // 3538944
#define OFF_AOH   111048960ul    // 3538944
#define SCRATCH_TOTAL 114587904ul

__device__ float g_scratch[SCRATCH_TOTAL];

// ---------------------------------------------------------------------------
// helpers
// ---------------------------------------------------------------------------
__device__ __forceinline__ uint32_t pack_h2(float lo, float hi) {
    __half2 h = __floats2half2_rn(lo, hi);
    return *reinterpret_cast<uint32_t*>(&h);
}

__device__ __forceinline__ void mma_16x8x16(float* c, const uint32_t* a,
                                            uint32_t b0, uint32_t b1) {
    asm volatile(
        "mma.sync.aligned.m16n8k16.row.col.f32.f16.f16.f32 "
        "{%0,%1,%2,%3}, {%4,%5,%6,%7}, {%8,%9}, {%0,%1,%2,%3};\n"
        : "+f"(c[0]), "+f"(c[1]), "+f"(c[2]), "+f"(c[3])
        : "r"(a[0]), "r"(a[1]), "r"(a[2]), "r"(a[3]), "r"(b0), "r"(b1));
}

__device__ __forceinline__ void cpasync4(uint32_t saddr, const void* g, bool pred) {
    int sz = pred ? 4 : 0;
    asm volatile("cp.async.ca.shared.global [%0], [%1], 4, %2;\n"
                 :: "r"(saddr), "l"(g), "r"(sz));
}
__device__ __forceinline__ void cpasync16(uint32_t saddr, const void* g) {
    asm volatile("cp.async.cg.shared.global [%0], [%1], 16;\n"
                 :: "r"(saddr), "l"(g));
}
#define CP_COMMIT() asm volatile("cp.async.commit_group;\n" ::: "memory")
#define CP_WAIT0()  asm volatile("cp.async.wait_group 0;\n" ::: "memory")

// ---------------------------------------------------------------------------
// Weight K-order permutation for 3x3 convs: Wp[m][t][ic] = W[m][ic][t].
// ---------------------------------------------------------------------------
__global__ void permw_kernel(const float* __restrict__ W,
                             float* __restrict__ Wp, int M, int Cin)
{
    int K = Cin * 9;
    int i = blockIdx.x * 256 + threadIdx.x;
    if (i >= M * K) return;
    int m = i / K;
    int r = i - m * K;          // r = t*Cin + ic
    int t = r / Cin;
    int ic = r - t * Cin;
    Wp[i] = W[(size_t)m * K + ic * 9 + t];
}

// ---------------------------------------------------------------------------
// fp32 [2P][4*N4] -> half2 channel-pair packed uint32 [P][4*N4] (as uint4)
// ---------------------------------------------------------------------------
__global__ void halfpack4_kernel(const float* __restrict__ X,
                                 uint4* __restrict__ Xp, int P, int N4)
{
    int i = blockIdx.x * 256 + threadIdx.x;
    if (i >= P * N4) return;
    int pr = i / N4, n4 = i - pr * N4;
    float4 a = reinterpret_cast<const float4*>(X)[(size_t)(2 * pr) * N4 + n4];
    float4 b = reinterpret_cast<const float4*>(X)[(size_t)(2 * pr + 1) * N4 + n4];
    uint4 o;
    o.x = pack_h2(a.x, b.x);
    o.y = pack_h2(a.y, b.y);
    o.z = pack_h2(a.z, b.z);
    o.w = pack_h2(a.w, b.w);
    Xp[i] = o;
}

// ---------------------------------------------------------------------------
// fp16 tensor-core implicit-GEMM conv, packed-B version.
// A (weights fp32, tap-major K for KS==3): LDG float4 -> half2 -> STS.
//   As2: uint32 kpair rows [8][BM+8]; frag banks conflict-free.
// B (activations, PRE-PACKED half2 channel pairs [Cin/2][IHW]): cp.async of
//   raw uint32; fragments are direct LDS.32 (b0=[lt], b1=[lt+4]); B2STR=136
//   gives banks 8*lt+lg — all 32 distinct.
// mma.m16n8k16 f16. KS==3 requires Cin % 16 == 0; KS==1 requires N % 128 == 0.
// ---------------------------------------------------------------------------
template<int KS, int FM>
__global__ __launch_bounds__(256)
void conv_mma(const float* __restrict__ Wt,
              const uint32_t* __restrict__ Xp,
              float* __restrict__ Y,
              const float* __restrict__ bias,
              int M, int Cin, int IH, int IW,
              int OH, int OW, int pad)
{
    constexpr int BM    = 32 * FM;
    constexpr int BN    = 128;
    constexpr int BK    = 16;               // k elements per tile (8 kpairs)
    constexpr int A2STR = BM + 8;
    constexpr int B2STR = 136;
    constexpr int AELE  = BM * BK / 4;
    constexpr int AITER = (AELE + 255) / 256;

    __shared__ uint32_t As2[2][8 * A2STR];
    __shared__ uint32_t Bs2[2][8 * B2STR];

    const int N   = OH * OW;
    const int K   = Cin * KS * KS;
    const int IHW = IH * IW;
    const int bz  = blockIdx.z;
    const int m0  = blockIdx.y * BM;
    const int n0  = blockIdx.x * BN;

    const int tid  = threadIdx.x;
    const int wid  = tid >> 5;
    const int lane = tid & 31;
    const int wm   = wid & 1;
    const int wn   = wid >> 1;
    const int mbase = wm * (16 * FM);
    const int nbase = wn * 32;
    const int lg = lane >> 2;
    const int lt = lane & 3;

    const uint32_t* Xb = Xp + (size_t)bz * (Cin >> 1) * IHW;

    float acc[FM][4][4];
    #pragma unroll
    for (int f = 0; f < FM; ++f)
        #pragma unroll
        for (int nf = 0; nf < 4; ++nf)
            #pragma unroll
            for (int r = 0; r < 4; ++r) acc[f][nf][r] = 0.f;

    // B-gather per-thread coords (KS==3 path)
    const int bn = tid & 127;
    const int gn = n0 + bn;
    const bool nvalid = gn < N;
    int oy = 0, ox = 0;
    if (KS == 3) { int g = nvalid ? gn : 0; oy = g / OW; ox = g - oy * OW; }

    float4 aReg[AITER];

    auto ldA = [&](int k0) {
        #pragma unroll
        for (int r = 0; r < AITER; ++r) {
            int e = tid + r * 256;
            float4 v = make_float4(0.f, 0.f, 0.f, 0.f);
            if (AELE == 512 || e < AELE) {
                int m  = e >> 2;
                int kq = e & 3;
                int gm = m0 + m;
                if (gm < M)
                    v = *reinterpret_cast<const float4*>(Wt + (size_t)gm * K + k0 + kq * 4);
            }
            aReg[r] = v;
        }
    };
    auto stA = [&](int buf) {
        #pragma unroll
        for (int r = 0; r < AITER; ++r) {
            int e = tid + r * 256;
            if (AELE == 512 || e < AELE) {
                int m  = e >> 2;
                int kq = e & 3;
                As2[buf][(kq * 2 + 0) * A2STR + m] = pack_h2(aReg[r].x, aReg[r].y);
                As2[buf][(kq * 2 + 1) * A2STR + m] = pack_h2(aReg[r].z, aReg[r].w);
            }
        }
    };
    auto issueB = [&](int k0, int buf) {
        if (KS == 1) {
            // 8 kpair rows x 128 cols of uint32; one 16B copy per thread
            int row = tid >> 5;
            int c4  = (tid & 31) * 4;
            uint32_t s = (uint32_t)__cvta_generic_to_shared(&Bs2[buf][row * B2STR + c4]);
            cpasync16(s, Xb + (size_t)((k0 >> 1) + row) * N + n0 + c4);
        } else {
            // tap-major K: whole tile shares one tap (uniform across block)
            int tp  = k0 / Cin;
            int icb = k0 - tp * Cin;
            int tdy = (tp >= 6) ? 2 : ((tp >= 3) ? 1 : 0);
            int tdx = tp - 3 * tdy;
            int iy  = oy + tdy - pad;
            int ix  = ox + tdx - pad;
            bool ok = nvalid && iy >= 0 && iy < IH && ix >= 0 && ix < IW;
            const uint32_t* base = Xb + (size_t)(icb >> 1) * IHW + iy * IW + ix;
            #pragma unroll
            for (int r = 0; r < 4; ++r) {
                int kp = (tid >> 7) + 2 * r;
                uint32_t s = (uint32_t)__cvta_generic_to_shared(&Bs2[buf][kp * B2STR + bn]);
                cpasync4(s, base + (size_t)kp * IHW, ok);
            }
        }
    };
    auto compute = [&](int buf) {
        uint32_t a[FM][4];
        #pragma unroll
        for (int f = 0; f < FM; ++f) {
            int mr = mbase + f * 16 + lg;
            a[f][0] = As2[buf][lt * A2STR + mr];
            a[f][1] = As2[buf][lt * A2STR + mr + 8];
            a[f][2] = As2[buf][(lt + 4) * A2STR + mr];
            a[f][3] = As2[buf][(lt + 4) * A2STR + mr + 8];
        }
        #pragma unroll
        for (int nf = 0; nf < 4; ++nf) {
            int nc = nbase + nf * 8 + lg;
            uint32_t b0 = Bs2[buf][lt * B2STR + nc];
            uint32_t b1 = Bs2[buf][(lt + 4) * B2STR + nc];
            #pragma unroll
            for (int f = 0; f < FM; ++f)
                mma_16x8x16(acc[f][nf], a[f], b0, b1);
        }
    };

    const int kTiles = K / BK;
    issueB(0, 0); CP_COMMIT();
    ldA(0); stA(0);
    CP_WAIT0(); __syncthreads();

    for (int t = 0; t < kTiles; ++t) {
        if (t + 1 < kTiles) {
            issueB((t + 1) * BK, (t + 1) & 1); CP_COMMIT();
            ldA((t + 1) * BK);
        }
        compute(t & 1);
        if (t + 1 < kTiles) {
            stA((t + 1) & 1);
            CP_WAIT0(); __syncthreads();
        }
    }

    // ---- epilogue ----
    #pragma unroll
    for (int f = 0; f < FM; ++f) {
        int r0 = m0 + mbase + f * 16 + lg;
        #pragma unroll
        for (int nf = 0; nf < 4; ++nf) {
            int cb = n0 + nbase + nf * 8 + 2 * lt;
            #pragma unroll
            for (int rr = 0; rr < 2; ++rr) {
                int m = r0 + rr * 8;
                if (m >= M) continue;
                float bval = bias ? bias[m] : 0.f;
                #pragma unroll
                for (int cc = 0; cc < 2; ++cc) {
                    int n = cb + cc;
                    if (n >= N) continue;
                    Y[((size_t)bz * M + m) * N + n] = acc[f][nf][rr * 2 + cc] + bval;
                }
            }
        }
    }
}

// ---------------------------------------------------------------------------
// grouped 3x3 conv, smem-tiled
// ---------------------------------------------------------------------------
__global__ __launch_bounds__(256)
void dwconv2_kernel(const float* __restrict__ X,
                    const float* __restrict__ W,
                    float* __restrict__ Y)
{
    __shared__ float xs[2][34][35];
    __shared__ float ws[36];

    const int tile = blockIdx.x;
    const int g    = blockIdx.y;
    const int b    = blockIdx.z;
    const int ty0  = (tile / 3) * 32;
    const int tx0  = (tile % 3) * 32;
    const int tid  = threadIdx.x;

    if (tid < 36) ws[tid] = W[(size_t)g * 36 + tid];

    for (int e = tid; e < 2 * 34 * 34; e += 256) {
        int c  = e / (34 * 34);
        int r  = e - c * 34 * 34;
        int yy = r / 34, xx = r - yy * 34;
        int gy = ty0 + yy - 1, gx = tx0 + xx - 1;
        float v = 0.f;
        if (gy >= 0 && gy < Hh && gx >= 0 && gx < Ww)
            v = X[((size_t)b * C2 + 2 * g + c) * HW + gy * Ww + gx];
        xs[c][yy][xx] = v;
    }
    __syncthreads();

    const int x  = tid & 31;
    const int yb = (tid >> 5) * 4;
    #pragma unroll
    for (int j = 0; j < 4; ++j) {
        int y = yb + j;
        float a0 = 0.f, a1 = 0.f;
        #pragma unroll
        for (int c = 0; c < 2; ++c)
            #pragma unroll
            for (int ky = 0; ky < 3; ++ky)
                #pragma unroll
                for (int kx = 0; kx < 3; ++kx) {
                    float v = xs[c][y + ky][x + kx];
                    a0 += v * ws[c * 9 + ky * 3 + kx];
                    a1 += v * ws[18 + c * 9 + ky * 3 + kx];
                }
        size_t o = ((size_t)b * C2 + 2 * g) * HW + (ty0 + y) * Ww + tx0 + x;
        Y[o]      = a0;
        Y[o + HW] = a1;
    }
}

// cat = [q ; y] (float4)
__global__ void cat4_kernel(const float* __restrict__ QKV,
                            const float* __restrict__ Yin,
                            float* __restrict__ CAT)
{
    int i = blockIdx.x * 256 + threadIdx.x;
    if (i >= Bn * C2 * HW / 4) return;
    int p4 = i % (HW / 4);
    int c  = (i / (HW / 4)) % C2;
    int b  = i / ((HW / 4) * C2);
    float4 v;
    if (c < Cc) v = reinterpret_cast<const float4*>(QKV + ((size_t)b * C2 + c) * HW)[p4];
    else        v = reinterpret_cast<const float4*>(Yin + ((size_t)b * Cc + (c - Cc)) * HW)[p4];
    reinterpret_cast<float4*>(CAT)[i] = v;
}

// 2x2 avg pool, 96 -> 48 (float4)
__global__ void pool4_kernel(const float* __restrict__ X, float* __restrict__ Y)
{
    int i = blockIdx.x * 256 + threadIdx.x;
    const int OHW4 = 48 * 48 / 4;      // 576
    if (i >= Bn * C2 * OHW4) return;
    int r  = i % OHW4;
    int bc = i / OHW4;
    int y  = r / 12;
    int x8 = (r % 12) * 8;
    const float* xp = X + (size_t)bc * HW;
    float4 r0a = *reinterpret_cast<const float4*>(xp + (2 * y) * Ww + x8);
    float4 r0b = *reinterpret_cast<const float4*>(xp + (2 * y) * Ww + x8 + 4);
    float4 r1a = *reinterpret_cast<const float4*>(xp + (2 * y + 1) * Ww + x8);
    float4 r1b = *reinterpret_cast<const float4*>(xp + (2 * y + 1) * Ww + x8 + 4);
    float4 o;
    o.x = (r0a.x + r0a.y + r1a.x + r1a.y) * 0.25f;
    o.y = (r0a.z + r0a.w + r1a.z + r1a.w) * 0.25f;
    o.z = (r0b.x + r0b.y + r1b.x + r1b.y) * 0.25f;
    o.w = (r0b.z + r0b.w + r1b.z + r1b.w) * 0.25f;
    reinterpret_cast<float4*>(Y)[i] = o;
}

// SC = SC * sigmoid(CAT + upsample(K2))  (float4)
__global__ void sigmul4_kernel(float* __restrict__ SC,
                               const float* __restrict__ CAT,
                               const float* __restrict__ K2)
{
    int i = blockIdx.x * 256 + threadIdx.x;
    if (i >= Bn * C2 * HW / 4) return;
    int p4 = i % (HW / 4);
    int bc = i / (HW / 4);
    int p  = p4 * 4;
    int y  = p / Ww, x = p % Ww;
    int iy = (y * 46) / 96;
    const float* k2r = K2 + (size_t)bc * (46 * 46) + iy * 46;
    float4 cv = reinterpret_cast<const float4*>(CAT)[i];
    float4 sv = reinterpret_cast<const float4*>(SC)[i];
    float k0 = k2r[((x + 0) * 46) / 96];
    float k1 = k2r[((x + 1) * 46) / 96];
    float k2v = k2r[((x + 2) * 46) / 96];
    float k3 = k2r[((x + 3) * 46) / 96];
    sv.x = sv.x / (1.f + expf(-(cv.x + k0)));
    sv.y = sv.y / (1.f + expf(-(cv.y + k1)));
    sv.z = sv.z / (1.f + expf(-(cv.z + k2v)));
    sv.w = sv.w / (1.f + expf(-(cv.w + k3)));
    reinterpret_cast<float4*>(SC)[i] = sv;
}

// ---------------------------------------------------------------------------
// fused deformable conv; weights transposed in smem; stores relu(out)
// ---------------------------------------------------------------------------
__global__ __launch_bounds__(128)
void deform_kernel(const float* __restrict__ Q,
                   const float* __restrict__ OFF,
                   const float* __restrict__ W,
                   const float* __restrict__ Bias,
                   float* __restrict__ Y)
{
    __shared__ float ws2[216 * 24];   // ws2[(i*9+t)*24 + o]
    const int g = blockIdx.y;
    const int b = blockIdx.z;
    const int tid = threadIdx.x;

    for (int e = tid; e < 216 * 24; e += 128) {
        int it = e / 24;
        int o  = e - it * 24;
        ws2[e] = W[(size_t)(g * CG + o) * 216 + it];
    }
    __syncthreads();

    int p = blockIdx.x * 128 + tid;
    int y = p / Ww, x = p % Ww;
    const float* offb = OFF + (size_t)b * 18 * HW;

    float acc[24];
    #pragma unroll
    for (int o = 0; o < 24; ++o) acc[o] = Bias[g * CG + o];

    const float* qc = Q + ((size_t)b * C2 + g * CG) * HW;

    for (int t = 0; t < 9; ++t) {
        float dy = offb[(size_t)(2 * t) * HW + p];
        float dx = offb[(size_t)(2 * t + 1) * HW + p];
        float m  = 1.f / (1.f + expf(-offb[(size_t)t * HW + p]));
        float py = dy + (float)(y - 1 + t / 3);
        float px = dx + (float)(x - 1 + t % 3);
        float y0f = floorf(py), x0f = floorf(px);
        int   y0 = (int)y0f,    x0 = (int)x0f;
        float fy = py - y0f,    fx = px - x0f;
        float w00 = (1.f - fy) * (1.f - fx);
        float w01 = (1.f - fy) * fx;
        float w10 = fy * (1.f - fx);
        float w11 = fy * fx;
        bool vy0 = (y0 >= 0 && y0 <= Hh - 1), vy1 = (y0 + 1 >= 0 && y0 + 1 <= Hh - 1);
        bool vx0 = (x0 >= 0 && x0 <= Ww - 1), vx1 = (x0 + 1 >= 0 && x0 + 1 <= Ww - 1);
        int cy0 = min(max(y0, 0), Hh - 1),     cy1 = min(max(y0 + 1, 0), Hh - 1);
        int cx0 = min(max(x0, 0), Ww - 1),     cx1 = min(max(x0 + 1, 0), Ww - 1);
        int i00 = cy0 * Ww + cx0, i01 = cy0 * Ww + cx1;
        int i10 = cy1 * Ww + cx0, i11 = cy1 * Ww + cx1;
        w00 = (vy0 && vx0) ? w00 * m : 0.f;
        w01 = (vy0 && vx1) ? w01 * m : 0.f;
        w10 = (vy1 && vx0) ? w10 * m : 0.f;
        w11 = (vy1 && vx1) ? w11 * m : 0.f;

        #pragma unroll
        for (int i = 0; i < 24; ++i) {
            const float* qp = qc + (size_t)i * HW;
            float val = w00 * qp[i00] + w01 * qp[i01] + w10 * qp[i10] + w11 * qp[i11];
            const float* wr = &ws2[(i * 9 + t) * 24];
            #pragma unroll
            for (int o = 0; o < 24; ++o) acc[o] += val * wr[o];
        }
    }
    #pragma unroll
    for (int o = 0; o < 24; ++o)
        Y[((size_t)b * Cc + g * CG + o) * HW + p] = fmaxf(acc[o], 0.f);
}

// ---------------------------------------------------------------------------
// row L2 norms (float4)
// ---------------------------------------------------------------------------
__global__ void rownorm_kernel(const float* __restrict__ QKV,
                               const float* __restrict__ Kb,
                               float* __restrict__ QN,
                               float* __restrict__ KN)
{
    int row   = blockIdx.x;
    int which = row / (Bn * Cc);
    row %= (Bn * Cc);
    int b = row / Cc, c = row % Cc;
    const float* src = which ? (Kb + ((size_t)b * Cc + c) * HW)
                             : (QKV + ((size_t)b * C2 + c) * HW);
    float s = 0.f;
    for (int n = threadIdx.x; n < HW / 4; n += 256) {
        float4 v = reinterpret_cast<const float4*>(src)[n];
        s += v.x * v.x + v.y * v.y + v.z * v.z + v.w * v.w;
    }
    __shared__ float sm[256];
    sm[threadIdx.x] = s;
    __syncthreads();
    for (int d = 128; d > 0; d >>= 1) {
        if (threadIdx.x < d) sm[threadIdx.x] += sm[threadIdx.x + d];
        __syncthreads();
    }
    if (threadIdx.x == 0) {
        float nrm = fmaxf(sqrtf(sm[0]), 1e-12f);
        (which ? KN : QN)[b * Cc + c] = nrm;
    }
}

// ---------------------------------------------------------------------------
// attention: one block per (b,h).  K-head staged through smem.
// ---------------------------------------------------------------------------
#define CNK 384
__global__ __launch_bounds__(256)
void attn2_kernel(const float* __restrict__ QKV,
                  const float* __restrict__ Kb,
                  const float* __restrict__ QN,
                  const float* __restrict__ KN,
                  const float* __restrict__ TEMP,
                  float* __restrict__ ATTN)
{
    __shared__ float ks_[24][CNK + 8];
    __shared__ float logits[24][24];

    const int b = blockIdx.x >> 3;
    const int h = blockIdx.x & 7;
    const int tid  = threadIdx.x;
    const int wid  = tid >> 5;
    const int lane = tid & 31;

    const float* qh = QKV + ((size_t)b * C2 + h * HD) * HW;
    const float* kh = Kb  + ((size_t)b * Cc + h * HD) * HW;

    float acc[3][24];
    #pragma unroll
    for (int r = 0; r < 3; ++r)
        #pragma unroll
        for (int j = 0; j < 24; ++j) acc[r][j] = 0.f;

    const float* q0p = qh + (size_t)(3 * wid + 0) * HW;
    const float* q1p = qh + (size_t)(3 * wid + 1) * HW;
    const float* q2p = qh + (size_t)(3 * wid + 2) * HW;

    for (int n0 = 0; n0 < HW; n0 += CNK) {
        __syncthreads();
        for (int e = tid; e < 24 * (CNK / 4); e += 256) {
            int j = e / (CNK / 4);
            int c = e - j * (CNK / 4);
            float4 v = *reinterpret_cast<const float4*>(kh + (size_t)j * HW + n0 + c * 4);
            ks_[j][c * 4 + 0] = v.x;
            ks_[j][c * 4 + 1] = v.y;
            ks_[j][c * 4 + 2] = v.z;
            ks_[j][c * 4 + 3] = v.w;
        }
        __syncthreads();

        for (int i = lane; i < CNK; i += 32) {
            int n = n0 + i;
            float q0 = q0p[n], q1 = q1p[n], q2 = q2p[n];
            #pragma unroll
            for (int j = 0; j < 24; ++j) {
                float kv = ks_[j][i];
                acc[0][j] += q0 * kv;
                acc[1][j] += q1 * kv;
                acc[2][j] += q2 * kv;
            }
        }
    }

    #pragma unroll
    for (int r = 0; r < 3; ++r)
        #pragma unroll
        for (int j = 0; j < 24; ++j) {
            float v = acc[r][j];
            for (int o = 16; o > 0; o >>= 1) v += __shfl_down_sync(0xffffffffu, v, o);
            if (lane == 0) logits[wid * 3 + r][j] = v;
        }
    __syncthreads();

    if (tid < 24) {
        int i = tid;
        float qn = QN[b * Cc + h * HD + i];
        float tp = TEMP[h];
        float s[24];
        float mx = -1e30f;
        #pragma unroll
        for (int j = 0; j < 24; ++j) {
            s[j] = logits[i][j] / (qn * KN[b * Cc + h * HD + j]) * tp;
            mx = fmaxf(mx, s[j]);
        }
        float sum = 0.f;
        #pragma unroll
        for (int j = 0; j < 24; ++j) { s[j] = expf(s[j] - mx); sum += s[j]; }
        float inv = 1.f / sum;
        #pragma unroll
        for (int j = 0; j < 24; ++j)
            ATTN[(((size_t)b * NH + h) * HD + i) * HD + j] = s[j] * inv;
    }
}

// out = attn @ v
__global__ void attnv_kernel(const float* __restrict__ ATTN,
                             const float* __restrict__ QKV,
                             float* __restrict__ AO)
{
    int h = blockIdx.y, b = blockIdx.z;
    int n = blockIdx.x * 256 + threadIdx.x;
    __shared__ float a_s[HD * HD];
    for (int e = threadIdx.x; e < HD * HD; e += 256)
        a_s[e] = ATTN[((size_t)b * NH + h) * HD * HD + e];
    __syncthreads();
    const float* vb = QKV + ((size_t)b * C2 + Cc + h * HD) * HW;
    float acc[HD] = {};
    #pragma unroll
    for (int j = 0; j < HD; ++j) {
        float vv = vb[(size_t)j * HW + n];
        #pragma unroll
        for (int i = 0; i < HD; ++i) acc[i] += a_s[i * HD + j] * vv;
    }
    #pragma unroll
    for (int i = 0; i < HD; ++i)
        AO[((size_t)b * Cc + h * HD + i) * HW + n] = acc[i];
}

// ---------------------------------------------------------------------------
// launcher
// ---------------------------------------------------------------------------
extern "C" void kernel_launch(void* const* d_in, const int* in_sizes, int n_in,
                              void* d_out, int out_size)
{
    const float* x           = (const float*)d_in[0];
    const float* y           = (const float*)d_in[1];
    const float* temperature = (const float*)d_in[2];
    const float* qkv_w       = (const float*)d_in[3];
    const float* qkv_conv_w  = (const float*)d_in[4];
    const float* proj_w      = (const float*)d_in[5];
    const float* k2_w        = (const float*)d_in[6];
    const float* k3_w        = (const float*)d_in[7];
    const float* k4_w        = (const float*)d_in[8];
    const float* deform_w    = (const float*)d_in[9];
    const float* deform_b    = (const float*)d_in[10];
    const float* pw_w        = (const float*)d_in[11];
    const float* pw_b        = (const float*)d_in[12];
    float* out = (float*)d_out;

    float* S = nullptr;
    cudaGetSymbolAddress((void**)&S, g_scratch);
    float* QKV1 = S + OFF_QKV1;
    float* QKV  = S + OFF_QKV;
    float* CAT  = S + OFF_CAT;
    float* SC   = S + OFF_SC;
    float* POOL = S + OFF_POOL;
    float* K2   = S + OFF_K2;
    float* OFFb = S + OFF_OFF;
    float* FEAT = S + OFF_FEAT;
    float* Kb   = S + OFF_K;
    float* AO   = S + OFF_AO;
    float* QN   = S + OFF_QN;
    float* KN   = S + OFF_KN;
    float* ATTN = S + OFF_ATTN;
    float* WK3P = S + OFF_WK3P;
    float* WK2P = S + OFF_WK2P;
    float* WK4P = S + OFF_WK4P;
    uint32_t* XH    = (uint32_t*)(S + OFF_XH);
    uint32_t* CATH  = (uint32_t*)(S + OFF_CATH);
    uint32_t* POOLH = (uint32_t*)(S + OFF_POOLH);
    uint32_t* SCH   = (uint32_t*)(S + OFF_SCH);
    uint32_t* FEATH = (uint32_t*)(S + OFF_FEATH);
    uint32_t* AOH   = (uint32_t*)(S + OFF_AOH);

    const int NE = Bn * C2 * HW;

    // 0) weight permutes + pack x
    permw_kernel<<<(1327104 + 255) / 256, 256>>>(k3_w, WK3P, C2, C2);
    permw_kernel<<<(1327104 + 255) / 256, 256>>>(k2_w, WK2P, C2, C2);
    permw_kernel<<<(62208 + 255) / 256, 256>>>(k4_w, WK4P, 18, C2);
    halfpack4_kernel<<<(384 * 2304 + 255) / 256, 256>>>(x, (uint4*)XH, 384, 2304);

    // 1) qkv 1x1: 384 x 192 x 9216
    conv_mma<1, 4><<<dim3(HW / 128, C2 / 128, Bn), 256>>>(
        qkv_w, XH, QKV1, nullptr, C2, Cc, Hh, Ww, Hh, Ww, 0);
    // 2) grouped 3x3 (groups=192)
    dwconv2_kernel<<<dim3(9, 192, Bn), 256>>>(QKV1, qkv_conv_w, QKV);
    // 3) cat = [q ; y] ; pack
    cat4_kernel<<<(NE / 4 + 255) / 256, 256>>>(QKV, y, CAT);
    halfpack4_kernel<<<(768 * 2304 + 255) / 256, 256>>>(CAT, (uint4*)CATH, 768, 2304);
    // 4) k3 conv 3x3 pad=1 (tap-major weights, packed B)
    conv_mma<3, 4><<<dim3(HW / 128, C2 / 128, Bn), 256>>>(
        WK3P, CATH, SC, nullptr, C2, C2, Hh, Ww, Hh, Ww, 1);
    // 5) avg pool 2x2 ; pack
    pool4_kernel<<<(Bn * C2 * 576 + 255) / 256, 256>>>(CAT, POOL);
    halfpack4_kernel<<<(768 * 576 + 255) / 256, 256>>>(POOL, (uint4*)POOLH, 768, 576);
    // 6) k2 conv 3x3 pad=0 : 48x48 -> 46x46
    conv_mma<3, 4><<<dim3((46 * 46 + 127) / 128, C2 / 128, Bn), 256>>>(
        WK2P, POOLH, K2, nullptr, C2, C2, 48, 48, 46, 46, 0);
    // 7) SC = SC * sigmoid(CAT + upsample(K2)) ; pack
    sigmul4_kernel<<<(NE / 4 + 255) / 256, 256>>>(SC, CAT, K2);
    halfpack4_kernel<<<(768 * 2304 + 255) / 256, 256>>>(SC, (uint4*)SCH, 768, 2304);
    // 8) offset = conv3x3(sc, k4, pad=1), M=18
    conv_mma<3, 1><<<dim3(HW / 128, 1, Bn), 256>>>(
        WK4P, SCH, OFFb, nullptr, 18, C2, Hh, Ww, Hh, Ww, 1);
    // 9) deformable conv -> FEAT = relu(deform) ; pack
    deform_kernel<<<dim3(HW / 128, Gg, Bn), 128>>>(QKV, OFFb, deform_w, deform_b, FEAT);
    halfpack4_kernel<<<(384 * 2304 + 255) / 256, 256>>>(FEAT, (uint4*)FEATH, 384, 2304);
    // 10) k = 1x1(FEAT) + pw_b
    conv_mma<1, 4><<<dim3(HW / 128, (Cc + 127) / 128, Bn), 256>>>(
        pw_w, FEATH, Kb, pw_b, Cc, Cc, Hh, Ww, Hh, Ww, 0);
    // 11) row norms
    rownorm_kernel<<<2 * Bn * Cc, 256>>>(QKV, Kb, QN, KN);
    // 12) attention logits + softmax
    attn2_kernel<<<Bn * NH, 256>>>(QKV, Kb, QN, KN, temperature, ATTN);
    // 13) out = attn @ v ; pack
    attnv_kernel<<<dim3(HW / 256, NH, Bn), 256>>>(ATTN, QKV, AO);
    halfpack4_kernel<<<(384 * 2304 + 255) / 256, 256>>>(AO, (uint4*)AOH, 384, 2304);
    // 14) final 1x1 proj -> d_out
    conv_mma<1, 4><<<dim3(HW / 128, (Cc + 127) / 128, Bn), 256>>>(
        proj_w, AOH, out, nullptr, Cc, Cc, Hh, Ww, Hh, Ww, 0);
}

// round 12
// speedup vs baseline: 2.2171x; 1.0194x over previous
#include <cuda_runtime.h>
#include <cuda_fp16.h>
#include <math.h>
#include <stdint.h>

// ---------------------------------------------------------------------------
// Problem constants
// ---------------------------------------------------------------------------
#define Bn   4
#define Cc   192
#define C2   384
#define Hh   96
#define Ww   96
#define HW   (Hh*Ww)          // 9216
#define NH   8
#define HD   24
#define Gg   8
#define CG   24

// scratch offsets (in floats / uint32 slots)
#define OFF_QKV1  0ul
#define OFF_QKV   14155776ul
#define OFF_CAT   28311552ul
#define OFF_SC    42467328ul
#define OFF_K2    56623104ul     // 3250176
#define OFF_OFF   59873280ul     // 663552
#define OFF_K     60536832ul     // 7077888
#define OFF_QN    67614720ul
#define OFF_KN    67615488ul
#define OFF_ATTN  67616256ul
#define OFF_WK3P  67634688ul     // 1327104
#define OFF_WK2P  68961792ul     // 1327104
#define OFF_WK4P  70288896ul     // 62208
#define OFF_XH    70351104ul     // 3538944
#define OFF_CATH  73890048ul     // 7077888
#define OFF_POOLH 80967936ul     // 1769472
#define OFF_SCH   82737408ul     // 7077888
#define OFF_FEATH 89815296ul     // 3538944
#define OFF_AOH   93354240ul     // 3538944
#define SCRATCH_TOTAL 96893184ul

__device__ float g_scratch[SCRATCH_TOTAL];

// ---------------------------------------------------------------------------
// helpers
// ---------------------------------------------------------------------------
__device__ __forceinline__ uint32_t pack_h2(float lo, float hi) {
    __half2 h = __floats2half2_rn(lo, hi);
    return *reinterpret_cast<uint32_t*>(&h);
}

__device__ __forceinline__ void mma_16x8x16(float* c, const uint32_t* a,
                                            uint32_t b0, uint32_t b1) {
    asm volatile(
        "mma.sync.aligned.m16n8k16.row.col.f32.f16.f16.f32 "
        "{%0,%1,%2,%3}, {%4,%5,%6,%7}, {%8,%9}, {%0,%1,%2,%3};\n"
        : "+f"(c[0]), "+f"(c[1]), "+f"(c[2]), "+f"(c[3])
        : "r"(a[0]), "r"(a[1]), "r"(a[2]), "r"(a[3]), "r"(b0), "r"(b1));
}

__device__ __forceinline__ void cpasync4(uint32_t saddr, const void* g, bool pred) {
    int sz = pred ? 4 : 0;
    asm volatile("cp.async.ca.shared.global [%0], [%1], 4, %2;\n"
                 :: "r"(saddr), "l"(g), "r"(sz));
}
__device__ __forceinline__ void cpasync16(uint32_t saddr, const void* g) {
    asm volatile("cp.async.cg.shared.global [%0], [%1], 16;\n"
                 :: "r"(saddr), "l"(g));
}
#define CP_COMMIT() asm volatile("cp.async.commit_group;\n" ::: "memory")
#define CP_WAIT0()  asm volatile("cp.async.wait_group 0;\n" ::: "memory")

// ---------------------------------------------------------------------------
// Weight K-order permutation for 3x3 convs: Wp[m][t][ic] = W[m][ic][t].
// ---------------------------------------------------------------------------
__global__ void permw_kernel(const float* __restrict__ W,
                             float* __restrict__ Wp, int M, int Cin)
{
    int K = Cin * 9;
    int i = blockIdx.x * 256 + threadIdx.x;
    if (i >= M * K) return;
    int m = i / K;
    int r = i - m * K;
    int t = r / Cin;
    int ic = r - t * Cin;
    Wp[i] = W[(size_t)m * K + ic * 9 + t];
}

// ---------------------------------------------------------------------------
// fp32 [2P][4*N4] -> half2 channel-pair packed uint32 [P][4*N4] (as uint4)
// (only used for the external input x)
// ---------------------------------------------------------------------------
__global__ void halfpack4_kernel(const float* __restrict__ X,
                                 uint4* __restrict__ Xp, int P, int N4)
{
    int i = blockIdx.x * 256 + threadIdx.x;
    if (i >= P * N4) return;
    int pr = i / N4, n4 = i - pr * N4;
    float4 a = reinterpret_cast<const float4*>(X)[(size_t)(2 * pr) * N4 + n4];
    float4 b = reinterpret_cast<const float4*>(X)[(size_t)(2 * pr + 1) * N4 + n4];
    uint4 o;
    o.x = pack_h2(a.x, b.x);
    o.y = pack_h2(a.y, b.y);
    o.z = pack_h2(a.z, b.z);
    o.w = pack_h2(a.w, b.w);
    Xp[i] = o;
}

// ---------------------------------------------------------------------------
// fp16 tensor-core implicit-GEMM conv, packed-B (proven round-11 config).
// ---------------------------------------------------------------------------
template<int KS, int FM>
__global__ __launch_bounds__(256)
void conv_mma(const float* __restrict__ Wt,
              const uint32_t* __restrict__ Xp,
              float* __restrict__ Y,
              const float* __restrict__ bias,
              int M, int Cin, int IH, int IW,
              int OH, int OW, int pad)
{
    constexpr int BM    = 32 * FM;
    constexpr int BN    = 128;
    constexpr int BK    = 16;
    constexpr int A2STR = BM + 8;
    constexpr int B2STR = 136;
    constexpr int AELE  = BM * BK / 4;
    constexpr int AITER = (AELE + 255) / 256;

    __shared__ uint32_t As2[2][8 * A2STR];
    __shared__ uint32_t Bs2[2][8 * B2STR];

    const int N   = OH * OW;
    const int K   = Cin * KS * KS;
    const int IHW = IH * IW;
    const int bz  = blockIdx.z;
    const int m0  = blockIdx.y * BM;
    const int n0  = blockIdx.x * BN;

    const int tid  = threadIdx.x;
    const int wid  = tid >> 5;
    const int lane = tid & 31;
    const int wm   = wid & 1;
    const int wn   = wid >> 1;
    const int mbase = wm * (16 * FM);
    const int nbase = wn * 32;
    const int lg = lane >> 2;
    const int lt = lane & 3;

    const uint32_t* Xb = Xp + (size_t)bz * (Cin >> 1) * IHW;

    float acc[FM][4][4];
    #pragma unroll
    for (int f = 0; f < FM; ++f)
        #pragma unroll
        for (int nf = 0; nf < 4; ++nf)
            #pragma unroll
            for (int r = 0; r < 4; ++r) acc[f][nf][r] = 0.f;

    const int bn = tid & 127;
    const int gn = n0 + bn;
    const bool nvalid = gn < N;
    int oy = 0, ox = 0;
    if (KS == 3) { int g = nvalid ? gn : 0; oy = g / OW; ox = g - oy * OW; }

    float4 aReg[AITER];

    auto ldA = [&](int k0) {
        #pragma unroll
        for (int r = 0; r < AITER; ++r) {
            int e = tid + r * 256;
            float4 v = make_float4(0.f, 0.f, 0.f, 0.f);
            if (AELE == 512 || e < AELE) {
                int m  = e >> 2;
                int kq = e & 3;
                int gm = m0 + m;
                if (gm < M)
                    v = *reinterpret_cast<const float4*>(Wt + (size_t)gm * K + k0 + kq * 4);
            }
            aReg[r] = v;
        }
    };
    auto stA = [&](int buf) {
        #pragma unroll
        for (int r = 0; r < AITER; ++r) {
            int e = tid + r * 256;
            if (AELE == 512 || e < AELE) {
                int m  = e >> 2;
                int kq = e & 3;
                As2[buf][(kq * 2 + 0) * A2STR + m] = pack_h2(aReg[r].x, aReg[r].y);
                As2[buf][(kq * 2 + 1) * A2STR + m] = pack_h2(aReg[r].z, aReg[r].w);
            }
        }
    };
    auto issueB = [&](int k0, int buf) {
        if (KS == 1) {
            int row = tid >> 5;
            int c4  = (tid & 31) * 4;
            uint32_t s = (uint32_t)__cvta_generic_to_shared(&Bs2[buf][row * B2STR + c4]);
            cpasync16(s, Xb + (size_t)((k0 >> 1) + row) * N + n0 + c4);
        } else {
            int tp  = k0 / Cin;
            int icb = k0 - tp * Cin;
            int tdy = (tp >= 6) ? 2 : ((tp >= 3) ? 1 : 0);
            int tdx = tp - 3 * tdy;
            int iy  = oy + tdy - pad;
            int ix  = ox + tdx - pad;
            bool ok = nvalid && iy >= 0 && iy < IH && ix >= 0 && ix < IW;
            const uint32_t* base = Xb + (size_t)(icb >> 1) * IHW + iy * IW + ix;
            #pragma unroll
            for (int r = 0; r < 4; ++r) {
                int kp = (tid >> 7) + 2 * r;
                uint32_t s = (uint32_t)__cvta_generic_to_shared(&Bs2[buf][kp * B2STR + bn]);
                cpasync4(s, base + (size_t)kp * IHW, ok);
            }
        }
    };
    auto compute = [&](int buf) {
        uint32_t a[FM][4];
        #pragma unroll
        for (int f = 0; f < FM; ++f) {
            int mr = mbase + f * 16 + lg;
            a[f][0] = As2[buf][lt * A2STR + mr];
            a[f][1] = As2[buf][lt * A2STR + mr + 8];
            a[f][2] = As2[buf][(lt + 4) * A2STR + mr];
            a[f][3] = As2[buf][(lt + 4) * A2STR + mr + 8];
        }
        #pragma unroll
        for (int nf = 0; nf < 4; ++nf) {
            int nc = nbase + nf * 8 + lg;
            uint32_t b0 = Bs2[buf][lt * B2STR + nc];
            uint32_t b1 = Bs2[buf][(lt + 4) * B2STR + nc];
            #pragma unroll
            for (int f = 0; f < FM; ++f)
                mma_16x8x16(acc[f][nf], a[f], b0, b1);
        }
    };

    const int kTiles = K / BK;
    issueB(0, 0); CP_COMMIT();
    ldA(0); stA(0);
    CP_WAIT0(); __syncthreads();

    for (int t = 0; t < kTiles; ++t) {
        if (t + 1 < kTiles) {
            issueB((t + 1) * BK, (t + 1) & 1); CP_COMMIT();
            ldA((t + 1) * BK);
        }
        compute(t & 1);
        if (t + 1 < kTiles) {
            stA((t + 1) & 1);
            CP_WAIT0(); __syncthreads();
        }
    }

    // ---- epilogue ----
    #pragma unroll
    for (int f = 0; f < FM; ++f) {
        int r0 = m0 + mbase + f * 16 + lg;
        #pragma unroll
        for (int nf = 0; nf < 4; ++nf) {
            int cb = n0 + nbase + nf * 8 + 2 * lt;
            #pragma unroll
            for (int rr = 0; rr < 2; ++rr) {
                int m = r0 + rr * 8;
                if (m >= M) continue;
                float bval = bias ? bias[m] : 0.f;
                #pragma unroll
                for (int cc = 0; cc < 2; ++cc) {
                    int n = cb + cc;
                    if (n >= N) continue;
                    Y[((size_t)bz * M + m) * N + n] = acc[f][nf][rr * 2 + cc] + bval;
                }
            }
        }
    }
}

// ---------------------------------------------------------------------------
// grouped 3x3 conv, smem-tiled
// ---------------------------------------------------------------------------
__global__ __launch_bounds__(256)
void dwconv2_kernel(const float* __restrict__ X,
                    const float* __restrict__ W,
                    float* __restrict__ Y)
{
    __shared__ float xs[2][34][35];
    __shared__ float ws[36];

    const int tile = blockIdx.x;
    const int g    = blockIdx.y;
    const int b    = blockIdx.z;
    const int ty0  = (tile / 3) * 32;
    const int tx0  = (tile % 3) * 32;
    const int tid  = threadIdx.x;

    if (tid < 36) ws[tid] = W[(size_t)g * 36 + tid];

    for (int e = tid; e < 2 * 34 * 34; e += 256) {
        int c  = e / (34 * 34);
        int r  = e - c * 34 * 34;
        int yy = r / 34, xx = r - yy * 34;
        int gy = ty0 + yy - 1, gx = tx0 + xx - 1;
        float v = 0.f;
        if (gy >= 0 && gy < Hh && gx >= 0 && gx < Ww)
            v = X[((size_t)b * C2 + 2 * g + c) * HW + gy * Ww + gx];
        xs[c][yy][xx] = v;
    }
    __syncthreads();

    const int x  = tid & 31;
    const int yb = (tid >> 5) * 4;
    #pragma unroll
    for (int j = 0; j < 4; ++j) {
        int y = yb + j;
        float a0 = 0.f, a1 = 0.f;
        #pragma unroll
        for (int c = 0; c < 2; ++c)
            #pragma unroll
            for (int ky = 0; ky < 3; ++ky)
                #pragma unroll
                for (int kx = 0; kx < 3; ++kx) {
                    float v = xs[c][y + ky][x + kx];
                    a0 += v * ws[c * 9 + ky * 3 + kx];
                    a1 += v * ws[18 + c * 9 + ky * 3 + kx];
                }
        size_t o = ((size_t)b * C2 + 2 * g) * HW + (ty0 + y) * Ww + tx0 + x;
        Y[o]      = a0;
        Y[o + HW] = a1;
    }
}

// cat: channel-pair thread; writes CAT fp32 (both rows) + CATH packed.
// pairs never straddle the q/y boundary (Cc = 192 even).
__global__ void catpack_kernel(const float* __restrict__ QKV,
                               const float* __restrict__ Yin,
                               float* __restrict__ CAT,
                               uint4* __restrict__ CATH)
{
    const int NP = C2 / 2;             // 192 pairs
    const int N4 = HW / 4;             // 2304
    int i = blockIdx.x * 256 + threadIdx.x;
    if (i >= Bn * NP * N4) return;
    int p4 = i % N4;
    int pr = (i / N4) % NP;
    int b  = i / (N4 * NP);
    int c0 = 2 * pr;
    float4 a, bv;
    if (c0 < Cc) {
        a  = reinterpret_cast<const float4*>(QKV + ((size_t)b * C2 + c0) * HW)[p4];
        bv = reinterpret_cast<const float4*>(QKV + ((size_t)b * C2 + c0 + 1) * HW)[p4];
    } else {
        a  = reinterpret_cast<const float4*>(Yin + ((size_t)b * Cc + (c0 - Cc)) * HW)[p4];
        bv = reinterpret_cast<const float4*>(Yin + ((size_t)b * Cc + (c0 - Cc) + 1) * HW)[p4];
    }
    reinterpret_cast<float4*>(CAT + ((size_t)b * C2 + c0) * HW)[p4]     = a;
    reinterpret_cast<float4*>(CAT + ((size_t)b * C2 + c0 + 1) * HW)[p4] = bv;
    uint4 o;
    o.x = pack_h2(a.x, bv.x);
    o.y = pack_h2(a.y, bv.y);
    o.z = pack_h2(a.z, bv.z);
    o.w = pack_h2(a.w, bv.w);
    CATH[((size_t)b * NP + pr) * N4 + p4] = o;
}

// 2x2 avg pool, 96 -> 48, packed-only output (channel pairs)
__global__ void poolpack_kernel(const float* __restrict__ X, uint4* __restrict__ Yp)
{
    const int NP   = C2 / 2;
    const int OHW4 = 48 * 48 / 4;      // 576
    int i = blockIdx.x * 256 + threadIdx.x;
    if (i >= Bn * NP * OHW4) return;
    int r  = i % OHW4;
    int pr = (i / OHW4) % NP;
    int b  = i / (OHW4 * NP);
    int y  = r / 12;
    int x8 = (r % 12) * 8;
    float pv[2][4];
    #pragma unroll
    for (int c = 0; c < 2; ++c) {
        const float* xp = X + ((size_t)b * C2 + 2 * pr + c) * HW;
        float4 r0a = *reinterpret_cast<const float4*>(xp + (2 * y) * Ww + x8);
        float4 r0b = *reinterpret_cast<const float4*>(xp + (2 * y) * Ww + x8 + 4);
        float4 r1a = *reinterpret_cast<const float4*>(xp + (2 * y + 1) * Ww + x8);
        float4 r1b = *reinterpret_cast<const float4*>(xp + (2 * y + 1) * Ww + x8 + 4);
        pv[c][0] = (r0a.x + r0a.y + r1a.x + r1a.y) * 0.25f;
        pv[c][1] = (r0a.z + r0a.w + r1a.z + r1a.w) * 0.25f;
        pv[c][2] = (r0b.x + r0b.y + r1b.x + r1b.y) * 0.25f;
        pv[c][3] = (r0b.z + r0b.w + r1b.z + r1b.w) * 0.25f;
    }
    uint4 o;
    o.x = pack_h2(pv[0][0], pv[1][0]);
    o.y = pack_h2(pv[0][1], pv[1][1]);
    o.z = pack_h2(pv[0][2], pv[1][2]);
    o.w = pack_h2(pv[0][3], pv[1][3]);
    Yp[((size_t)b * NP + pr) * OHW4 + r] = o;
}

// SCH = pack(SC * sigmoid(CAT + upsample(K2)))  (channel pairs, packed-only out)
__global__ void sigmulpack_kernel(const float* __restrict__ SC,
                                  const float* __restrict__ CAT,
                                  const float* __restrict__ K2,
                                  uint4* __restrict__ SCH)
{
    const int NP = C2 / 2;
    const int N4 = HW / 4;
    int i = blockIdx.x * 256 + threadIdx.x;
    if (i >= Bn * NP * N4) return;
    int p4 = i % N4;
    int pr = (i / N4) % NP;
    int b  = i / (N4 * NP);
    int p  = p4 * 4;
    int y  = p / Ww, x = p % Ww;
    int iy = (y * 46) / 96;
    int ix0 = ((x + 0) * 46) / 96;
    int ix1 = ((x + 1) * 46) / 96;
    int ix2 = ((x + 2) * 46) / 96;
    int ix3 = ((x + 3) * 46) / 96;
    float sv2[2][4];
    #pragma unroll
    for (int c = 0; c < 2; ++c) {
        size_t bc = (size_t)b * C2 + 2 * pr + c;
        const float* k2r = K2 + bc * (46 * 46) + iy * 46;
        float4 cv = reinterpret_cast<const float4*>(CAT + bc * HW)[p4];
        float4 sv = reinterpret_cast<const float4*>(SC + bc * HW)[p4];
        sv2[c][0] = sv.x / (1.f + expf(-(cv.x + k2r[ix0])));
        sv2[c][1] = sv.y / (1.f + expf(-(cv.y + k2r[ix1])));
        sv2[c][2] = sv.z / (1.f + expf(-(cv.z + k2r[ix2])));
        sv2[c][3] = sv.w / (1.f + expf(-(cv.w + k2r[ix3])));
    }
    uint4 o;
    o.x = pack_h2(sv2[0][0], sv2[1][0]);
    o.y = pack_h2(sv2[0][1], sv2[1][1]);
    o.z = pack_h2(sv2[0][2], sv2[1][2]);
    o.w = pack_h2(sv2[0][3], sv2[1][3]);
    SCH[((size_t)b * NP + pr) * N4 + p4] = o;
}

// ---------------------------------------------------------------------------
// fused deformable conv; writes packed half2 relu output directly.
// ---------------------------------------------------------------------------
__global__ __launch_bounds__(128)
void deform_kernel(const float* __restrict__ Q,
                   const float* __restrict__ OFF,
                   const float* __restrict__ W,
                   const float* __restrict__ Bias,
                   uint32_t* __restrict__ Yp)   // [B][Cc/2][HW]
{
    __shared__ float ws2[216 * 24];
    const int g = blockIdx.y;
    const int b = blockIdx.z;
    const int tid = threadIdx.x;

    for (int e = tid; e < 216 * 24; e += 128) {
        int it = e / 24;
        int o  = e - it * 24;
        ws2[e] = W[(size_t)(g * CG + o) * 216 + it];
    }
    __syncthreads();

    int p = blockIdx.x * 128 + tid;
    int y = p / Ww, x = p % Ww;
    const float* offb = OFF + (size_t)b * 18 * HW;

    float acc[24];
    #pragma unroll
    for (int o = 0; o < 24; ++o) acc[o] = Bias[g * CG + o];

    const float* qc = Q + ((size_t)b * C2 + g * CG) * HW;

    for (int t = 0; t < 9; ++t) {
        float dy = offb[(size_t)(2 * t) * HW + p];
        float dx = offb[(size_t)(2 * t + 1) * HW + p];
        float m  = 1.f / (1.f + expf(-offb[(size_t)t * HW + p]));
        float py = dy + (float)(y - 1 + t / 3);
        float px = dx + (float)(x - 1 + t % 3);
        float y0f = floorf(py), x0f = floorf(px);
        int   y0 = (int)y0f,    x0 = (int)x0f;
        float fy = py - y0f,    fx = px - x0f;
        float w00 = (1.f - fy) * (1.f - fx);
        float w01 = (1.f - fy) * fx;
        float w10 = fy * (1.f - fx);
        float w11 = fy * fx;
        bool vy0 = (y0 >= 0 && y0 <= Hh - 1), vy1 = (y0 + 1 >= 0 && y0 + 1 <= Hh - 1);
        bool vx0 = (x0 >= 0 && x0 <= Ww - 1), vx1 = (x0 + 1 >= 0 && x0 + 1 <= Ww - 1);
        int cy0 = min(max(y0, 0), Hh - 1),     cy1 = min(max(y0 + 1, 0), Hh - 1);
        int cx0 = min(max(x0, 0), Ww - 1),     cx1 = min(max(x0 + 1, 0), Ww - 1);
        int i00 = cy0 * Ww + cx0, i01 = cy0 * Ww + cx1;
        int i10 = cy1 * Ww + cx0, i11 = cy1 * Ww + cx1;
        w00 = (vy0 && vx0) ? w00 * m : 0.f;
        w01 = (vy0 && vx1) ? w01 * m : 0.f;
        w10 = (vy1 && vx0) ? w10 * m : 0.f;
        w11 = (vy1 && vx1) ? w11 * m : 0.f;

        #pragma unroll
        for (int i = 0; i < 24; ++i) {
            const float* qp = qc + (size_t)i * HW;
            float val = w00 * qp[i00] + w01 * qp[i01] + w10 * qp[i10] + w11 * qp[i11];
            const float* wr = &ws2[(i * 9 + t) * 24];
            #pragma unroll
            for (int o = 0; o < 24; ++o) acc[o] += val * wr[o];
        }
    }
    #pragma unroll
    for (int u = 0; u < 12; ++u) {
        uint32_t v = pack_h2(fmaxf(acc[2 * u], 0.f), fmaxf(acc[2 * u + 1], 0.f));
        Yp[((size_t)b * (Cc / 2) + g * 12 + u) * HW + p] = v;
    }
}

// ---------------------------------------------------------------------------
// row L2 norms (float4)
// ---------------------------------------------------------------------------
__global__ void rownorm_kernel(const float* __restrict__ QKV,
                               const float* __restrict__ Kb,
                               float* __restrict__ QN,
                               float* __restrict__ KN)
{
    int row   = blockIdx.x;
    int which = row / (Bn * Cc);
    row %= (Bn * Cc);
    int b = row / Cc, c = row % Cc;
    const float* src = which ? (Kb + ((size_t)b * Cc + c) * HW)
                             : (QKV + ((size_t)b * C2 + c) * HW);
    float s = 0.f;
    for (int n = threadIdx.x; n < HW / 4; n += 256) {
        float4 v = reinterpret_cast<const float4*>(src)[n];
        s += v.x * v.x + v.y * v.y + v.z * v.z + v.w * v.w;
    }
    __shared__ float sm[256];
    sm[threadIdx.x] = s;
    __syncthreads();
    for (int d = 128; d > 0; d >>= 1) {
        if (threadIdx.x < d) sm[threadIdx.x] += sm[threadIdx.x + d];
        __syncthreads();
    }
    if (threadIdx.x == 0) {
        float nrm = fmaxf(sqrtf(sm[0]), 1e-12f);
        (which ? KN : QN)[b * Cc + c] = nrm;
    }
}

// ---------------------------------------------------------------------------
// attention: one block per (b,h).  K-head staged through smem.
// ---------------------------------------------------------------------------
#define CNK 384
__global__ __launch_bounds__(256)
void attn2_kernel(const float* __restrict__ QKV,
                  const float* __restrict__ Kb,
                  const float* __restrict__ QN,
                  const float* __restrict__ KN,
                  const float* __restrict__ TEMP,
                  float* __restrict__ ATTN)
{
    __shared__ float ks_[24][CNK + 8];
    __shared__ float logits[24][24];

    const int b = blockIdx.x >> 3;
    const int h = blockIdx.x & 7;
    const int tid  = threadIdx.x;
    const int wid  = tid >> 5;
    const int lane = tid & 31;

    const float* qh = QKV + ((size_t)b * C2 + h * HD) * HW;
    const float* kh = Kb  + ((size_t)b * Cc + h * HD) * HW;

    float acc[3][24];
    #pragma unroll
    for (int r = 0; r < 3; ++r)
        #pragma unroll
        for (int j = 0; j < 24; ++j) acc[r][j] = 0.f;

    const float* q0p = qh + (size_t)(3 * wid + 0) * HW;
    const float* q1p = qh + (size_t)(3 * wid + 1) * HW;
    const float* q2p = qh + (size_t)(3 * wid + 2) * HW;

    for (int n0 = 0; n0 < HW; n0 += CNK) {
        __syncthreads();
        for (int e = tid; e < 24 * (CNK / 4); e += 256) {
            int j = e / (CNK / 4);
            int c = e - j * (CNK / 4);
            float4 v = *reinterpret_cast<const float4*>(kh + (size_t)j * HW + n0 + c * 4);
            ks_[j][c * 4 + 0] = v.x;
            ks_[j][c * 4 + 1] = v.y;
            ks_[j][c * 4 + 2] = v.z;
            ks_[j][c * 4 + 3] = v.w;
        }
        __syncthreads();

        for (int i = lane; i < CNK; i += 32) {
            int n = n0 + i;
            float q0 = q0p[n], q1 = q1p[n], q2 = q2p[n];
            #pragma unroll
            for (int j = 0; j < 24; ++j) {
                float kv = ks_[j][i];
                acc[0][j] += q0 * kv;
                acc[1][j] += q1 * kv;
                acc[2][j] += q2 * kv;
            }
        }
    }

    #pragma unroll
    for (int r = 0; r < 3; ++r)
        #pragma unroll
        for (int j = 0; j < 24; ++j) {
            float v = acc[r][j];
            for (int o = 16; o > 0; o >>= 1) v += __shfl_down_sync(0xffffffffu, v, o);
            if (lane == 0) logits[wid * 3 + r][j] = v;
        }
    __syncthreads();

    if (tid < 24) {
        int i = tid;
        float qn = QN[b * Cc + h * HD + i];
        float tp = TEMP[h];
        float s[24];
        float mx = -1e30f;
        #pragma unroll
        for (int j = 0; j < 24; ++j) {
            s[j] = logits[i][j] / (qn * KN[b * Cc + h * HD + j]) * tp;
            mx = fmaxf(mx, s[j]);
        }
        float sum = 0.f;
        #pragma unroll
        for (int j = 0; j < 24; ++j) { s[j] = expf(s[j] - mx); sum += s[j]; }
        float inv = 1.f / sum;
        #pragma unroll
        for (int j = 0; j < 24; ++j)
            ATTN[(((size_t)b * NH + h) * HD + i) * HD + j] = s[j] * inv;
    }
}

// out = attn @ v ; writes packed half2 directly (consumed only by proj conv)
__global__ void attnv_kernel(const float* __restrict__ ATTN,
                             const float* __restrict__ QKV,
                             uint32_t* __restrict__ AOp)   // [B][Cc/2][HW]
{
    int h = blockIdx.y, b = blockIdx.z;
    int n = blockIdx.x * 256 + threadIdx.x;
    __shared__ float a_s[HD * HD];
    for (int e = threadIdx.x; e < HD * HD; e += 256)
        a_s[e] = ATTN[((size_t)b * NH + h) * HD * HD + e];
    __syncthreads();
    const float* vb = QKV + ((size_t)b * C2 + Cc + h * HD) * HW;
    float acc[HD] = {};
    #pragma unroll
    for (int j = 0; j < HD; ++j) {
        float vv = vb[(size_t)j * HW + n];
        #pragma unroll
        for (int i = 0; i < HD; ++i) acc[i] += a_s[i * HD + j] * vv;
    }
    #pragma unroll
    for (int u = 0; u < HD / 2; ++u)
        AOp[((size_t)b * (Cc / 2) + h * (HD / 2) + u) * HW + n] =
            pack_h2(acc[2 * u], acc[2 * u + 1]);
}

// ---------------------------------------------------------------------------
// launcher
// ---------------------------------------------------------------------------
extern "C" void kernel_launch(void* const* d_in, const int* in_sizes, int n_in,
                              void* d_out, int out_size)
{
    const float* x           = (const float*)d_in[0];
    const float* y           = (const float*)d_in[1];
    const float* temperature = (const float*)d_in[2];
    const float* qkv_w       = (const float*)d_in[3];
    const float* qkv_conv_w  = (const float*)d_in[4];
    const float* proj_w      = (const float*)d_in[5];
    const float* k2_w        = (const float*)d_in[6];
    const float* k3_w        = (const float*)d_in[7];
    const float* k4_w        = (const float*)d_in[8];
    const float* deform_w    = (const float*)d_in[9];
    const float* deform_b    = (const float*)d_in[10];
    const float* pw_w        = (const float*)d_in[11];
    const float* pw_b        = (const float*)d_in[12];
    float* out = (float*)d_out;

    float* S = nullptr;
    cudaGetSymbolAddress((void**)&S, g_scratch);
    float* QKV1 = S + OFF_QKV1;
    float* QKV  = S + OFF_QKV;
    float* CAT  = S + OFF_CAT;
    float* SC   = S + OFF_SC;
    float* K2   = S + OFF_K2;
    float* OFFb = S + OFF_OFF;
    float* Kb   = S + OFF_K;
    float* QN   = S + OFF_QN;
    float* KN   = S + OFF_KN;
    float* ATTN = S + OFF_ATTN;
    float* WK3P = S + OFF_WK3P;
    float* WK2P = S + OFF_WK2P;
    float* WK4P = S + OFF_WK4P;
    uint32_t* XH    = (uint32_t*)(S + OFF_XH);
    uint32_t* CATH  = (uint32_t*)(S + OFF_CATH);
    uint32_t* POOLH = (uint32_t*)(S + OFF_POOLH);
    uint32_t* SCH   = (uint32_t*)(S + OFF_SCH);
    uint32_t* FEATH = (uint32_t*)(S + OFF_FEATH);
    uint32_t* AOH   = (uint32_t*)(S + OFF_AOH);

    // 0) weight permutes + pack x
    permw_kernel<<<(1327104 + 255) / 256, 256>>>(k3_w, WK3P, C2, C2);
    permw_kernel<<<(1327104 + 255) / 256, 256>>>(k2_w, WK2P, C2, C2);
    permw_kernel<<<(62208 + 255) / 256, 256>>>(k4_w, WK4P, 18, C2);
    halfpack4_kernel<<<(384 * 2304 + 255) / 256, 256>>>(x, (uint4*)XH, 384, 2304);

    // 1) qkv 1x1
    conv_mma<1, 4><<<dim3(HW / 128, C2 / 128, Bn), 256>>>(
        qkv_w, XH, QKV1, nullptr, C2, Cc, Hh, Ww, Hh, Ww, 0);
    // 2) grouped 3x3 (groups=192)
    dwconv2_kernel<<<dim3(9, 192, Bn), 256>>>(QKV1, qkv_conv_w, QKV);
    // 3) cat (fp32 + packed in one pass)
    catpack_kernel<<<(Bn * 192 * 2304 + 255) / 256, 256>>>(QKV, y, CAT, (uint4*)CATH);
    // 4) k3 conv 3x3 pad=1
    conv_mma<3, 4><<<dim3(HW / 128, C2 / 128, Bn), 256>>>(
        WK3P, CATH, SC, nullptr, C2, C2, Hh, Ww, Hh, Ww, 1);
    // 5) avg pool 2x2 (packed only)
    poolpack_kernel<<<(Bn * 192 * 576 + 255) / 256, 256>>>(CAT, (uint4*)POOLH);
    // 6) k2 conv 3x3 pad=0 : 48x48 -> 46x46
    conv_mma<3, 4><<<dim3((46 * 46 + 127) / 128, C2 / 128, Bn), 256>>>(
        WK2P, POOLH, K2, nullptr, C2, C2, 48, 48, 46, 46, 0);
    // 7) SCH = pack(SC * sigmoid(CAT + upsample(K2)))
    sigmulpack_kernel<<<(Bn * 192 * 2304 + 255) / 256, 256>>>(SC, CAT, K2, (uint4*)SCH);
    // 8) offset = conv3x3(sc, k4, pad=1), M=18
    conv_mma<3, 1><<<dim3(HW / 128, 1, Bn), 256>>>(
        WK4P, SCH, OFFb, nullptr, 18, C2, Hh, Ww, Hh, Ww, 1);
    // 9) deformable conv -> packed relu output
    deform_kernel<<<dim3(HW / 128, Gg, Bn), 128>>>(QKV, OFFb, deform_w, deform_b, FEATH);
    // 10) k = 1x1(FEAT) + pw_b
    conv_mma<1, 4><<<dim3(HW / 128, (Cc + 127) / 128, Bn), 256>>>(
        pw_w, FEATH, Kb, pw_b, Cc, Cc, Hh, Ww, Hh, Ww, 0);
    // 11) row norms
    rownorm_kernel<<<2 * Bn * Cc, 256>>>(QKV, Kb, QN, KN);
    // 12) attention logits + softmax
    attn2_kernel<<<Bn * NH, 256>>>(QKV, Kb, QN, KN, temperature, ATTN);
    // 13) out = attn @ v (packed output)
    attnv_kernel<<<dim3(HW / 256, NH, Bn), 256>>>(ATTN, QKV, AOH);
    // 14) final 1x1 proj -> d_out
    conv_mma<1, 4><<<dim3(HW / 128, (Cc + 127) / 128, Bn), 256>>>(
        proj_w, AOH, out, nullptr, Cc, Cc, Hh, Ww, Hh, Ww, 0);
}

// round 13
// speedup vs baseline: 2.2741x; 1.0257x over previous
#include <cuda_runtime.h>
#include <cuda_fp16.h>
#include <math.h>
#include <stdint.h>

// ---------------------------------------------------------------------------
// Problem constants
// ---------------------------------------------------------------------------
#define Bn   4
#define Cc   192
#define C2   384
#define Hh   96
#define Ww   96
#define HW   (Hh*Ww)          // 9216
#define NH   8
#define HD   24
#define Gg   8
#define CG   24

// scratch offsets (in floats / uint32 slots)
#define OFF_QKV1   0ul
#define OFF_QKV    14155776ul
#define OFF_CAT    28311552ul
#define OFF_SC     42467328ul
#define OFF_K2     56623104ul     // 3250176
#define OFF_OFF    59873280ul     // 663552
#define OFF_K      60536832ul     // 7077888
#define OFF_QN     67614720ul
#define OFF_KN     67615488ul
#define OFF_ATTN   67616256ul
#define OFF_WK3H   67634688ul     // 663552 (u32)
#define OFF_WK2H   68298240ul     // 663552
#define OFF_WK4H   68961792ul     // 31104
#define OFF_WQKVH  68992896ul     // 36864
#define OFF_WPWH   69029760ul     // 18432
#define OFF_WPROJH 69048192ul     // 18432
#define OFF_XH     69066624ul     // 3538944
#define OFF_CATH   72605568ul     // 7077888
#define OFF_POOLH  79683456ul     // 1769472
#define OFF_SCH    81452928ul     // 7077888
#define OFF_FEATH  88530816ul     // 3538944
#define OFF_AOH    92069760ul     // 3538944
#define SCRATCH_TOTAL 95608704ul

__device__ float g_scratch[SCRATCH_TOTAL];

// ---------------------------------------------------------------------------
// helpers
// ---------------------------------------------------------------------------
__device__ __forceinline__ uint32_t pack_h2(float lo, float hi) {
    __half2 h = __floats2half2_rn(lo, hi);
    return *reinterpret_cast<uint32_t*>(&h);
}

__device__ __forceinline__ void mma_16x8x16(float* c, const uint32_t* a,
                                            uint32_t b0, uint32_t b1) {
    asm volatile(
        "mma.sync.aligned.m16n8k16.row.col.f32.f16.f16.f32 "
        "{%0,%1,%2,%3}, {%4,%5,%6,%7}, {%8,%9}, {%0,%1,%2,%3};\n"
        : "+f"(c[0]), "+f"(c[1]), "+f"(c[2]), "+f"(c[3])
        : "r"(a[0]), "r"(a[1]), "r"(a[2]), "r"(a[3]), "r"(b0), "r"(b1));
}

__device__ __forceinline__ void cpasync4(uint32_t saddr, const void* g, bool pred) {
    int sz = pred ? 4 : 0;
    asm volatile("cp.async.ca.shared.global [%0], [%1], 4, %2;\n"
                 :: "r"(saddr), "l"(g), "r"(sz));
}
__device__ __forceinline__ void cpasync16(uint32_t saddr, const void* g) {
    asm volatile("cp.async.cg.shared.global [%0], [%1], 16;\n"
                 :: "r"(saddr), "l"(g));
}
// .ca variant: keeps L1 residency (weights are block-reused)
__device__ __forceinline__ void cpasync16ca(uint32_t saddr, const void* g, bool pred) {
    int sz = pred ? 16 : 0;
    asm volatile("cp.async.ca.shared.global [%0], [%1], 16, %2;\n"
                 :: "r"(saddr), "l"(g), "r"(sz));
}
#define CP_COMMIT() asm volatile("cp.async.commit_group;\n" ::: "memory")
#define CP_WAIT0()  asm volatile("cp.async.wait_group 0;\n" ::: "memory")

// ---------------------------------------------------------------------------
// 3x3 weights: permute to tap-major K AND pack half2 K-pairs.
// Wph[m][r] = half2(W[m][2r'] , W[m][2r'+1]) in tap-major order; r = t*(Cin/2)+ic/2.
// ---------------------------------------------------------------------------
__global__ void permpack3_kernel(const float* __restrict__ W,
                                 uint32_t* __restrict__ Wph, int M, int Cin)
{
    int K2 = Cin * 9 / 2;
    int i = blockIdx.x * 256 + threadIdx.x;
    if (i >= M * K2) return;
    int m = i / K2;
    int r = i - m * K2;
    int t  = r / (Cin / 2);
    int ic = 2 * (r - t * (Cin / 2));
    float lo = W[(size_t)m * Cin * 9 + ic * 9 + t];
    float hi = W[(size_t)m * Cin * 9 + (ic + 1) * 9 + t];
    Wph[i] = pack_h2(lo, hi);
}

// 1x1 weights: pack half2 K-pairs. Wph[m][kp] = half2(W[m][2kp], W[m][2kp+1])
__global__ void packw1_kernel(const float* __restrict__ W,
                              uint32_t* __restrict__ Wph, int M, int K)
{
    int K2 = K / 2;
    int i = blockIdx.x * 256 + threadIdx.x;
    if (i >= M * K2) return;
    int m = i / K2;
    int kp = i - m * K2;
    Wph[i] = pack_h2(W[(size_t)m * K + 2 * kp], W[(size_t)m * K + 2 * kp + 1]);
}

// fp32 [2P][4*N4] -> half2 channel-pair packed (external input x only)
__global__ void halfpack4_kernel(const float* __restrict__ X,
                                 uint4* __restrict__ Xp, int P, int N4)
{
    int i = blockIdx.x * 256 + threadIdx.x;
    if (i >= P * N4) return;
    int pr = i / N4, n4 = i - pr * N4;
    float4 a = reinterpret_cast<const float4*>(X)[(size_t)(2 * pr) * N4 + n4];
    float4 b = reinterpret_cast<const float4*>(X)[(size_t)(2 * pr + 1) * N4 + n4];
    uint4 o;
    o.x = pack_h2(a.x, b.x);
    o.y = pack_h2(a.y, b.y);
    o.z = pack_h2(a.z, b.z);
    o.w = pack_h2(a.w, b.w);
    Xp[i] = o;
}

// ---------------------------------------------------------------------------
// fp16 tensor-core implicit-GEMM conv. BOTH operands pre-packed half2 K-pairs.
// A: cp.async.ca 16B into smem [m][12] (8 kpairs + 4 pad; frag banks 12*lg+lt
//    all distinct mod 32). No register staging, no STS, no in-loop converts.
// B: cp.async [kpair(8)][136]; fragments direct LDS.32.
// mma.m16n8k16 f16. KS==3 requires Cin % 16 == 0; KS==1 requires N % 128 == 0.
// K parameter is in ELEMENTS (weights row length = K/2 uint32).
// ---------------------------------------------------------------------------
template<int KS, int FM>
__global__ __launch_bounds__(256)
void conv_mma(const uint32_t* __restrict__ Wph,
              const uint32_t* __restrict__ Xp,
              float* __restrict__ Y,
              const float* __restrict__ bias,
              int M, int Cin, int IH, int IW,
              int OH, int OW, int pad)
{
    constexpr int BM    = 32 * FM;
    constexpr int BK    = 16;
    constexpr int ASTR  = 12;               // u32 per m row (8 kpairs + 4 pad)
    constexpr int B2STR = 136;
    constexpr int ACP   = BM * 2;           // 16B copies per A tile (2 per m row)

    __shared__ uint32_t As2[2][BM * ASTR];
    __shared__ uint32_t Bs2[2][8 * B2STR];

    const int N   = OH * OW;
    const int K   = Cin * KS * KS;
    const int K2  = K >> 1;
    const int IHW = IH * IW;
    const int bz  = blockIdx.z;
    const int m0  = blockIdx.y * BM;
    const int n0  = blockIdx.x * 128;

    const int tid  = threadIdx.x;
    const int wid  = tid >> 5;
    const int lane = tid & 31;
    const int wm   = wid & 1;
    const int wn   = wid >> 1;
    const int mbase = wm * (16 * FM);
    const int nbase = wn * 32;
    const int lg = lane >> 2;
    const int lt = lane & 3;

    const uint32_t* Xb = Xp + (size_t)bz * (Cin >> 1) * IHW;

    float acc[FM][4][4];
    #pragma unroll
    for (int f = 0; f < FM; ++f)
        #pragma unroll
        for (int nf = 0; nf < 4; ++nf)
            #pragma unroll
            for (int r = 0; r < 4; ++r) acc[f][nf][r] = 0.f;

    const int bn = tid & 127;
    const int gn = n0 + bn;
    const bool nvalid = gn < N;
    int oy = 0, ox = 0;
    if (KS == 3) { int g = nvalid ? gn : 0; oy = g / OW; ox = g - oy * OW; }

    // A copy coords (fixed per thread): thread handles (m = tid>>1, half = tid&1)
    const int am = tid >> 1;
    const int ah = tid & 1;
    const bool avalid = (ACP == 512) || (tid < ACP);
    const int gm_a = m0 + am;

    auto issueA = [&](int k0, int buf) {
        if (avalid) {
            uint32_t s = (uint32_t)__cvta_generic_to_shared(
                &As2[buf][am * ASTR + ah * 4]);
            cpasync16ca(s, Wph + (size_t)gm_a * K2 + (k0 >> 1) + ah * 4, gm_a < M);
        }
    };
    auto issueB = [&](int k0, int buf) {
        if (KS == 1) {
            int row = tid >> 5;
            int c4  = (tid & 31) * 4;
            uint32_t s = (uint32_t)__cvta_generic_to_shared(&Bs2[buf][row * B2STR + c4]);
            cpasync16(s, Xb + (size_t)((k0 >> 1) + row) * N + n0 + c4);
        } else {
            int tp  = k0 / Cin;
            int icb = k0 - tp * Cin;
            int tdy = (tp >= 6) ? 2 : ((tp >= 3) ? 1 : 0);
            int tdx = tp - 3 * tdy;
            int iy  = oy + tdy - pad;
            int ix  = ox + tdx - pad;
            bool ok = nvalid && iy >= 0 && iy < IH && ix >= 0 && ix < IW;
            const uint32_t* base = Xb + (size_t)(icb >> 1) * IHW + iy * IW + ix;
            #pragma unroll
            for (int r = 0; r < 4; ++r) {
                int kp = (tid >> 7) + 2 * r;
                uint32_t s = (uint32_t)__cvta_generic_to_shared(&Bs2[buf][kp * B2STR + bn]);
                cpasync4(s, base + (size_t)kp * IHW, ok);
            }
        }
    };
    auto compute = [&](int buf) {
        uint32_t a[FM][4];
        #pragma unroll
        for (int f = 0; f < FM; ++f) {
            int mr = mbase + f * 16 + lg;
            a[f][0] = As2[buf][mr * ASTR + lt];
            a[f][1] = As2[buf][(mr + 8) * ASTR + lt];
            a[f][2] = As2[buf][mr * ASTR + lt + 4];
            a[f][3] = As2[buf][(mr + 8) * ASTR + lt + 4];
        }
        #pragma unroll
        for (int nf = 0; nf < 4; ++nf) {
            int nc = nbase + nf * 8 + lg;
            uint32_t b0 = Bs2[buf][lt * B2STR + nc];
            uint32_t b1 = Bs2[buf][(lt + 4) * B2STR + nc];
            #pragma unroll
            for (int f = 0; f < FM; ++f)
                mma_16x8x16(acc[f][nf], a[f], b0, b1);
        }
    };

    const int kTiles = K / BK;
    issueA(0, 0); issueB(0, 0); CP_COMMIT();
    CP_WAIT0(); __syncthreads();

    for (int t = 0; t < kTiles; ++t) {
        if (t + 1 < kTiles) {
            issueA((t + 1) * BK, (t + 1) & 1);
            issueB((t + 1) * BK, (t + 1) & 1);
            CP_COMMIT();
        }
        compute(t & 1);
        if (t + 1 < kTiles) {
            CP_WAIT0(); __syncthreads();
        }
    }

    // ---- epilogue ----
    #pragma unroll
    for (int f = 0; f < FM; ++f) {
        int r0 = m0 + mbase + f * 16 + lg;
        #pragma unroll
        for (int nf = 0; nf < 4; ++nf) {
            int cb = n0 + nbase + nf * 8 + 2 * lt;
            #pragma unroll
            for (int rr = 0; rr < 2; ++rr) {
                int m = r0 + rr * 8;
                if (m >= M) continue;
                float bval = bias ? bias[m] : 0.f;
                #pragma unroll
                for (int cc = 0; cc < 2; ++cc) {
                    int n = cb + cc;
                    if (n >= N) continue;
                    Y[((size_t)bz * M + m) * N + n] = acc[f][nf][rr * 2 + cc] + bval;
                }
            }
        }
    }
}

// ---------------------------------------------------------------------------
// grouped 3x3 conv, smem-tiled
// ---------------------------------------------------------------------------
__global__ __launch_bounds__(256)
void dwconv2_kernel(const float* __restrict__ X,
                    const float* __restrict__ W,
                    float* __restrict__ Y)
{
    __shared__ float xs[2][34][35];
    __shared__ float ws[36];

    const int tile = blockIdx.x;
    const int g    = blockIdx.y;
    const int b    = blockIdx.z;
    const int ty0  = (tile / 3) * 32;
    const int tx0  = (tile % 3) * 32;
    const int tid  = threadIdx.x;

    if (tid < 36) ws[tid] = W[(size_t)g * 36 + tid];

    for (int e = tid; e < 2 * 34 * 34; e += 256) {
        int c  = e / (34 * 34);
        int r  = e - c * 34 * 34;
        int yy = r / 34, xx = r - yy * 34;
        int gy = ty0 + yy - 1, gx = tx0 + xx - 1;
        float v = 0.f;
        if (gy >= 0 && gy < Hh && gx >= 0 && gx < Ww)
            v = X[((size_t)b * C2 + 2 * g + c) * HW + gy * Ww + gx];
        xs[c][yy][xx] = v;
    }
    __syncthreads();

    const int x  = tid & 31;
    const int yb = (tid >> 5) * 4;
    #pragma unroll
    for (int j = 0; j < 4; ++j) {
        int y = yb + j;
        float a0 = 0.f, a1 = 0.f;
        #pragma unroll
        for (int c = 0; c < 2; ++c)
            #pragma unroll
            for (int ky = 0; ky < 3; ++ky)
                #pragma unroll
                for (int kx = 0; kx < 3; ++kx) {
                    float v = xs[c][y + ky][x + kx];
                    a0 += v * ws[c * 9 + ky * 3 + kx];
                    a1 += v * ws[18 + c * 9 + ky * 3 + kx];
                }
        size_t o = ((size_t)b * C2 + 2 * g) * HW + (ty0 + y) * Ww + tx0 + x;
        Y[o]      = a0;
        Y[o + HW] = a1;
    }
}

// cat: channel-pair thread; writes CAT fp32 + CATH packed in one pass.
__global__ void catpack_kernel(const float* __restrict__ QKV,
                               const float* __restrict__ Yin,
                               float* __restrict__ CAT,
                               uint4* __restrict__ CATH)
{
    const int NP = C2 / 2;
    const int N4 = HW / 4;
    int i = blockIdx.x * 256 + threadIdx.x;
    if (i >= Bn * NP * N4) return;
    int p4 = i % N4;
    int pr = (i / N4) % NP;
    int b  = i / (N4 * NP);
    int c0 = 2 * pr;
    float4 a, bv;
    if (c0 < Cc) {
        a  = reinterpret_cast<const float4*>(QKV + ((size_t)b * C2 + c0) * HW)[p4];
        bv = reinterpret_cast<const float4*>(QKV + ((size_t)b * C2 + c0 + 1) * HW)[p4];
    } else {
        a  = reinterpret_cast<const float4*>(Yin + ((size_t)b * Cc + (c0 - Cc)) * HW)[p4];
        bv = reinterpret_cast<const float4*>(Yin + ((size_t)b * Cc + (c0 - Cc) + 1) * HW)[p4];
    }
    reinterpret_cast<float4*>(CAT + ((size_t)b * C2 + c0) * HW)[p4]     = a;
    reinterpret_cast<float4*>(CAT + ((size_t)b * C2 + c0 + 1) * HW)[p4] = bv;
    uint4 o;
    o.x = pack_h2(a.x, bv.x);
    o.y = pack_h2(a.y, bv.y);
    o.z = pack_h2(a.z, bv.z);
    o.w = pack_h2(a.w, bv.w);
    CATH[((size_t)b * NP + pr) * N4 + p4] = o;
}

// 2x2 avg pool, packed-only output
__global__ void poolpack_kernel(const float* __restrict__ X, uint4* __restrict__ Yp)
{
    const int NP   = C2 / 2;
    const int OHW4 = 48 * 48 / 4;
    int i = blockIdx.x * 256 + threadIdx.x;
    if (i >= Bn * NP * OHW4) return;
    int r  = i % OHW4;
    int pr = (i / OHW4) % NP;
    int b  = i / (OHW4 * NP);
    int y  = r / 12;
    int x8 = (r % 12) * 8;
    float pv[2][4];
    #pragma unroll
    for (int c = 0; c < 2; ++c) {
        const float* xp = X + ((size_t)b * C2 + 2 * pr + c) * HW;
        float4 r0a = *reinterpret_cast<const float4*>(xp + (2 * y) * Ww + x8);
        float4 r0b = *reinterpret_cast<const float4*>(xp + (2 * y) * Ww + x8 + 4);
        float4 r1a = *reinterpret_cast<const float4*>(xp + (2 * y + 1) * Ww + x8);
        float4 r1b = *reinterpret_cast<const float4*>(xp + (2 * y + 1) * Ww + x8 + 4);
        pv[c][0] = (r0a.x + r0a.y + r1a.x + r1a.y) * 0.25f;
        pv[c][1] = (r0a.z + r0a.w + r1a.z + r1a.w) * 0.25f;
        pv[c][2] = (r0b.x + r0b.y + r1b.x + r1b.y) * 0.25f;
        pv[c][3] = (r0b.z + r0b.w + r1b.z + r1b.w) * 0.25f;
    }
    uint4 o;
    o.x = pack_h2(pv[0][0], pv[1][0]);
    o.y = pack_h2(pv[0][1], pv[1][1]);
    o.z = pack_h2(pv[0][2], pv[1][2]);
    o.w = pack_h2(pv[0][3], pv[1][3]);
    Yp[((size_t)b * NP + pr) * OHW4 + r] = o;
}

// SCH = pack(SC * sigmoid(CAT + upsample(K2)))
__global__ void sigmulpack_kernel(const float* __restrict__ SC,
                                  const float* __restrict__ CAT,
                                  const float* __restrict__ K2,
                                  uint4* __restrict__ SCH)
{
    const int NP = C2 / 2;
    const int N4 = HW / 4;
    int i = blockIdx.x * 256 + threadIdx.x;
    if (i >= Bn * NP * N4) return;
    int p4 = i % N4;
    int pr = (i / N4) % NP;
    int b  = i / (N4 * NP);
    int p  = p4 * 4;
    int y  = p / Ww, x = p % Ww;
    int iy = (y * 46) / 96;
    int ix0 = ((x + 0) * 46) / 96;
    int ix1 = ((x + 1) * 46) / 96;
    int ix2 = ((x + 2) * 46) / 96;
    int ix3 = ((x + 3) * 46) / 96;
    float sv2[2][4];
    #pragma unroll
    for (int c = 0; c < 2; ++c) {
        size_t bc = (size_t)b * C2 + 2 * pr + c;
        const float* k2r = K2 + bc * (46 * 46) + iy * 46;
        float4 cv = reinterpret_cast<const float4*>(CAT + bc * HW)[p4];
        float4 sv = reinterpret_cast<const float4*>(SC + bc * HW)[p4];
        sv2[c][0] = sv.x / (1.f + expf(-(cv.x + k2r[ix0])));
        sv2[c][1] = sv.y / (1.f + expf(-(cv.y + k2r[ix1])));
        sv2[c][2] = sv.z / (1.f + expf(-(cv.z + k2r[ix2])));
        sv2[c][3] = sv.w / (1.f + expf(-(cv.w + k2r[ix3])));
    }
    uint4 o;
    o.x = pack_h2(sv2[0][0], sv2[1][0]);
    o.y = pack_h2(sv2[0][1], sv2[1][1]);
    o.z = pack_h2(sv2[0][2], sv2[1][2]);
    o.w = pack_h2(sv2[0][3], sv2[1][3]);
    SCH[((size_t)b * NP + pr) * N4 + p4] = o;
}

// ---------------------------------------------------------------------------
// fused deformable conv; writes packed half2 relu output directly.
// ---------------------------------------------------------------------------
__global__ __launch_bounds__(128)
void deform_kernel(const float* __restrict__ Q,
                   const float* __restrict__ OFF,
                   const float* __restrict__ W,
                   const float* __restrict__ Bias,
                   uint32_t* __restrict__ Yp)
{
    __shared__ float ws2[216 * 24];
    const int g = blockIdx.y;
    const int b = blockIdx.z;
    const int tid = threadIdx.x;

    for (int e = tid; e < 216 * 24; e += 128) {
        int it = e / 24;
        int o  = e - it * 24;
        ws2[e] = W[(size_t)(g * CG + o) * 216 + it];
    }
    __syncthreads();

    int p = blockIdx.x * 128 + tid;
    int y = p / Ww, x = p % Ww;
    const float* offb = OFF + (size_t)b * 18 * HW;

    float acc[24];
    #pragma unroll
    for (int o = 0; o < 24; ++o) acc[o] = Bias[g * CG + o];

    const float* qc = Q + ((size_t)b * C2 + g * CG) * HW;

    for (int t = 0; t < 9; ++t) {
        float dy = offb[(size_t)(2 * t) * HW + p];
        float dx = offb[(size_t)(2 * t + 1) * HW + p];
        float m  = 1.f / (1.f + expf(-offb[(size_t)t * HW + p]));
        float py = dy + (float)(y - 1 + t / 3);
        float px = dx + (float)(x - 1 + t % 3);
        float y0f = floorf(py), x0f = floorf(px);
        int   y0 = (int)y0f,    x0 = (int)x0f;
        float fy = py - y0f,    fx = px - x0f;
        float w00 = (1.f - fy) * (1.f - fx);
        float w01 = (1.f - fy) * fx;
        float w10 = fy * (1.f - fx);
        float w11 = fy * fx;
        bool vy0 = (y0 >= 0 && y0 <= Hh - 1), vy1 = (y0 + 1 >= 0 && y0 + 1 <= Hh - 1);
        bool vx0 = (x0 >= 0 && x0 <= Ww - 1), vx1 = (x0 + 1 >= 0 && x0 + 1 <= Ww - 1);
        int cy0 = min(max(y0, 0), Hh - 1),     cy1 = min(max(y0 + 1, 0), Hh - 1);
        int cx0 = min(max(x0, 0), Ww - 1),     cx1 = min(max(x0 + 1, 0), Ww - 1);
        int i00 = cy0 * Ww + cx0, i01 = cy0 * Ww + cx1;
        int i10 = cy1 * Ww + cx0, i11 = cy1 * Ww + cx1;
        w00 = (vy0 && vx0) ? w00 * m : 0.f;
        w01 = (vy0 && vx1) ? w01 * m : 0.f;
        w10 = (vy1 && vx0) ? w10 * m : 0.f;
        w11 = (vy1 && vx1) ? w11 * m : 0.f;

        #pragma unroll
        for (int i = 0; i < 24; ++i) {
            const float* qp = qc + (size_t)i * HW;
            float val = w00 * qp[i00] + w01 * qp[i01] + w10 * qp[i10] + w11 * qp[i11];
            const float* wr = &ws2[(i * 9 + t) * 24];
            #pragma unroll
            for (int o = 0; o < 24; ++o) acc[o] += val * wr[o];
        }
    }
    #pragma unroll
    for (int u = 0; u < 12; ++u) {
        uint32_t v = pack_h2(fmaxf(acc[2 * u], 0.f), fmaxf(acc[2 * u + 1], 0.f));
        Yp[((size_t)b * (Cc / 2) + g * 12 + u) * HW + p] = v;
    }
}

// ---------------------------------------------------------------------------
// row L2 norms (float4)
// ---------------------------------------------------------------------------
__global__ void rownorm_kernel(const float* __restrict__ QKV,
                               const float* __restrict__ Kb,
                               float* __restrict__ QN,
                               float* __restrict__ KN)
{
    int row   = blockIdx.x;
    int which = row / (Bn * Cc);
    row %= (Bn * Cc);
    int b = row / Cc, c = row % Cc;
    const float* src = which ? (Kb + ((size_t)b * Cc + c) * HW)
                             : (QKV + ((size_t)b * C2 + c) * HW);
    float s = 0.f;
    for (int n = threadIdx.x; n < HW / 4; n += 256) {
        float4 v = reinterpret_cast<const float4*>(src)[n];
        s += v.x * v.x + v.y * v.y + v.z * v.z + v.w * v.w;
    }
    __shared__ float sm[256];
    sm[threadIdx.x] = s;
    __syncthreads();
    for (int d = 128; d > 0; d >>= 1) {
        if (threadIdx.x < d) sm[threadIdx.x] += sm[threadIdx.x + d];
        __syncthreads();
    }
    if (threadIdx.x == 0) {
        float nrm = fmaxf(sqrtf(sm[0]), 1e-12f);
        (which ? KN : QN)[b * Cc + c] = nrm;
    }
}

// ---------------------------------------------------------------------------
// attention: one block per (b,h).  K-head staged through smem.
// ---------------------------------------------------------------------------
#define CNK 384
__global__ __launch_bounds__(256)
void attn2_kernel(const float* __restrict__ QKV,
                  const float* __restrict__ Kb,
                  const float* __restrict__ QN,
                  const float* __restrict__ KN,
                  const float* __restrict__ TEMP,
                  float* __restrict__ ATTN)
{
    __shared__ float ks_[24][CNK + 8];
    __shared__ float logits[24][24];

    const int b = blockIdx.x >> 3;
    const int h = blockIdx.x & 7;
    const int tid  = threadIdx.x;
    const int wid  = tid >> 5;
    const int lane = tid & 31;

    const float* qh = QKV + ((size_t)b * C2 + h * HD) * HW;
    const float* kh = Kb  + ((size_t)b * Cc + h * HD) * HW;

    float acc[3][24];
    #pragma unroll
    for (int r = 0; r < 3; ++r)
        #pragma unroll
        for (int j = 0; j < 24; ++j) acc[r][j] = 0.f;

    const float* q0p = qh + (size_t)(3 * wid + 0) * HW;
    const float* q1p = qh + (size_t)(3 * wid + 1) * HW;
    const float* q2p = qh + (size_t)(3 * wid + 2) * HW;

    for (int n0 = 0; n0 < HW; n0 += CNK) {
        __syncthreads();
        for (int e = tid; e < 24 * (CNK / 4); e += 256) {
            int j = e / (CNK / 4);
            int c = e - j * (CNK / 4);
            float4 v = *reinterpret_cast<const float4*>(kh + (size_t)j * HW + n0 + c * 4);
            ks_[j][c * 4 + 0] = v.x;
            ks_[j][c * 4 + 1] = v.y;
            ks_[j][c * 4 + 2] = v.z;
            ks_[j][c * 4 + 3] = v.w;
        }
        __syncthreads();

        for (int i = lane; i < CNK; i += 32) {
            int n = n0 + i;
            float q0 = q0p[n], q1 = q1p[n], q2 = q2p[n];
            #pragma unroll
            for (int j = 0; j < 24; ++j) {
                float kv = ks_[j][i];
                acc[0][j] += q0 * kv;
                acc[1][j] += q1 * kv;
                acc[2][j] += q2 * kv;
            }
        }
    }

    #pragma unroll
    for (int r = 0; r < 3; ++r)
        #pragma unroll
        for (int j = 0; j < 24; ++j) {
            float v = acc[r][j];
            for (int o = 16; o > 0; o >>= 1) v += __shfl_down_sync(0xffffffffu, v, o);
            if (lane == 0) logits[wid * 3 + r][j] = v;
        }
    __syncthreads();

    if (tid < 24) {
        int i = tid;
        float qn = QN[b * Cc + h * HD + i];
        float tp = TEMP[h];
        float s[24];
        float mx = -1e30f;
        #pragma unroll
        for (int j = 0; j < 24; ++j) {
            s[j] = logits[i][j] / (qn * KN[b * Cc + h * HD + j]) * tp;
            mx = fmaxf(mx, s[j]);
        }
        float sum = 0.f;
        #pragma unroll
        for (int j = 0; j < 24; ++j) { s[j] = expf(s[j] - mx); sum += s[j]; }
        float inv = 1.f / sum;
        #pragma unroll
        for (int j = 0; j < 24; ++j)
            ATTN[(((size_t)b * NH + h) * HD + i) * HD + j] = s[j] * inv;
    }
}

// out = attn @ v ; writes packed half2 directly
__global__ void attnv_kernel(const float* __restrict__ ATTN,
                             const float* __restrict__ QKV,
                             uint32_t* __restrict__ AOp)
{
    int h = blockIdx.y, b = blockIdx.z;
    int n = blockIdx.x * 256 + threadIdx.x;
    __shared__ float a_s[HD * HD];
    for (int e = threadIdx.x; e < HD * HD; e += 256)
        a_s[e] = ATTN[((size_t)b * NH + h) * HD * HD + e];
    __syncthreads();
    const float* vb = QKV + ((size_t)b * C2 + Cc + h * HD) * HW;
    float acc[HD] = {};
    #pragma unroll
    for (int j = 0; j < HD; ++j) {
        float vv = vb[(size_t)j * HW + n];
        #pragma unroll
        for (int i = 0; i < HD; ++i) acc[i] += a_s[i * HD + j] * vv;
    }
    #pragma unroll
    for (int u = 0; u < HD / 2; ++u)
        AOp[((size_t)b * (Cc / 2) + h * (HD / 2) + u) * HW + n] =
            pack_h2(acc[2 * u], acc[2 * u + 1]);
}

// ---------------------------------------------------------------------------
// launcher
// ---------------------------------------------------------------------------
extern "C" void kernel_launch(void* const* d_in, const int* in_sizes, int n_in,
                              void* d_out, int out_size)
{
    const float* x           = (const float*)d_in[0];
    const float* y           = (const float*)d_in[1];
    const float* temperature = (const float*)d_in[2];
    const float* qkv_w       = (const float*)d_in[3];
    const float* qkv_conv_w  = (const float*)d_in[4];
    const float* proj_w      = (const float*)d_in[5];
    const float* k2_w        = (const float*)d_in[6];
    const float* k3_w        = (const float*)d_in[7];
    const float* k4_w        = (const float*)d_in[8];
    const float* deform_w    = (const float*)d_in[9];
    const float* deform_b    = (const float*)d_in[10];
    const float* pw_w        = (const float*)d_in[11];
    const float* pw_b        = (const float*)d_in[12];
    float* out = (float*)d_out;

    float* S = nullptr;
    cudaGetSymbolAddress((void**)&S, g_scratch);
    float* QKV1 = S + OFF_QKV1;
    float* QKV  = S + OFF_QKV;
    float* CAT  = S + OFF_CAT;
    float* SC   = S + OFF_SC;
    float* K2   = S + OFF_K2;
    float* OFFb = S + OFF_OFF;
    float* Kb   = S + OFF_K;
    float* QN   = S + OFF_QN;
    float* KN   = S + OFF_KN;
    float* ATTN = S + OFF_ATTN;
    uint32_t* WK3H   = (uint32_t*)(S + OFF_WK3H);
    uint32_t* WK2H   = (uint32_t*)(S + OFF_WK2H);
    uint32_t* WK4H   = (uint32_t*)(S + OFF_WK4H);
    uint32_t* WQKVH  = (uint32_t*)(S + OFF_WQKVH);
    uint32_t* WPWH   = (uint32_t*)(S + OFF_WPWH);
    uint32_t* WPROJH = (uint32_t*)(S + OFF_WPROJH);
    uint32_t* XH    = (uint32_t*)(S + OFF_XH);
    uint32_t* CATH  = (uint32_t*)(S + OFF_CATH);
    uint32_t* POOLH = (uint32_t*)(S + OFF_POOLH);
    uint32_t* SCH   = (uint32_t*)(S + OFF_SCH);
    uint32_t* FEATH = (uint32_t*)(S + OFF_FEATH);
    uint32_t* AOH   = (uint32_t*)(S + OFF_AOH);

    // 0) weight permute+pack, 1x1 weight pack, pack x
    permpack3_kernel<<<(663552 + 255) / 256, 256>>>(k3_w, WK3H, C2, C2);
    permpack3_kernel<<<(663552 + 255) / 256, 256>>>(k2_w, WK2H, C2, C2);
    permpack3_kernel<<<(31104 + 255) / 256, 256>>>(k4_w, WK4H, 18, C2);
    packw1_kernel<<<(36864 + 255) / 256, 256>>>(qkv_w, WQKVH, C2, Cc);
    packw1_kernel<<<(18432 + 255) / 256, 256>>>(pw_w, WPWH, Cc, Cc);
    packw1_kernel<<<(18432 + 255) / 256, 256>>>(proj_w, WPROJH, Cc, Cc);
    halfpack4_kernel<<<(384 * 2304 + 255) / 256, 256>>>(x, (uint4*)XH, 384, 2304);

    // 1) qkv 1x1
    conv_mma<1, 4><<<dim3(HW / 128, C2 / 128, Bn), 256>>>(
        WQKVH, XH, QKV1, nullptr, C2, Cc, Hh, Ww, Hh, Ww, 0);
    // 2) grouped 3x3 (groups=192)
    dwconv2_kernel<<<dim3(9, 192, Bn), 256>>>(QKV1, qkv_conv_w, QKV);
    // 3) cat (fp32 + packed in one pass)
    catpack_kernel<<<(Bn * 192 * 2304 + 255) / 256, 256>>>(QKV, y, CAT, (uint4*)CATH);
    // 4) k3 conv 3x3 pad=1
    conv_mma<3, 4><<<dim3(HW / 128, C2 / 128, Bn), 256>>>(
        WK3H, CATH, SC, nullptr, C2, C2, Hh, Ww, Hh, Ww, 1);
    // 5) avg pool 2x2 (packed only)
    poolpack_kernel<<<(Bn * 192 * 576 + 255) / 256, 256>>>(CAT, (uint4*)POOLH);
    // 6) k2 conv 3x3 pad=0 : 48x48 -> 46x46
    conv_mma<3, 4><<<dim3((46 * 46 + 127) / 128, C2 / 128, Bn), 256>>>(
        WK2H, POOLH, K2, nullptr, C2, C2, 48, 48, 46, 46, 0);
    // 7) SCH = pack(SC * sigmoid(CAT + upsample(K2)))
    sigmulpack_kernel<<<(Bn * 192 * 2304 + 255) / 256, 256>>>(SC, CAT, K2, (uint4*)SCH);
    // 8) offset = conv3x3(sc, k4, pad=1), M=18
    conv_mma<3, 1><<<dim3(HW / 128, 1, Bn), 256>>>(
        WK4H, SCH, OFFb, nullptr, 18, C2, Hh, Ww, Hh, Ww, 1);
    // 9) deformable conv -> packed relu output
    deform_kernel<<<dim3(HW / 128, Gg, Bn), 128>>>(QKV, OFFb, deform_w, deform_b, FEATH);
    // 10) k = 1x1(FEAT) + pw_b
    conv_mma<1, 4><<<dim3(HW / 128, (Cc + 127) / 128, Bn), 256>>>(
        WPWH, FEATH, Kb, pw_b, Cc, Cc, Hh, Ww, Hh, Ww, 0);
    // 11) row norms
    rownorm_kernel<<<2 * Bn * Cc, 256>>>(QKV, Kb, QN, KN);
    // 12) attention logits + softmax
    attn2_kernel<<<Bn * NH, 256>>>(QKV, Kb, QN, KN, temperature, ATTN);
    // 13) out = attn @ v (packed output)
    attnv_kernel<<<dim3(HW / 256, NH, Bn), 256>>>(ATTN, QKV, AOH);
    // 14) final 1x1 proj -> d_out
    conv_mma<1, 4><<<dim3(HW / 128, (Cc + 127) / 128, Bn), 256>>>(
        WPROJH, AOH, out, nullptr, Cc, Cc, Hh, Ww, Hh, Ww, 0);
}

// round 14
// speedup vs baseline: 2.7013x; 1.1878x over previous
#include <cuda_runtime.h>
#include <cuda_fp16.h>
#include <math.h>
#include <stdint.h>

// ---------------------------------------------------------------------------
// Problem constants
// ---------------------------------------------------------------------------
#define Bn   4
#define Cc   192
#define C2   384
#define Hh   96
#define Ww   96
#define HW   (Hh*Ww)          // 9216
#define NH   8
#define HD   24
#define Gg   8
#define CG   24

// scratch offsets (in floats / uint32 slots)
#define OFF_QKV1   0ul
#define OFF_QKV    14155776ul
#define OFF_CAT    28311552ul
#define OFF_SC     42467328ul
#define OFF_K2     56623104ul
#define OFF_OFF    59873280ul
#define OFF_K      60536832ul
#define OFF_QN     67614720ul
#define OFF_KN     67615488ul
#define OFF_ATTN   67616256ul
#define OFF_WK3H   67634688ul
#define OFF_WK2H   68298240ul
#define OFF_WK4H   68961792ul
#define OFF_WQKVH  68992896ul
#define OFF_WPWH   69029760ul
#define OFF_WPROJH 69048192ul
#define OFF_XH     69066624ul
#define OFF_CATH   72605568ul
#define OFF_POOLH  79683456ul
#define OFF_SCH    81452928ul
#define OFF_FEATH  88530816ul
#define OFF_AOH    92069760ul
#define SCRATCH_TOTAL 95608704ul

__device__ float g_scratch[SCRATCH_TOTAL];

// ---------------------------------------------------------------------------
// helpers
// ---------------------------------------------------------------------------
__device__ __forceinline__ uint32_t pack_h2(float lo, float hi) {
    __half2 h = __floats2half2_rn(lo, hi);
    return *reinterpret_cast<uint32_t*>(&h);
}

__device__ __forceinline__ void mma_16x8x16(float* c, const uint32_t* a,
                                            uint32_t b0, uint32_t b1) {
    asm volatile(
        "mma.sync.aligned.m16n8k16.row.col.f32.f16.f16.f32 "
        "{%0,%1,%2,%3}, {%4,%5,%6,%7}, {%8,%9}, {%0,%1,%2,%3};\n"
        : "+f"(c[0]), "+f"(c[1]), "+f"(c[2]), "+f"(c[3])
        : "r"(a[0]), "r"(a[1]), "r"(a[2]), "r"(a[3]), "r"(b0), "r"(b1));
}

__device__ __forceinline__ void cpasync4(uint32_t saddr, const void* g, bool pred) {
    int sz = pred ? 4 : 0;
    asm volatile("cp.async.ca.shared.global [%0], [%1], 4, %2;\n"
                 :: "r"(saddr), "l"(g), "r"(sz));
}
__device__ __forceinline__ void cpasync16(uint32_t saddr, const void* g) {
    asm volatile("cp.async.cg.shared.global [%0], [%1], 16;\n"
                 :: "r"(saddr), "l"(g));
}
__device__ __forceinline__ void cpasync16ca(uint32_t saddr, const void* g, bool pred) {
    int sz = pred ? 16 : 0;
    asm volatile("cp.async.ca.shared.global [%0], [%1], 16, %2;\n"
                 :: "r"(saddr), "l"(g), "r"(sz));
}
#define CP_COMMIT() asm volatile("cp.async.commit_group;\n" ::: "memory")
#define CP_WAIT0()  asm volatile("cp.async.wait_group 0;\n" ::: "memory")

// ---------------------------------------------------------------------------
// 3x3 weights: permute to tap-major K AND pack half2 K-pairs.
// ---------------------------------------------------------------------------
__global__ void permpack3_kernel(const float* __restrict__ W,
                                 uint32_t* __restrict__ Wph, int M, int Cin)
{
    int K2 = Cin * 9 / 2;
    int i = blockIdx.x * 256 + threadIdx.x;
    if (i >= M * K2) return;
    int m = i / K2;
    int r = i - m * K2;
    int t  = r / (Cin / 2);
    int ic = 2 * (r - t * (Cin / 2));
    float lo = W[(size_t)m * Cin * 9 + ic * 9 + t];
    float hi = W[(size_t)m * Cin * 9 + (ic + 1) * 9 + t];
    Wph[i] = pack_h2(lo, hi);
}

// 1x1 weights: pack half2 K-pairs
__global__ void packw1_kernel(const float* __restrict__ W,
                              uint32_t* __restrict__ Wph, int M, int K)
{
    int K2 = K / 2;
    int i = blockIdx.x * 256 + threadIdx.x;
    if (i >= M * K2) return;
    int m = i / K2;
    int kp = i - m * K2;
    Wph[i] = pack_h2(W[(size_t)m * K + 2 * kp], W[(size_t)m * K + 2 * kp + 1]);
}

// fp32 [2P][4*N4] -> half2 channel-pair packed (external input x only)
__global__ void halfpack4_kernel(const float* __restrict__ X,
                                 uint4* __restrict__ Xp, int P, int N4)
{
    int i = blockIdx.x * 256 + threadIdx.x;
    if (i >= P * N4) return;
    int pr = i / N4, n4 = i - pr * N4;
    float4 a = reinterpret_cast<const float4*>(X)[(size_t)(2 * pr) * N4 + n4];
    float4 b = reinterpret_cast<const float4*>(X)[(size_t)(2 * pr + 1) * N4 + n4];
    uint4 o;
    o.x = pack_h2(a.x, b.x);
    o.y = pack_h2(a.y, b.y);
    o.z = pack_h2(a.z, b.z);
    o.w = pack_h2(a.w, b.w);
    Xp[i] = o;
}

// ---------------------------------------------------------------------------
// fp16 tensor-core implicit-GEMM conv. BOTH operands pre-packed half2 K-pairs.
// BK = 32 elements (16 kpairs) per tile: two m16n8k16 k-steps per sync, so
// per-tile compute (~2x) fully covers cp.async L2 latency and halves the
// sync/loop overhead count.
// A: cp.async.ca 16B into smem [m][20] (16 kpairs + 4 pad; frag banks
//    20*lg+lt all distinct). B: cp.async [kpair(16)][136].
// KS==3 requires Cin % 32 == 0; KS==1 requires N % 128 == 0.
// ---------------------------------------------------------------------------
template<int KS, int FM>
__global__ __launch_bounds__(256)
void conv_mma(const uint32_t* __restrict__ Wph,
              const uint32_t* __restrict__ Xp,
              float* __restrict__ Y,
              const float* __restrict__ bias,
              int M, int Cin, int IH, int IW,
              int OH, int OW, int pad)
{
    constexpr int BM    = 32 * FM;
    constexpr int BK    = 32;               // elements per tile
    constexpr int ASTR  = 20;               // u32 per m row (16 kpairs + 4 pad)
    constexpr int B2STR = 136;
    constexpr int ACP   = BM * 4;           // 16B copies per A tile (4 per m row)
    constexpr int AIT   = (ACP + 255) / 256;

    __shared__ uint32_t As2[2][BM * ASTR];
    __shared__ uint32_t Bs2[2][16 * B2STR];

    const int N   = OH * OW;
    const int K   = Cin * KS * KS;
    const int K2  = K >> 1;
    const int IHW = IH * IW;
    const int bz  = blockIdx.z;
    const int m0  = blockIdx.y * BM;
    const int n0  = blockIdx.x * 128;

    const int tid  = threadIdx.x;
    const int wid  = tid >> 5;
    const int lane = tid & 31;
    const int wm   = wid & 1;
    const int wn   = wid >> 1;
    const int mbase = wm * (16 * FM);
    const int nbase = wn * 32;
    const int lg = lane >> 2;
    const int lt = lane & 3;

    const uint32_t* Xb = Xp + (size_t)bz * (Cin >> 1) * IHW;

    float acc[FM][4][4];
    #pragma unroll
    for (int f = 0; f < FM; ++f)
        #pragma unroll
        for (int nf = 0; nf < 4; ++nf)
            #pragma unroll
            for (int r = 0; r < 4; ++r) acc[f][nf][r] = 0.f;

    const int bn = tid & 127;
    const int gn = n0 + bn;
    const bool nvalid = gn < N;
    int oy = 0, ox = 0;
    if (KS == 3) { int g = nvalid ? gn : 0; oy = g / OW; ox = g - oy * OW; }

    auto issueA = [&](int k0, int buf) {
        #pragma unroll
        for (int r = 0; r < AIT; ++r) {
            int idx = tid + 256 * r;
            if (ACP >= 256 * (r + 1) || idx < ACP) {
                int m = idx >> 2;
                int q = idx & 3;
                int gm = m0 + m;
                uint32_t s = (uint32_t)__cvta_generic_to_shared(
                    &As2[buf][m * ASTR + q * 4]);
                cpasync16ca(s, Wph + (size_t)gm * K2 + (k0 >> 1) + q * 4, gm < M);
            }
        }
    };
    auto issueB = [&](int k0, int buf) {
        if (KS == 1) {
            #pragma unroll
            for (int r = 0; r < 2; ++r) {
                int idx = tid + 256 * r;
                int row = idx >> 5;
                int c4  = (idx & 31) * 4;
                uint32_t s = (uint32_t)__cvta_generic_to_shared(&Bs2[buf][row * B2STR + c4]);
                cpasync16(s, Xb + (size_t)((k0 >> 1) + row) * N + n0 + c4);
            }
        } else {
            int tp  = k0 / Cin;
            int icb = k0 - tp * Cin;
            int tdy = (tp >= 6) ? 2 : ((tp >= 3) ? 1 : 0);
            int tdx = tp - 3 * tdy;
            int iy  = oy + tdy - pad;
            int ix  = ox + tdx - pad;
            bool ok = nvalid && iy >= 0 && iy < IH && ix >= 0 && ix < IW;
            const uint32_t* base = Xb + (size_t)(icb >> 1) * IHW + iy * IW + ix;
            #pragma unroll
            for (int r = 0; r < 8; ++r) {
                int kp = (tid >> 7) + 2 * r;
                uint32_t s = (uint32_t)__cvta_generic_to_shared(&Bs2[buf][kp * B2STR + bn]);
                cpasync4(s, base + (size_t)kp * IHW, ok);
            }
        }
    };
    auto compute = [&](int buf) {
        #pragma unroll
        for (int ks = 0; ks < 2; ++ks) {
            const int kb = ks * 8;
            uint32_t a[FM][4];
            #pragma unroll
            for (int f = 0; f < FM; ++f) {
                int mr = mbase + f * 16 + lg;
                a[f][0] = As2[buf][mr * ASTR + kb + lt];
                a[f][1] = As2[buf][(mr + 8) * ASTR + kb + lt];
                a[f][2] = As2[buf][mr * ASTR + kb + lt + 4];
                a[f][3] = As2[buf][(mr + 8) * ASTR + kb + lt + 4];
            }
            #pragma unroll
            for (int nf = 0; nf < 4; ++nf) {
                int nc = nbase + nf * 8 + lg;
                uint32_t b0 = Bs2[buf][(kb + lt) * B2STR + nc];
                uint32_t b1 = Bs2[buf][(kb + lt + 4) * B2STR + nc];
                #pragma unroll
                for (int f = 0; f < FM; ++f)
                    mma_16x8x16(acc[f][nf], a[f], b0, b1);
            }
        }
    };

    const int kTiles = K / BK;
    issueA(0, 0); issueB(0, 0); CP_COMMIT();
    CP_WAIT0(); __syncthreads();

    for (int t = 0; t < kTiles; ++t) {
        if (t + 1 < kTiles) {
            issueA((t + 1) * BK, (t + 1) & 1);
            issueB((t + 1) * BK, (t + 1) & 1);
            CP_COMMIT();
        }
        compute(t & 1);
        if (t + 1 < kTiles) {
            CP_WAIT0(); __syncthreads();
        }
    }

    // ---- epilogue ----
    #pragma unroll
    for (int f = 0; f < FM; ++f) {
        int r0 = m0 + mbase + f * 16 + lg;
        #pragma unroll
        for (int nf = 0; nf < 4; ++nf) {
            int cb = n0 + nbase + nf * 8 + 2 * lt;
            #pragma unroll
            for (int rr = 0; rr < 2; ++rr) {
                int m = r0 + rr * 8;
                if (m >= M) continue;
                float bval = bias ? bias[m] : 0.f;
                #pragma unroll
                for (int cc = 0; cc < 2; ++cc) {
                    int n = cb + cc;
                    if (n >= N) continue;
                    Y[((size_t)bz * M + m) * N + n] = acc[f][nf][rr * 2 + cc] + bval;
                }
            }
        }
    }
}

// ---------------------------------------------------------------------------
// grouped 3x3 conv, smem-tiled
// ---------------------------------------------------------------------------
__global__ __launch_bounds__(256)
void dwconv2_kernel(const float* __restrict__ X,
                    const float* __restrict__ W,
                    float* __restrict__ Y)
{
    __shared__ float xs[2][34][35];
    __shared__ float ws[36];

    const int tile = blockIdx.x;
    const int g    = blockIdx.y;
    const int b    = blockIdx.z;
    const int ty0  = (tile / 3) * 32;
    const int tx0  = (tile % 3) * 32;
    const int tid  = threadIdx.x;

    if (tid < 36) ws[tid] = W[(size_t)g * 36 + tid];

    for (int e = tid; e < 2 * 34 * 34; e += 256) {
        int c  = e / (34 * 34);
        int r  = e - c * 34 * 34;
        int yy = r / 34, xx = r - yy * 34;
        int gy = ty0 + yy - 1, gx = tx0 + xx - 1;
        float v = 0.f;
        if (gy >= 0 && gy < Hh && gx >= 0 && gx < Ww)
            v = X[((size_t)b * C2 + 2 * g + c) * HW + gy * Ww + gx];
        xs[c][yy][xx] = v;
    }
    __syncthreads();

    const int x  = tid & 31;
    const int yb = (tid >> 5) * 4;
    #pragma unroll
    for (int j = 0; j < 4; ++j) {
        int y = yb + j;
        float a0 = 0.f, a1 = 0.f;
        #pragma unroll
        for (int c = 0; c < 2; ++c)
            #pragma unroll
            for (int ky = 0; ky < 3; ++ky)
                #pragma unroll
                for (int kx = 0; kx < 3; ++kx) {
                    float v = xs[c][y + ky][x + kx];
                    a0 += v * ws[c * 9 + ky * 3 + kx];
                    a1 += v * ws[18 + c * 9 + ky * 3 + kx];
                }
        size_t o = ((size_t)b * C2 + 2 * g) * HW + (ty0 + y) * Ww + tx0 + x;
        Y[o]      = a0;
        Y[o + HW] = a1;
    }
}

// cat: channel-pair thread; writes CAT fp32 + CATH packed in one pass.
__global__ void catpack_kernel(const float* __restrict__ QKV,
                               const float* __restrict__ Yin,
                               float* __restrict__ CAT,
                               uint4* __restrict__ CATH)
{
    const int NP = C2 / 2;
    const int N4 = HW / 4;
    int i = blockIdx.x * 256 + threadIdx.x;
    if (i >= Bn * NP * N4) return;
    int p4 = i % N4;
    int pr = (i / N4) % NP;
    int b  = i / (N4 * NP);
    int c0 = 2 * pr;
    float4 a, bv;
    if (c0 < Cc) {
        a  = reinterpret_cast<const float4*>(QKV + ((size_t)b * C2 + c0) * HW)[p4];
        bv = reinterpret_cast<const float4*>(QKV + ((size_t)b * C2 + c0 + 1) * HW)[p4];
    } else {
        a  = reinterpret_cast<const float4*>(Yin + ((size_t)b * Cc + (c0 - Cc)) * HW)[p4];
        bv = reinterpret_cast<const float4*>(Yin + ((size_t)b * Cc + (c0 - Cc) + 1) * HW)[p4];
    }
    reinterpret_cast<float4*>(CAT + ((size_t)b * C2 + c0) * HW)[p4]     = a;
    reinterpret_cast<float4*>(CAT + ((size_t)b * C2 + c0 + 1) * HW)[p4] = bv;
    uint4 o;
    o.x = pack_h2(a.x, bv.x);
    o.y = pack_h2(a.y, bv.y);
    o.z = pack_h2(a.z, bv.z);
    o.w = pack_h2(a.w, bv.w);
    CATH[((size_t)b * NP + pr) * N4 + p4] = o;
}

// 2x2 avg pool, packed-only output
__global__ void poolpack_kernel(const float* __restrict__ X, uint4* __restrict__ Yp)
{
    const int NP   = C2 / 2;
    const int OHW4 = 48 * 48 / 4;
    int i = blockIdx.x * 256 + threadIdx.x;
    if (i >= Bn * NP * OHW4) return;
    int r  = i % OHW4;
    int pr = (i / OHW4) % NP;
    int b  = i / (OHW4 * NP);
    int y  = r / 12;
    int x8 = (r % 12) * 8;
    float pv[2][4];
    #pragma unroll
    for (int c = 0; c < 2; ++c) {
        const float* xp = X + ((size_t)b * C2 + 2 * pr + c) * HW;
        float4 r0a = *reinterpret_cast<const float4*>(xp + (2 * y) * Ww + x8);
        float4 r0b = *reinterpret_cast<const float4*>(xp + (2 * y) * Ww + x8 + 4);
        float4 r1a = *reinterpret_cast<const float4*>(xp + (2 * y + 1) * Ww + x8);
        float4 r1b = *reinterpret_cast<const float4*>(xp + (2 * y + 1) * Ww + x8 + 4);
        pv[c][0] = (r0a.x + r0a.y + r1a.x + r1a.y) * 0.25f;
        pv[c][1] = (r0a.z + r0a.w + r1a.z + r1a.w) * 0.25f;
        pv[c][2] = (r0b.x + r0b.y + r1b.x + r1b.y) * 0.25f;
        pv[c][3] = (r0b.z + r0b.w + r1b.z + r1b.w) * 0.25f;
    }
    uint4 o;
    o.x = pack_h2(pv[0][0], pv[1][0]);
    o.y = pack_h2(pv[0][1], pv[1][1]);
    o.z = pack_h2(pv[0][2], pv[1][2]);
    o.w = pack_h2(pv[0][3], pv[1][3]);
    Yp[((size_t)b * NP + pr) * OHW4 + r] = o;
}

// SCH = pack(SC * sigmoid(CAT + upsample(K2)))
__global__ void sigmulpack_kernel(const float* __restrict__ SC,
                                  const float* __restrict__ CAT,
                                  const float* __restrict__ K2,
                                  uint4* __restrict__ SCH)
{
    const int NP = C2 / 2;
    const int N4 = HW / 4;
    int i = blockIdx.x * 256 + threadIdx.x;
    if (i >= Bn * NP * N4) return;
    int p4 = i % N4;
    int pr = (i / N4) % NP;
    int b  = i / (N4 * NP);
    int p  = p4 * 4;
    int y  = p / Ww, x = p % Ww;
    int iy = (y * 46) / 96;
    int ix0 = ((x + 0) * 46) / 96;
    int ix1 = ((x + 1) * 46) / 96;
    int ix2 = ((x + 2) * 46) / 96;
    int ix3 = ((x + 3) * 46) / 96;
    float sv2[2][4];
    #pragma unroll
    for (int c = 0; c < 2; ++c) {
        size_t bc = (size_t)b * C2 + 2 * pr + c;
        const float* k2r = K2 + bc * (46 * 46) + iy * 46;
        float4 cv = reinterpret_cast<const float4*>(CAT + bc * HW)[p4];
        float4 sv = reinterpret_cast<const float4*>(SC + bc * HW)[p4];
        sv2[c][0] = sv.x / (1.f + expf(-(cv.x + k2r[ix0])));
        sv2[c][1] = sv.y / (1.f + expf(-(cv.y + k2r[ix1])));
        sv2[c][2] = sv.z / (1.f + expf(-(cv.z + k2r[ix2])));
        sv2[c][3] = sv.w / (1.f + expf(-(cv.w + k2r[ix3])));
    }
    uint4 o;
    o.x = pack_h2(sv2[0][0], sv2[1][0]);
    o.y = pack_h2(sv2[0][1], sv2[1][1]);
    o.z = pack_h2(sv2[0][2], sv2[1][2]);
    o.w = pack_h2(sv2[0][3], sv2[1][3]);
    SCH[((size_t)b * NP + pr) * N4 + p4] = o;
}

// ---------------------------------------------------------------------------
// fused deformable conv; writes packed half2 relu output directly.
// ---------------------------------------------------------------------------
__global__ __launch_bounds__(128)
void deform_kernel(const float* __restrict__ Q,
                   const float* __restrict__ OFF,
                   const float* __restrict__ W,
                   const float* __restrict__ Bias,
                   uint32_t* __restrict__ Yp)
{
    __shared__ float ws2[216 * 24];
    const int g = blockIdx.y;
    const int b = blockIdx.z;
    const int tid = threadIdx.x;

    for (int e = tid; e < 216 * 24; e += 128) {
        int it = e / 24;
        int o  = e - it * 24;
        ws2[e] = W[(size_t)(g * CG + o) * 216 + it];
    }
    __syncthreads();

    int p = blockIdx.x * 128 + tid;
    int y = p / Ww, x = p % Ww;
    const float* offb = OFF + (size_t)b * 18 * HW;

    float acc[24];
    #pragma unroll
    for (int o = 0; o < 24; ++o) acc[o] = Bias[g * CG + o];

    const float* qc = Q + ((size_t)b * C2 + g * CG) * HW;

    for (int t = 0; t < 9; ++t) {
        float dy = offb[(size_t)(2 * t) * HW + p];
        float dx = offb[(size_t)(2 * t + 1) * HW + p];
        float m  = 1.f / (1.f + expf(-offb[(size_t)t * HW + p]));
        float py = dy + (float)(y - 1 + t / 3);
        float px = dx + (float)(x - 1 + t % 3);
        float y0f = floorf(py), x0f = floorf(px);
        int   y0 = (int)y0f,    x0 = (int)x0f;
        float fy = py - y0f,    fx = px - x0f;
        float w00 = (1.f - fy) * (1.f - fx);
        float w01 = (1.f - fy) * fx;
        float w10 = fy * (1.f - fx);
        float w11 = fy * fx;
        bool vy0 = (y0 >= 0 && y0 <= Hh - 1), vy1 = (y0 + 1 >= 0 && y0 + 1 <= Hh - 1);
        bool vx0 = (x0 >= 0 && x0 <= Ww - 1), vx1 = (x0 + 1 >= 0 && x0 + 1 <= Ww - 1);
        int cy0 = min(max(y0, 0), Hh - 1),     cy1 = min(max(y0 + 1, 0), Hh - 1);
        int cx0 = min(max(x0, 0), Ww - 1),     cx1 = min(max(x0 + 1, 0), Ww - 1);
        int i00 = cy0 * Ww + cx0, i01 = cy0 * Ww + cx1;
        int i10 = cy1 * Ww + cx0, i11 = cy1 * Ww + cx1;
        w00 = (vy0 && vx0) ? w00 * m : 0.f;
        w01 = (vy0 && vx1) ? w01 * m : 0.f;
        w10 = (vy1 && vx0) ? w10 * m : 0.f;
        w11 = (vy1 && vx1) ? w11 * m : 0.f;

        #pragma unroll
        for (int i = 0; i < 24; ++i) {
            const float* qp = qc + (size_t)i * HW;
            float val = w00 * qp[i00] + w01 * qp[i01] + w10 * qp[i10] + w11 * qp[i11];
            const float* wr = &ws2[(i * 9 + t) * 24];
            #pragma unroll
            for (int o = 0; o < 24; ++o) acc[o] += val * wr[o];
        }
    }
    #pragma unroll
    for (int u = 0; u < 12; ++u) {
        uint32_t v = pack_h2(fmaxf(acc[2 * u], 0.f), fmaxf(acc[2 * u + 1], 0.f));
        Yp[((size_t)b * (Cc / 2) + g * 12 + u) * HW + p] = v;
    }
}

// ---------------------------------------------------------------------------
// row L2 norms (float4)
// ---------------------------------------------------------------------------
__global__ void rownorm_kernel(const float* __restrict__ QKV,
                               const float* __restrict__ Kb,
                               float* __restrict__ QN,
                               float* __restrict__ KN)
{
    int row   = blockIdx.x;
    int which = row / (Bn * Cc);
    row %= (Bn * Cc);
    int b = row / Cc, c = row % Cc;
    const float* src = which ? (Kb + ((size_t)b * Cc + c) * HW)
                             : (QKV + ((size_t)b * C2 + c) * HW);
    float s = 0.f;
    for (int n = threadIdx.x; n < HW / 4; n += 256) {
        float4 v = reinterpret_cast<const float4*>(src)[n];
        s += v.x * v.x + v.y * v.y + v.z * v.z + v.w * v.w;
    }
    __shared__ float sm[256];
    sm[threadIdx.x] = s;
    __syncthreads();
    for (int d = 128; d > 0; d >>= 1) {
        if (threadIdx.x < d) sm[threadIdx.x] += sm[threadIdx.x + d];
        __syncthreads();
    }
    if (threadIdx.x == 0) {
        float nrm = fmaxf(sqrtf(sm[0]), 1e-12f);
        (which ? KN : QN)[b * Cc + c] = nrm;
    }
}

// ---------------------------------------------------------------------------
// attention: one block per (b,h).  K-head staged through smem.
// ---------------------------------------------------------------------------
#define CNK 384
__global__ __launch_bounds__(256)
void attn2_kernel(const float* __restrict__ QKV,
                  const float* __restrict__ Kb,
                  const float* __restrict__ QN,
                  const float* __restrict__ KN,
                  const float* __restrict__ TEMP,
                  float* __restrict__ ATTN)
{
    __shared__ float ks_[24][CNK + 8];
    __shared__ float logits[24][24];

    const int b = blockIdx.x >> 3;
    const int h = blockIdx.x & 7;
    const int tid  = threadIdx.x;
    const int wid  = tid >> 5;
    const int lane = tid & 31;

    const float* qh = QKV + ((size_t)b * C2 + h * HD) * HW;
    const float* kh = Kb  + ((size_t)b * Cc + h * HD) * HW;

    float acc[3][24];
    #pragma unroll
    for (int r = 0; r < 3; ++r)
        #pragma unroll
        for (int j = 0; j < 24; ++j) acc[r][j] = 0.f;

    const float* q0p = qh + (size_t)(3 * wid + 0) * HW;
    const float* q1p = qh + (size_t)(3 * wid + 1) * HW;
    const float* q2p = qh + (size_t)(3 * wid + 2) * HW;

    for (int n0 = 0; n0 < HW; n0 += CNK) {
        __syncthreads();
        for (int e = tid; e < 24 * (CNK / 4); e += 256) {
            int j = e / (CNK / 4);
            int c = e - j * (CNK / 4);
            float4 v = *reinterpret_cast<const float4*>(kh + (size_t)j * HW + n0 + c * 4);
            ks_[j][c * 4 + 0] = v.x;
            ks_[j][c * 4 + 1] = v.y;
            ks_[j][c * 4 + 2] = v.z;
            ks_[j][c * 4 + 3] = v.w;
        }
        __syncthreads();

        for (int i = lane; i < CNK; i += 32) {
            int n = n0 + i;
            float q0 = q0p[n], q1 = q1p[n], q2 = q2p[n];
            #pragma unroll
            for (int j = 0; j < 24; ++j) {
                float kv = ks_[j][i];
                acc[0][j] += q0 * kv;
                acc[1][j] += q1 * kv;
                acc[2][j] += q2 * kv;
            }
        }
    }

    #pragma unroll
    for (int r = 0; r < 3; ++r)
        #pragma unroll
        for (int j = 0; j < 24; ++j) {
            float v = acc[r][j];
            for (int o = 16; o > 0; o >>= 1) v += __shfl_down_sync(0xffffffffu, v, o);
            if (lane == 0) logits[wid * 3 + r][j] = v;
        }
    __syncthreads();

    if (tid < 24) {
        int i = tid;
        float qn = QN[b * Cc + h * HD + i];
        float tp = TEMP[h];
        float s[24];
        float mx = -1e30f;
        #pragma unroll
        for (int j = 0; j < 24; ++j) {
            s[j] = logits[i][j] / (qn * KN[b * Cc + h * HD + j]) * tp;
            mx = fmaxf(mx, s[j]);
        }
        float sum = 0.f;
        #pragma unroll
        for (int j = 0; j < 24; ++j) { s[j] = expf(s[j] - mx); sum += s[j]; }
        float inv = 1.f / sum;
        #pragma unroll
        for (int j = 0; j < 24; ++j)
            ATTN[(((size_t)b * NH + h) * HD + i) * HD + j] = s[j] * inv;
    }
}

// out = attn @ v ; writes packed half2 directly
__global__ void attnv_kernel(const float* __restrict__ ATTN,
                             const float* __restrict__ QKV,
                             uint32_t* __restrict__ AOp)
{
    int h = blockIdx.y, b = blockIdx.z;
    int n = blockIdx.x * 256 + threadIdx.x;
    __shared__ float a_s[HD * HD];
    for (int e = threadIdx.x; e < HD * HD; e += 256)
        a_s[e] = ATTN[((size_t)b * NH + h) * HD * HD + e];
    __syncthreads();
    const float* vb = QKV + ((size_t)b * C2 + Cc + h * HD) * HW;
    float acc[HD] = {};
    #pragma unroll
    for (int j = 0; j < HD; ++j) {
        float vv = vb[(size_t)j * HW + n];
        #pragma unroll
        for (int i = 0; i < HD; ++i) acc[i] += a_s[i * HD + j] * vv;
    }
    #pragma unroll
    for (int u = 0; u < HD / 2; ++u)
        AOp[((size_t)b * (Cc / 2) + h * (HD / 2) + u) * HW + n] =
            pack_h2(acc[2 * u], acc[2 * u + 1]);
}

// ---------------------------------------------------------------------------
// launcher
// ---------------------------------------------------------------------------
extern "C" void kernel_launch(void* const* d_in, const int* in_sizes, int n_in,
                              void* d_out, int out_size)
{
    const float* x           = (const float*)d_in[0];
    const float* y           = (const float*)d_in[1];
    const float* temperature = (const float*)d_in[2];
    const float* qkv_w       = (const float*)d_in[3];
    const float* qkv_conv_w  = (const float*)d_in[4];
    const float* proj_w      = (const float*)d_in[5];
    const float* k2_w        = (const float*)d_in[6];
    const float* k3_w        = (const float*)d_in[7];
    const float* k4_w        = (const float*)d_in[8];
    const float* deform_w    = (const float*)d_in[9];
    const float* deform_b    = (const float*)d_in[10];
    const float* pw_w        = (const float*)d_in[11];
    const float* pw_b        = (const float*)d_in[12];
    float* out = (float*)d_out;

    float* S = nullptr;
    cudaGetSymbolAddress((void**)&S, g_scratch);
    float* QKV1 = S + OFF_QKV1;
    float* QKV  = S + OFF_QKV;
    float* CAT  = S + OFF_CAT;
    float* SC   = S + OFF_SC;
    float* K2   = S + OFF_K2;
    float* OFFb = S + OFF_OFF;
    float* Kb   = S + OFF_K;
    float* QN   = S + OFF_QN;
    float* KN   = S + OFF_KN;
    float* ATTN = S + OFF_ATTN;
    uint32_t* WK3H   = (uint32_t*)(S + OFF_WK3H);
    uint32_t* WK2H   = (uint32_t*)(S + OFF_WK2H);
    uint32_t* WK4H   = (uint32_t*)(S + OFF_WK4H);
    uint32_t* WQKVH  = (uint32_t*)(S + OFF_WQKVH);
    uint32_t* WPWH   = (uint32_t*)(S + OFF_WPWH);
    uint32_t* WPROJH = (uint32_t*)(S + OFF_WPROJH);
    uint32_t* XH    = (uint32_t*)(S + OFF_XH);
    uint32_t* CATH  = (uint32_t*)(S + OFF_CATH);
    uint32_t* POOLH = (uint32_t*)(S + OFF_POOLH);
    uint32_t* SCH   = (uint32_t*)(S + OFF_SCH);
    uint32_t* FEATH = (uint32_t*)(S + OFF_FEATH);
    uint32_t* AOH   = (uint32_t*)(S + OFF_AOH);

    // 0) weight permute+pack, 1x1 weight pack, pack x
    permpack3_kernel<<<(663552 + 255) / 256, 256>>>(k3_w, WK3H, C2, C2);
    permpack3_kernel<<<(663552 + 255) / 256, 256>>>(k2_w, WK2H, C2, C2);
    permpack3_kernel<<<(31104 + 255) / 256, 256>>>(k4_w, WK4H, 18, C2);
    packw1_kernel<<<(36864 + 255) / 256, 256>>>(qkv_w, WQKVH, C2, Cc);
    packw1_kernel<<<(18432 + 255) / 256, 256>>>(pw_w, WPWH, Cc, Cc);
    packw1_kernel<<<(18432 + 255) / 256, 256>>>(proj_w, WPROJH, Cc, Cc);
    halfpack4_kernel<<<(384 * 2304 + 255) / 256, 256>>>(x, (uint4*)XH, 384, 2304);

    // 1) qkv 1x1
    conv_mma<1, 4><<<dim3(HW / 128, C2 / 128, Bn), 256>>>(
        WQKVH, XH, QKV1, nullptr, C2, Cc, Hh, Ww, Hh, Ww, 0);
    // 2) grouped 3x3 (groups=192)
    dwconv2_kernel<<<dim3(9, 192, Bn), 256>>>(QKV1, qkv_conv_w, QKV);
    // 3) cat (fp32 + packed in one pass)
    catpack_kernel<<<(Bn * 192 * 2304 + 255) / 256, 256>>>(QKV, y, CAT, (uint4*)CATH);
    // 4) k3 conv 3x3 pad=1
    conv_mma<3, 4><<<dim3(HW / 128, C2 / 128, Bn), 256>>>(
        WK3H, CATH, SC, nullptr, C2, C2, Hh, Ww, Hh, Ww, 1);
    // 5) avg pool 2x2 (packed only)
    poolpack_kernel<<<(Bn * 192 * 576 + 255) / 256, 256>>>(CAT, (uint4*)POOLH);
    // 6) k2 conv 3x3 pad=0 : 48x48 -> 46x46
    conv_mma<3, 4><<<dim3((46 * 46 + 127) / 128, C2 / 128, Bn), 256>>>(
        WK2H, POOLH, K2, nullptr, C2, C2, 48, 48, 46, 46, 0);
    // 7) SCH = pack(SC * sigmoid(CAT + upsample(K2)))
    sigmulpack_kernel<<<(Bn * 192 * 2304 + 255) / 256, 256>>>(SC, CAT, K2, (uint4*)SCH);
    // 8) offset = conv3x3(sc, k4, pad=1), M=18
    conv_mma<3, 1><<<dim3(HW / 128, 1, Bn), 256>>>(
        WK4H, SCH, OFFb, nullptr, 18, C2, Hh, Ww, Hh, Ww, 1);
    // 9) deformable conv -> packed relu output
    deform_kernel<<<dim3(HW / 128, Gg, Bn), 128>>>(QKV, OFFb, deform_w, deform_b, FEATH);
    // 10) k = 1x1(FEAT) + pw_b
    conv_mma<1, 4><<<dim3(HW / 128, (Cc + 127) / 128, Bn), 256>>>(
        WPWH, FEATH, Kb, pw_b, Cc, Cc, Hh, Ww, Hh, Ww, 0);
    // 11) row norms
    rownorm_kernel<<<2 * Bn * Cc, 256>>>(QKV, Kb, QN, KN);
    // 12) attention logits + softmax
    attn2_kernel<<<Bn * NH, 256>>>(QKV, Kb, QN, KN, temperature, ATTN);
    // 13) out = attn @ v (packed output)
    attnv_kernel<<<dim3(HW / 256, NH, Bn), 256>>>(ATTN, QKV, AOH);
    // 14) final 1x1 proj -> d_out
    conv_mma<1, 4><<<dim3(HW / 128, (Cc + 127) / 128, Bn), 256>>>(
        WPROJH, AOH, out, nullptr, Cc, Cc, Hh, Ww, Hh, Ww, 0);
}